// round 1
// baseline (speedup 1.0000x reference)
#include <cuda_runtime.h>
#include <cstdint>

// ---------------------------------------------------------------------------
// LiteMLA: qkv(1x1) -> {dw3+pw3, dw5+pw5} -> relu linear attention -> proj(1x1)
// Shapes: x (8,256,64,64), qkv (8,768,64,64), multi = [qkv,s3,s5] (8,2304,64,64)
// heads: 96 total (32 per source), 24 ch/head = 8 q + 8 k + 8 v
// ---------------------------------------------------------------------------

#define BATCH 8
#define C3 768
#define NPIX 4096
#define WIDTH 64

// scratch (allocation-free rule: static __device__ arrays)
__device__ float g_qkv[(size_t)BATCH * C3 * NPIX];
__device__ float g_s3 [(size_t)BATCH * C3 * NPIX];
__device__ float g_s5 [(size_t)BATCH * C3 * NPIX];
__device__ float g_att[(size_t)BATCH * C3 * NPIX];
__device__ float g_vk [(size_t)BATCH * 96 * 72];

// ---------------- packed f32x2 helpers (FFMA2 path) ------------------------
__device__ __forceinline__ unsigned long long pk2(float lo, float hi) {
    unsigned long long r;
    asm("mov.b64 %0, {%1, %2};" : "=l"(r)
        : "r"(__float_as_uint(lo)), "r"(__float_as_uint(hi)));
    return r;
}
__device__ __forceinline__ void ffma2(unsigned long long& d,
                                      unsigned long long a,
                                      unsigned long long b) {
    asm("fma.rn.f32x2 %0, %1, %2, %0;" : "+l"(d) : "l"(a), "l"(b));
}
__device__ __forceinline__ float f2lo(unsigned long long v) {
    return __uint_as_float((unsigned)(v & 0xffffffffull));
}
__device__ __forceinline__ float f2hi(unsigned long long v) {
    return __uint_as_float((unsigned)(v >> 32));
}

// ---------------------------------------------------------------------------
// Generic SGEMM: C[b] (M,N) = A (M,K) @ B[b] (K,N) + bias[M]
// A row-major shared across batch; B,C batched. 128x128 tile, BK=8,
// 256 threads, 8x8 microtile via f32x2 packed FMA.
// Requires M%128==0, N%128==0, K%8==0.
// ---------------------------------------------------------------------------
__global__ __launch_bounds__(256, 2)
void gemm128(const float* __restrict__ A, const float* __restrict__ Bm,
             const float* __restrict__ bias, float* __restrict__ C,
             int M, int N, int K)
{
    __shared__ __align__(16) float As[8][128];   // As[k][m]
    __shared__ __align__(16) float Bs[8][128];   // Bs[k][n]

    const int tid  = threadIdx.x;
    const int n0   = blockIdx.x * 128;
    const int m0   = blockIdx.y * 128;
    const float* Bb = Bm + (size_t)blockIdx.z * K * N;
    float*       Cb = C  + (size_t)blockIdx.z * M * N;

    const int tidx = tid & 15;        // n-direction
    const int tidy = tid >> 4;        // m-direction
    const int arow = tid >> 1;        // A tile loader: row within 128
    const int ac   = (tid & 1) * 4;   // A tile loader: k offset
    const int brow = tid >> 5;        // B tile loader: k row
    const int bc   = (tid & 31) * 4;  // B tile loader: n offset

    unsigned long long acc[2][4][2][2];
#pragma unroll
    for (int mh = 0; mh < 2; mh++)
#pragma unroll
        for (int i = 0; i < 4; i++)
#pragma unroll
            for (int nh = 0; nh < 2; nh++) {
                acc[mh][i][nh][0] = 0ull;
                acc[mh][i][nh][1] = 0ull;
            }

    const float* Aptr = A  + (size_t)(m0 + arow) * K + ac;
    const float* Bptr = Bb + (size_t)brow * N + n0 + bc;

    for (int k0 = 0; k0 < K; k0 += 8) {
        float4 av = *(const float4*)(Aptr + k0);
        float4 bv = *(const float4*)(Bptr + (size_t)k0 * N);
        As[ac + 0][arow] = av.x;
        As[ac + 1][arow] = av.y;
        As[ac + 2][arow] = av.z;
        As[ac + 3][arow] = av.w;
        *(float4*)&Bs[brow][bc] = bv;
        __syncthreads();

#pragma unroll
        for (int kk = 0; kk < 8; kk++) {
            float4 a0 = *(const float4*)&As[kk][tidy * 4];
            float4 a1 = *(const float4*)&As[kk][64 + tidy * 4];
            float4 b0 = *(const float4*)&Bs[kk][tidx * 4];
            float4 b1 = *(const float4*)&Bs[kk][64 + tidx * 4];

            unsigned long long bp[2][2];
            bp[0][0] = pk2(b0.x, b0.y);
            bp[0][1] = pk2(b0.z, b0.w);
            bp[1][0] = pk2(b1.x, b1.y);
            bp[1][1] = pk2(b1.z, b1.w);

            float aval[2][4] = {{a0.x, a0.y, a0.z, a0.w},
                                {a1.x, a1.y, a1.z, a1.w}};
#pragma unroll
            for (int mh = 0; mh < 2; mh++)
#pragma unroll
                for (int i = 0; i < 4; i++) {
                    unsigned long long ap = pk2(aval[mh][i], aval[mh][i]);
#pragma unroll
                    for (int nh = 0; nh < 2; nh++) {
                        ffma2(acc[mh][i][nh][0], ap, bp[nh][0]);
                        ffma2(acc[mh][i][nh][1], ap, bp[nh][1]);
                    }
                }
        }
        __syncthreads();
    }

#pragma unroll
    for (int mh = 0; mh < 2; mh++)
#pragma unroll
        for (int i = 0; i < 4; i++) {
            int m = m0 + mh * 64 + tidy * 4 + i;
            float bi = bias[m];
#pragma unroll
            for (int nh = 0; nh < 2; nh++) {
                int n = n0 + nh * 64 + tidx * 4;
                unsigned long long v0 = acc[mh][i][nh][0];
                unsigned long long v1 = acc[mh][i][nh][1];
                float4 o;
                o.x = f2lo(v0) + bi;
                o.y = f2hi(v0) + bi;
                o.z = f2lo(v1) + bi;
                o.w = f2hi(v1) + bi;
                *(float4*)&Cb[(size_t)m * N + n] = o;
            }
        }
}

// ---------------------------------------------------------------------------
// Fused depthwise(3x3 & 5x5) + grouped pointwise (24ch in -> 24ch out / group).
// grid: (ytiles=16, groups=32, batch=8), 256 threads = 4 rows x 64 cols.
// Two phases of 12 input channels each (keeps static smem < 48KB).
// ---------------------------------------------------------------------------
__global__ __launch_bounds__(256)
void dwpw_kernel(const float* __restrict__ qkv,
                 const float* __restrict__ dw3_w, const float* __restrict__ dw3_b,
                 const float* __restrict__ pw3_w, const float* __restrict__ pw3_b,
                 const float* __restrict__ dw5_w, const float* __restrict__ dw5_b,
                 const float* __restrict__ pw5_w, const float* __restrict__ pw5_b,
                 float* __restrict__ s3, float* __restrict__ s5)
{
    const int ytile = blockIdx.x;
    const int g     = blockIdx.y;
    const int b     = blockIdx.z;

    __shared__ float sin_[12][8][68];      // 12 ch, 8 rows (y0-2..y0+5), 68 cols (x pad 2)
    __shared__ float w3s[24][24], w5s[24][24];
    __shared__ float w3d[12][9],  w5d[12][25];
    __shared__ float db3[12], db5[12];

    const int tid = threadIdx.x;
    const int tx  = tid & 63;
    const int ty  = tid >> 6;
    const int y0  = ytile * 4;

    // grouped-pointwise weights (persist across both phases)
    for (int i = tid; i < 576; i += 256) {
        w3s[i / 24][i % 24] = pw3_w[g * 576 + i];
        w5s[i / 24][i % 24] = pw5_w[g * 576 + i];
    }

    float acc3[24], acc5[24];
#pragma unroll
    for (int o = 0; o < 24; o++) { acc3[o] = 0.f; acc5[o] = 0.f; }

    for (int ph = 0; ph < 2; ph++) {
        const int icb = ph * 12;
        __syncthreads();   // protects w3s/w5s (ph 0) and prev-phase sin_/w3d reads

        const float* src = qkv + ((size_t)b * C3 + g * 24 + icb) * NPIX;
        for (int i = tid; i < 12 * 8 * 68; i += 256) {
            int xx = i % 68;
            int r  = (i / 68) & 7;
            int c  = i / (68 * 8);
            int yy = y0 - 2 + r;
            int xg = xx - 2;
            float v = 0.f;
            if ((unsigned)yy < 64u && (unsigned)xg < 64u)
                v = src[(size_t)c * NPIX + yy * WIDTH + xg];
            sin_[c][r][xx] = v;
        }
        for (int i = tid; i < 12 * 9; i += 256)
            w3d[i / 9][i % 9] = dw3_w[(g * 24 + icb) * 9 + i];
        for (int i = tid; i < 12 * 25; i += 256)
            w5d[i / 25][i % 25] = dw5_w[(g * 24 + icb) * 25 + i];
        if (tid < 12) {
            db3[tid] = dw3_b[g * 24 + icb + tid];
            db5[tid] = dw5_b[g * 24 + icb + tid];
        }
        __syncthreads();

        for (int ic = 0; ic < 12; ic++) {
            float d3 = db3[ic];
            float d5 = db5[ic];
#pragma unroll
            for (int dy = 0; dy < 5; dy++)
#pragma unroll
                for (int dx = 0; dx < 5; dx++) {
                    float v = sin_[ic][ty + dy][tx + dx];
                    d5 += w5d[ic][dy * 5 + dx] * v;
                    if (dy >= 1 && dy <= 3 && dx >= 1 && dx <= 3)
                        d3 += w3d[ic][(dy - 1) * 3 + (dx - 1)] * v;
                }
            const int ici = icb + ic;
#pragma unroll
            for (int o = 0; o < 24; o++) {
                acc3[o] += w3s[o][ici] * d3;
                acc5[o] += w5s[o][ici] * d5;
            }
        }
    }

    const int y = y0 + ty;
    const size_t outbase = ((size_t)b * C3 + g * 24) * NPIX + y * WIDTH + tx;
#pragma unroll
    for (int o = 0; o < 24; o++) {
        s3[outbase + (size_t)o * NPIX] = acc3[o] + pw3_b[g * 24 + o];
        s5[outbase + (size_t)o * NPIX] = acc5[o] + pw5_b[g * 24 + o];
    }
}

// ---------------------------------------------------------------------------
// vk reduction: vk[b][hh][d][e] = sum_n v9_d(n) * k_e(n),  d in 0..8, e in 0..7
// v9[8] = 1 (ones row). k = relu(ch 8..15), v = ch 16..23 (raw).
// grid (96, 8), 256 threads.
// ---------------------------------------------------------------------------
__global__ __launch_bounds__(256)
void vk_kernel(const float* __restrict__ qkv, const float* __restrict__ s3,
               const float* __restrict__ s5, float* __restrict__ vk)
{
    const int hh = blockIdx.x;
    const int b  = blockIdx.y;
    const int src_id = hh >> 5;
    const int g      = hh & 31;
    const float* base =
        (src_id == 0 ? qkv : (src_id == 1 ? s3 : s5)) +
        ((size_t)b * C3 + g * 24) * NPIX;

    float acc[9][8];
#pragma unroll
    for (int d = 0; d < 9; d++)
#pragma unroll
        for (int e = 0; e < 8; e++) acc[d][e] = 0.f;

    const int tid = threadIdx.x;
    for (int n = tid; n < NPIX; n += 256) {
        float kv[8], vv[8];
#pragma unroll
        for (int e = 0; e < 8; e++)
            kv[e] = fmaxf(base[(size_t)(8 + e) * NPIX + n], 0.f);
#pragma unroll
        for (int d = 0; d < 8; d++)
            vv[d] = base[(size_t)(16 + d) * NPIX + n];
#pragma unroll
        for (int d = 0; d < 8; d++)
#pragma unroll
            for (int e = 0; e < 8; e++)
                acc[d][e] += vv[d] * kv[e];
#pragma unroll
        for (int e = 0; e < 8; e++)
            acc[8][e] += kv[e];
    }

    // warp butterfly reduce all 72 values
#pragma unroll
    for (int d = 0; d < 9; d++)
#pragma unroll
        for (int e = 0; e < 8; e++) {
            float v = acc[d][e];
            v += __shfl_xor_sync(0xffffffffu, v, 16);
            v += __shfl_xor_sync(0xffffffffu, v, 8);
            v += __shfl_xor_sync(0xffffffffu, v, 4);
            v += __shfl_xor_sync(0xffffffffu, v, 2);
            v += __shfl_xor_sync(0xffffffffu, v, 1);
            acc[d][e] = v;
        }

    __shared__ float red[8][72];
    const int wid  = tid >> 5;
    const int lane = tid & 31;
    if (lane == 0) {
#pragma unroll
        for (int d = 0; d < 9; d++)
#pragma unroll
            for (int e = 0; e < 8; e++)
                red[wid][d * 8 + e] = acc[d][e];
    }
    __syncthreads();
    if (tid < 72) {
        float s = 0.f;
#pragma unroll
        for (int w = 0; w < 8; w++) s += red[w][tid];
        vk[((size_t)b * 96 + hh) * 72 + tid] = s;
    }
}

// ---------------------------------------------------------------------------
// attention normalize: att[b][hh*8+d][n] = (sum_e vk[d][e] q_e(n)) / (den + eps)
// den = sum_e vk[8][e] q_e(n).  q = relu(ch 0..7).
// grid (96, 8), 256 threads.
// ---------------------------------------------------------------------------
__global__ __launch_bounds__(256)
void att_kernel(const float* __restrict__ qkv, const float* __restrict__ s3,
                const float* __restrict__ s5, const float* __restrict__ vk,
                float* __restrict__ att)
{
    const int hh = blockIdx.x;
    const int b  = blockIdx.y;
    const int src_id = hh >> 5;
    const int g      = hh & 31;
    const float* base =
        (src_id == 0 ? qkv : (src_id == 1 ? s3 : s5)) +
        ((size_t)b * C3 + g * 24) * NPIX;

    __shared__ float vs[72];
    const int tid = threadIdx.x;
    if (tid < 72) vs[tid] = vk[((size_t)b * 96 + hh) * 72 + tid];
    __syncthreads();

    float* out = att + ((size_t)b * C3 + hh * 8) * NPIX;
    for (int n = tid; n < NPIX; n += 256) {
        float q[8];
#pragma unroll
        for (int e = 0; e < 8; e++)
            q[e] = fmaxf(base[(size_t)e * NPIX + n], 0.f);
        float den = 1e-15f;
#pragma unroll
        for (int e = 0; e < 8; e++) den += vs[64 + e] * q[e];
        float rd = __fdividef(1.f, den);
#pragma unroll
        for (int d = 0; d < 8; d++) {
            float num = 0.f;
#pragma unroll
            for (int e = 0; e < 8; e++) num += vs[d * 8 + e] * q[e];
            out[(size_t)d * NPIX + n] = num * rd;
        }
    }
}

// ---------------------------------------------------------------------------
extern "C" void kernel_launch(void* const* d_in, const int* in_sizes, int n_in,
                              void* d_out, int out_size)
{
    const float* x      = (const float*)d_in[0];
    const float* qkv_w  = (const float*)d_in[1];
    const float* qkv_b  = (const float*)d_in[2];
    const float* dw3_w  = (const float*)d_in[3];
    const float* dw3_b  = (const float*)d_in[4];
    const float* pw3_w  = (const float*)d_in[5];
    const float* pw3_b  = (const float*)d_in[6];
    const float* dw5_w  = (const float*)d_in[7];
    const float* dw5_b  = (const float*)d_in[8];
    const float* pw5_w  = (const float*)d_in[9];
    const float* pw5_b  = (const float*)d_in[10];
    const float* proj_w = (const float*)d_in[11];
    const float* proj_b = (const float*)d_in[12];
    float* out = (float*)d_out;

    void *p_qkv, *p_s3, *p_s5, *p_att, *p_vk;
    cudaGetSymbolAddress(&p_qkv, g_qkv);
    cudaGetSymbolAddress(&p_s3,  g_s3);
    cudaGetSymbolAddress(&p_s5,  g_s5);
    cudaGetSymbolAddress(&p_att, g_att);
    cudaGetSymbolAddress(&p_vk,  g_vk);
    float* qkv = (float*)p_qkv;
    float* s3  = (float*)p_s3;
    float* s5  = (float*)p_s5;
    float* att = (float*)p_att;
    float* vkb = (float*)p_vk;

    // 1) qkv = W(768,256) @ x[b](256,4096) + b
    gemm128<<<dim3(NPIX / 128, C3 / 128, BATCH), 256>>>(
        qkv_w, x, qkv_b, qkv, C3, NPIX, 256);

    // 2) fused depthwise + grouped pointwise -> s3, s5
    dwpw_kernel<<<dim3(16, 32, BATCH), 256>>>(
        qkv, dw3_w, dw3_b, pw3_w, pw3_b, dw5_w, dw5_b, pw5_w, pw5_b, s3, s5);

    // 3) vk global reduction per (batch, head)
    vk_kernel<<<dim3(96, BATCH), 256>>>(qkv, s3, s5, vkb);

    // 4) attention normalize -> att
    att_kernel<<<dim3(96, BATCH), 256>>>(qkv, s3, s5, vkb, att);

    // 5) out = Wp(256,768) @ att[b](768,4096) + b
    gemm128<<<dim3(NPIX / 128, 256 / 128, BATCH), 256>>>(
        proj_w, att, proj_b, out, 256, NPIX, C3);
}

// round 3
// speedup vs baseline: 1.3068x; 1.3068x over previous
#include <cuda_runtime.h>
#include <cuda_bf16.h>
#include <cstdint>

// ---------------------------------------------------------------------------
// LiteMLA on sm_103a (harness PTX target lacks the 'a' feature, so tensor
// cores are used via mma.sync HMMA, not tcgen05).
// qkv(1x1) and proj(1x1) GEMMs: bf16 hi/lo split, 3 mma products, fp32 accum.
// ---------------------------------------------------------------------------

#define BATCH 8
#define C3 768
#define NPIX 4096
#define WIDTH 64

// scratch (allocation-free rule: static __device__ arrays)
__device__ float g_qkv[(size_t)BATCH * C3 * NPIX];
__device__ float g_s3 [(size_t)BATCH * C3 * NPIX];
__device__ float g_s5 [(size_t)BATCH * C3 * NPIX];
__device__ float g_vk [(size_t)BATCH * 96 * 72];

__device__ __nv_bfloat16 g_xt_h [(size_t)BATCH * NPIX * 256];  // x^T  [b][n][k]
__device__ __nv_bfloat16 g_xt_l [(size_t)BATCH * NPIX * 256];
__device__ __nv_bfloat16 g_at_h [(size_t)BATCH * NPIX * C3];   // att^T [b][n][k]
__device__ __nv_bfloat16 g_at_l [(size_t)BATCH * NPIX * C3];
__device__ __nv_bfloat16 g_wq_h [C3 * 256];
__device__ __nv_bfloat16 g_wq_l [C3 * 256];
__device__ __nv_bfloat16 g_wp_h [256 * C3];
__device__ __nv_bfloat16 g_wp_l [256 * C3];

// ---------------------------------------------------------------------------
__device__ __forceinline__ uint32_t smem_u32(const void* p) {
    uint32_t a;
    asm("{ .reg .u64 t; cvta.to.shared.u64 t, %1; cvt.u32.u64 %0, t; }"
        : "=r"(a) : "l"(p));
    return a;
}
#define CP_ASYNC16(s, g) \
    asm volatile("cp.async.cg.shared.global [%0], [%1], 16;" :: "r"(s), "l"(g))
#define CP_COMMIT() asm volatile("cp.async.commit_group;" ::: "memory")
#define CP_WAIT(n)  asm volatile("cp.async.wait_group %0;" :: "n"(n) : "memory")

__device__ __forceinline__ void ldsm4(uint32_t addr, uint32_t* r) {
    asm volatile("ldmatrix.sync.aligned.m8n8.x4.shared.b16 {%0,%1,%2,%3}, [%4];"
                 : "=r"(r[0]), "=r"(r[1]), "=r"(r[2]), "=r"(r[3]) : "r"(addr));
}
__device__ __forceinline__ void mma_bf16(float* d, const uint32_t* a,
                                         const uint32_t* b) {
    asm volatile(
        "mma.sync.aligned.m16n8k16.row.col.f32.bf16.bf16.f32 "
        "{%0,%1,%2,%3}, {%4,%5,%6,%7}, {%8,%9}, {%0,%1,%2,%3};"
        : "+f"(d[0]), "+f"(d[1]), "+f"(d[2]), "+f"(d[3])
        : "r"(a[0]), "r"(a[1]), "r"(a[2]), "r"(a[3]), "r"(b[0]), "r"(b[1]));
}

// ---------------------------------------------------------------------------
// bf16 split GEMM: C[b](M,N) = Ah/Al(M,K) @ Bth/Btl(b,N,K)^T + bias[M]
// Block 128x128, BK=32, 3-stage cp.async ring, 8 warps (4m x 2n).
// SMEM per stage: 4 operands x 128 rows x 80B pitch = 40960B.
// ---------------------------------------------------------------------------
#define STG_BYTES 40960
#define OPD_BYTES 10240
#define NSTAGE 3

__device__ __forceinline__ void stage_load(
    uint32_t sbase, const __nv_bfloat16* gA_h, const __nv_bfloat16* gA_l,
    const __nv_bfloat16* gB_h, const __nv_bfloat16* gB_l,
    int K, int kc, int tid)
{
    const int op = tid >> 6;        // 0..3: Ah, Al, Bh, Bl
    const int t  = tid & 63;
    const __nv_bfloat16* gp =
        (op == 0) ? gA_h : (op == 1) ? gA_l : (op == 2) ? gB_h : gB_l;
    const uint32_t sb = sbase + op * OPD_BYTES;
    const __nv_bfloat16* gk = gp + kc * 32;
#pragma unroll
    for (int it = 0; it < 8; it++) {
        int chunk = t + it * 64;          // 0..511
        int row = chunk >> 2;
        int c   = chunk & 3;
        CP_ASYNC16(sb + row * 80 + c * 16, gk + (size_t)row * K + c * 8);
    }
}

__global__ __launch_bounds__(256, 1)
void gemm_bf16(const __nv_bfloat16* __restrict__ Ah,
               const __nv_bfloat16* __restrict__ Al,
               const __nv_bfloat16* __restrict__ Bth,
               const __nv_bfloat16* __restrict__ Btl,
               const float* __restrict__ bias, float* __restrict__ C,
               int M, int N, int K)
{
    extern __shared__ __align__(16) char smem[];
    const uint32_t sm0 = smem_u32(smem);

    const int tid  = threadIdx.x;
    const int wid  = tid >> 5;
    const int lane = tid & 31;
    const int n0 = blockIdx.x * 128;
    const int m0 = blockIdx.y * 128;
    const int b  = blockIdx.z;

    const int wm = (wid >> 1) * 32;       // warp m offset in tile
    const int wn = (wid & 1) * 64;        // warp n offset in tile

    const __nv_bfloat16* gA_h = Ah + (size_t)m0 * K;
    const __nv_bfloat16* gA_l = Al + (size_t)m0 * K;
    const __nv_bfloat16* gB_h = Bth + ((size_t)b * N + n0) * K;
    const __nv_bfloat16* gB_l = Btl + ((size_t)b * N + n0) * K;

    float acc[2][8][4];
#pragma unroll
    for (int t = 0; t < 2; t++)
#pragma unroll
        for (int nt = 0; nt < 8; nt++)
#pragma unroll
            for (int i = 0; i < 4; i++) acc[t][nt][i] = 0.f;

    const int nk = K / 32;

    // prologue: stages 0,1 in flight
    stage_load(sm0, gA_h, gA_l, gB_h, gB_l, K, 0, tid);
    CP_COMMIT();
    if (nk > 1) {
        stage_load(sm0 + STG_BYTES, gA_h, gA_l, gB_h, gB_l, K, 1, tid);
        CP_COMMIT();
    }

    // per-lane ldmatrix address components
    const int a_row = lane & 15;
    const int a_hi  = (lane >> 4) * 16;                     // k-half byte
    const int b_row = ((lane >> 4) & 1) * 8 + (lane & 7);
    const int b_hi  = ((lane >> 3) & 1) * 16;

    for (int kc = 0; kc < nk; kc++) {
        if (kc + 2 < nk) {
            stage_load(sm0 + ((kc + 2) % NSTAGE) * STG_BYTES,
                       gA_h, gA_l, gB_h, gB_l, K, kc + 2, tid);
            CP_COMMIT();
        }
        if (kc + 2 < nk)      CP_WAIT(2);
        else if (kc + 1 < nk) CP_WAIT(1);
        else                  CP_WAIT(0);
        __syncthreads();

        const uint32_t sb  = sm0 + (kc % NSTAGE) * STG_BYTES;
        const uint32_t aAh = sb;
        const uint32_t aAl = sb + OPD_BYTES;
        const uint32_t aBh = sb + 2 * OPD_BYTES;
        const uint32_t aBl = sb + 3 * OPD_BYTES;

#pragma unroll
        for (int j = 0; j < 2; j++) {                       // two k16 halves
            uint32_t ah[2][4], al[2][4];
#pragma unroll
            for (int t = 0; t < 2; t++) {
                uint32_t off = (uint32_t)(wm + t * 16 + a_row) * 80 + j * 32 + a_hi;
                ldsm4(aAh + off, ah[t]);
                ldsm4(aAl + off, al[t]);
            }
            uint32_t bh[4][4], bl[4][4];
#pragma unroll
            for (int p = 0; p < 4; p++) {
                uint32_t off = (uint32_t)(wn + p * 16 + b_row) * 80 + j * 32 + b_hi;
                ldsm4(aBh + off, bh[p]);
                ldsm4(aBl + off, bl[p]);
            }
#pragma unroll
            for (int t = 0; t < 2; t++)
#pragma unroll
                for (int nt = 0; nt < 8; nt++) {
                    const uint32_t* bhp = &bh[nt >> 1][(nt & 1) * 2];
                    const uint32_t* blp = &bl[nt >> 1][(nt & 1) * 2];
                    mma_bf16(acc[t][nt], ah[t], bhp);
                    mma_bf16(acc[t][nt], ah[t], blp);
                    mma_bf16(acc[t][nt], al[t], bhp);
                }
        }
        __syncthreads();
    }

    // epilogue
    const int l4 = lane >> 2;
    const int l2 = (lane & 3) * 2;
#pragma unroll
    for (int t = 0; t < 2; t++) {
        const int m_lo = m0 + wm + t * 16 + l4;
        const float bi_lo = bias[m_lo];
        const float bi_hi = bias[m_lo + 8];
        float* c_lo = C + ((size_t)b * M + m_lo) * N + n0 + wn + l2;
        float* c_hi = c_lo + (size_t)8 * N;
#pragma unroll
        for (int nt = 0; nt < 8; nt++) {
            float2 v0 = {acc[t][nt][0] + bi_lo, acc[t][nt][1] + bi_lo};
            float2 v1 = {acc[t][nt][2] + bi_hi, acc[t][nt][3] + bi_hi};
            *(float2*)(c_lo + nt * 8) = v0;
            *(float2*)(c_hi + nt * 8) = v1;
        }
    }
}

// ---------------------------------------------------------------------------
// weight split: hi = bf16(w), lo = bf16(w - hi)
// ---------------------------------------------------------------------------
__global__ void wsplit_kernel(const float* __restrict__ w,
                              __nv_bfloat16* __restrict__ hi,
                              __nv_bfloat16* __restrict__ lo, int n)
{
    int i = blockIdx.x * 256 + threadIdx.x;
    if (i < n) {
        float v = w[i];
        __nv_bfloat16 h = __float2bfloat16(v);
        hi[i] = h;
        lo[i] = __float2bfloat16(v - __bfloat162float(h));
    }
}

// ---------------------------------------------------------------------------
// x transpose + split: x[b][k=256][n=4096] -> xt[b][n][k] bf16 hi/lo
// ---------------------------------------------------------------------------
__global__ void xt_kernel(const float* __restrict__ x,
                          __nv_bfloat16* __restrict__ xth,
                          __nv_bfloat16* __restrict__ xtl)
{
    __shared__ float t[32][33];
    const int n0 = blockIdx.x * 32;
    const int k0 = blockIdx.y * 32;
    const int b  = blockIdx.z;
    const int tx = threadIdx.x, ty = threadIdx.y;

    const float* src = x + ((size_t)b * 256 + k0) * NPIX + n0;
#pragma unroll
    for (int r = ty; r < 32; r += 8)
        t[r][tx] = src[(size_t)r * NPIX + tx];
    __syncthreads();
#pragma unroll
    for (int r = ty; r < 32; r += 8) {
        float v = t[tx][r];                       // x[k0+tx][n0+r]
        size_t o = ((size_t)b * NPIX + n0 + r) * 256 + k0 + tx;
        __nv_bfloat16 h = __float2bfloat16(v);
        xth[o] = h;
        xtl[o] = __float2bfloat16(v - __bfloat162float(h));
    }
}

// ---------------------------------------------------------------------------
// Fused depthwise(3x3 & 5x5) + grouped pointwise
// ---------------------------------------------------------------------------
__global__ __launch_bounds__(256)
void dwpw_kernel(const float* __restrict__ qkv,
                 const float* __restrict__ dw3_w, const float* __restrict__ dw3_b,
                 const float* __restrict__ pw3_w, const float* __restrict__ pw3_b,
                 const float* __restrict__ dw5_w, const float* __restrict__ dw5_b,
                 const float* __restrict__ pw5_w, const float* __restrict__ pw5_b,
                 float* __restrict__ s3, float* __restrict__ s5)
{
    const int ytile = blockIdx.x;
    const int g     = blockIdx.y;
    const int b     = blockIdx.z;

    __shared__ float sin_[12][8][68];
    __shared__ float w3s[24][24], w5s[24][24];
    __shared__ float w3d[12][9],  w5d[12][25];
    __shared__ float db3[12], db5[12];

    const int tid = threadIdx.x;
    const int tx  = tid & 63;
    const int ty  = tid >> 6;
    const int y0  = ytile * 4;

    for (int i = tid; i < 576; i += 256) {
        w3s[i / 24][i % 24] = pw3_w[g * 576 + i];
        w5s[i / 24][i % 24] = pw5_w[g * 576 + i];
    }

    float acc3[24], acc5[24];
#pragma unroll
    for (int o = 0; o < 24; o++) { acc3[o] = 0.f; acc5[o] = 0.f; }

    for (int ph = 0; ph < 2; ph++) {
        const int icb = ph * 12;
        __syncthreads();

        const float* src = qkv + ((size_t)b * C3 + g * 24 + icb) * NPIX;
        for (int i = tid; i < 12 * 8 * 68; i += 256) {
            int xx = i % 68;
            int r  = (i / 68) & 7;
            int c  = i / (68 * 8);
            int yy = y0 - 2 + r;
            int xg = xx - 2;
            float v = 0.f;
            if ((unsigned)yy < 64u && (unsigned)xg < 64u)
                v = src[(size_t)c * NPIX + yy * WIDTH + xg];
            sin_[c][r][xx] = v;
        }
        for (int i = tid; i < 12 * 9; i += 256)
            w3d[i / 9][i % 9] = dw3_w[(g * 24 + icb) * 9 + i];
        for (int i = tid; i < 12 * 25; i += 256)
            w5d[i / 25][i % 25] = dw5_w[(g * 24 + icb) * 25 + i];
        if (tid < 12) {
            db3[tid] = dw3_b[g * 24 + icb + tid];
            db5[tid] = dw5_b[g * 24 + icb + tid];
        }
        __syncthreads();

        for (int ic = 0; ic < 12; ic++) {
            float d3 = db3[ic];
            float d5 = db5[ic];
#pragma unroll
            for (int dy = 0; dy < 5; dy++)
#pragma unroll
                for (int dx = 0; dx < 5; dx++) {
                    float v = sin_[ic][ty + dy][tx + dx];
                    d5 += w5d[ic][dy * 5 + dx] * v;
                    if (dy >= 1 && dy <= 3 && dx >= 1 && dx <= 3)
                        d3 += w3d[ic][(dy - 1) * 3 + (dx - 1)] * v;
                }
            const int ici = icb + ic;
#pragma unroll
            for (int o = 0; o < 24; o++) {
                acc3[o] += w3s[o][ici] * d3;
                acc5[o] += w5s[o][ici] * d5;
            }
        }
    }

    const int y = y0 + ty;
    const size_t outbase = ((size_t)b * C3 + g * 24) * NPIX + y * WIDTH + tx;
#pragma unroll
    for (int o = 0; o < 24; o++) {
        s3[outbase + (size_t)o * NPIX] = acc3[o] + pw3_b[g * 24 + o];
        s5[outbase + (size_t)o * NPIX] = acc5[o] + pw5_b[g * 24 + o];
    }
}

// ---------------------------------------------------------------------------
// vk reduction
// ---------------------------------------------------------------------------
__global__ __launch_bounds__(256)
void vk_kernel(const float* __restrict__ qkv, const float* __restrict__ s3,
               const float* __restrict__ s5, float* __restrict__ vk)
{
    const int hh = blockIdx.x;
    const int b  = blockIdx.y;
    const int src_id = hh >> 5;
    const int g      = hh & 31;
    const float* base =
        (src_id == 0 ? qkv : (src_id == 1 ? s3 : s5)) +
        ((size_t)b * C3 + g * 24) * NPIX;

    float acc[9][8];
#pragma unroll
    for (int d = 0; d < 9; d++)
#pragma unroll
        for (int e = 0; e < 8; e++) acc[d][e] = 0.f;

    const int tid = threadIdx.x;
    for (int n = tid; n < NPIX; n += 256) {
        float kv[8], vv[8];
#pragma unroll
        for (int e = 0; e < 8; e++)
            kv[e] = fmaxf(base[(size_t)(8 + e) * NPIX + n], 0.f);
#pragma unroll
        for (int d = 0; d < 8; d++)
            vv[d] = base[(size_t)(16 + d) * NPIX + n];
#pragma unroll
        for (int d = 0; d < 8; d++)
#pragma unroll
            for (int e = 0; e < 8; e++)
                acc[d][e] += vv[d] * kv[e];
#pragma unroll
        for (int e = 0; e < 8; e++)
            acc[8][e] += kv[e];
    }

#pragma unroll
    for (int d = 0; d < 9; d++)
#pragma unroll
        for (int e = 0; e < 8; e++) {
            float v = acc[d][e];
            v += __shfl_xor_sync(0xffffffffu, v, 16);
            v += __shfl_xor_sync(0xffffffffu, v, 8);
            v += __shfl_xor_sync(0xffffffffu, v, 4);
            v += __shfl_xor_sync(0xffffffffu, v, 2);
            v += __shfl_xor_sync(0xffffffffu, v, 1);
            acc[d][e] = v;
        }

    __shared__ float red[8][72];
    const int wid  = tid >> 5;
    const int lane = tid & 31;
    if (lane == 0) {
#pragma unroll
        for (int d = 0; d < 9; d++)
#pragma unroll
            for (int e = 0; e < 8; e++)
                red[wid][d * 8 + e] = acc[d][e];
    }
    __syncthreads();
    if (tid < 72) {
        float s = 0.f;
#pragma unroll
        for (int w = 0; w < 8; w++) s += red[w][tid];
        vk[((size_t)b * 96 + hh) * 72 + tid] = s;
    }
}

// ---------------------------------------------------------------------------
// attention normalize -> transposed bf16-split B operand for proj GEMM
// ---------------------------------------------------------------------------
__global__ __launch_bounds__(256)
void att_kernel(const float* __restrict__ qkv, const float* __restrict__ s3,
                const float* __restrict__ s5, const float* __restrict__ vk,
                __nv_bfloat16* __restrict__ atth, __nv_bfloat16* __restrict__ attl)
{
    const int hh = blockIdx.x;
    const int b  = blockIdx.y;
    const int src_id = hh >> 5;
    const int g      = hh & 31;
    const float* base =
        (src_id == 0 ? qkv : (src_id == 1 ? s3 : s5)) +
        ((size_t)b * C3 + g * 24) * NPIX;

    __shared__ float vs[72];
    const int tid = threadIdx.x;
    if (tid < 72) vs[tid] = vk[((size_t)b * 96 + hh) * 72 + tid];
    __syncthreads();

    for (int n = tid; n < NPIX; n += 256) {
        float q[8];
#pragma unroll
        for (int e = 0; e < 8; e++)
            q[e] = fmaxf(base[(size_t)e * NPIX + n], 0.f);
        float den = 1e-15f;
#pragma unroll
        for (int e = 0; e < 8; e++) den += vs[64 + e] * q[e];
        float rd = __fdividef(1.f, den);

        __align__(16) __nv_bfloat16 hb[8];
        __align__(16) __nv_bfloat16 lb[8];
#pragma unroll
        for (int d = 0; d < 8; d++) {
            float num = 0.f;
#pragma unroll
            for (int e = 0; e < 8; e++) num += vs[d * 8 + e] * q[e];
            float val = num * rd;
            __nv_bfloat16 h = __float2bfloat16(val);
            hb[d] = h;
            lb[d] = __float2bfloat16(val - __bfloat162float(h));
        }
        size_t o = ((size_t)b * NPIX + n) * C3 + hh * 8;
        *(uint4*)(atth + o) = *(const uint4*)hb;
        *(uint4*)(attl + o) = *(const uint4*)lb;
    }
}

// ---------------------------------------------------------------------------
extern "C" void kernel_launch(void* const* d_in, const int* in_sizes, int n_in,
                              void* d_out, int out_size)
{
    const float* x      = (const float*)d_in[0];
    const float* qkv_w  = (const float*)d_in[1];
    const float* qkv_b  = (const float*)d_in[2];
    const float* dw3_w  = (const float*)d_in[3];
    const float* dw3_b  = (const float*)d_in[4];
    const float* pw3_w  = (const float*)d_in[5];
    const float* pw3_b  = (const float*)d_in[6];
    const float* dw5_w  = (const float*)d_in[7];
    const float* dw5_b  = (const float*)d_in[8];
    const float* pw5_w  = (const float*)d_in[9];
    const float* pw5_b  = (const float*)d_in[10];
    const float* proj_w = (const float*)d_in[11];
    const float* proj_b = (const float*)d_in[12];
    float* out = (float*)d_out;

    void *p;
    cudaGetSymbolAddress(&p, g_qkv);  float* qkv = (float*)p;
    cudaGetSymbolAddress(&p, g_s3);   float* s3  = (float*)p;
    cudaGetSymbolAddress(&p, g_s5);   float* s5  = (float*)p;
    cudaGetSymbolAddress(&p, g_vk);   float* vkb = (float*)p;
    cudaGetSymbolAddress(&p, g_xt_h); __nv_bfloat16* xth = (__nv_bfloat16*)p;
    cudaGetSymbolAddress(&p, g_xt_l); __nv_bfloat16* xtl = (__nv_bfloat16*)p;
    cudaGetSymbolAddress(&p, g_at_h); __nv_bfloat16* ath = (__nv_bfloat16*)p;
    cudaGetSymbolAddress(&p, g_at_l); __nv_bfloat16* atl = (__nv_bfloat16*)p;
    cudaGetSymbolAddress(&p, g_wq_h); __nv_bfloat16* wqh = (__nv_bfloat16*)p;
    cudaGetSymbolAddress(&p, g_wq_l); __nv_bfloat16* wql = (__nv_bfloat16*)p;
    cudaGetSymbolAddress(&p, g_wp_h); __nv_bfloat16* wph = (__nv_bfloat16*)p;
    cudaGetSymbolAddress(&p, g_wp_l); __nv_bfloat16* wpl = (__nv_bfloat16*)p;

    cudaFuncSetAttribute(gemm_bf16, cudaFuncAttributeMaxDynamicSharedMemorySize,
                         NSTAGE * STG_BYTES);
    const int GSM = NSTAGE * STG_BYTES;

    // 0) weight splits + x transpose/split
    wsplit_kernel<<<(C3 * 256 + 255) / 256, 256>>>(qkv_w, wqh, wql, C3 * 256);
    wsplit_kernel<<<(256 * C3 + 255) / 256, 256>>>(proj_w, wph, wpl, 256 * C3);
    xt_kernel<<<dim3(128, 8, BATCH), dim3(32, 8)>>>(x, xth, xtl);

    // 1) qkv = Wq(768,256) @ x[b](256,4096) + b
    gemm_bf16<<<dim3(NPIX / 128, C3 / 128, BATCH), 256, GSM>>>(
        wqh, wql, xth, xtl, qkv_b, qkv, C3, NPIX, 256);

    // 2) fused depthwise + grouped pointwise
    dwpw_kernel<<<dim3(16, 32, BATCH), 256>>>(
        qkv, dw3_w, dw3_b, pw3_w, pw3_b, dw5_w, dw5_b, pw5_w, pw5_b, s3, s5);

    // 3) vk reduction
    vk_kernel<<<dim3(96, BATCH), 256>>>(qkv, s3, s5, vkb);

    // 4) attention normalize -> transposed bf16 splits
    att_kernel<<<dim3(96, BATCH), 256>>>(qkv, s3, s5, vkb, ath, atl);

    // 5) out = Wp(256,768) @ att[b](768,4096) + b
    gemm_bf16<<<dim3(NPIX / 128, 256 / 128, BATCH), 256, GSM>>>(
        wph, wpl, ath, atl, proj_b, out, 256, NPIX, C3);
}

// round 4
// speedup vs baseline: 1.5111x; 1.1563x over previous
#include <cuda_runtime.h>
#include <cuda_fp16.h>
#include <cstdint>

// ---------------------------------------------------------------------------
// LiteMLA on sm_103a. GEMMs: fp16 hi/lo split (22-bit effective), 3 mma
// products, fp32 accum (mma.sync HMMA — tcgen05 not available at compute_103).
// dwpw: two-phase (depthwise f32x2 pixel-pairs -> smem -> pointwise FFMA2).
// ---------------------------------------------------------------------------

#define BATCH 8
#define C3 768
#define NPIX 4096
#define WIDTH 64

__device__ float g_qkv[(size_t)BATCH * C3 * NPIX];
__device__ float g_s3 [(size_t)BATCH * C3 * NPIX];
__device__ float g_s5 [(size_t)BATCH * C3 * NPIX];
__device__ float g_vk [(size_t)BATCH * 96 * 72];

__device__ __half g_xt_h [(size_t)BATCH * NPIX * 256];  // x^T  [b][n][k]
__device__ __half g_xt_l [(size_t)BATCH * NPIX * 256];
__device__ __half g_at_h [(size_t)BATCH * NPIX * C3];   // att^T [b][n][k]
__device__ __half g_at_l [(size_t)BATCH * NPIX * C3];
__device__ __half g_wq_h [C3 * 256];
__device__ __half g_wq_l [C3 * 256];
__device__ __half g_wp_h [256 * C3];
__device__ __half g_wp_l [256 * C3];

// ---------------------------------------------------------------------------
typedef unsigned long long ull;

__device__ __forceinline__ uint32_t smem_u32(const void* p) {
    uint32_t a;
    asm("{ .reg .u64 t; cvta.to.shared.u64 t, %1; cvt.u32.u64 %0, t; }"
        : "=r"(a) : "l"(p));
    return a;
}
__device__ __forceinline__ ull pk2(float lo, float hi) {
    ull r;
    asm("mov.b64 %0, {%1, %2};" : "=l"(r)
        : "r"(__float_as_uint(lo)), "r"(__float_as_uint(hi)));
    return r;
}
__device__ __forceinline__ void ffma2(ull& d, ull a, ull b) {
    asm("fma.rn.f32x2 %0, %1, %2, %0;" : "+l"(d) : "l"(a), "l"(b));
}
__device__ __forceinline__ float f2lo(ull v) {
    return __uint_as_float((unsigned)(v & 0xffffffffull));
}
__device__ __forceinline__ float f2hi(ull v) {
    return __uint_as_float((unsigned)(v >> 32));
}

#define CP_ASYNC16(s, g) \
    asm volatile("cp.async.cg.shared.global [%0], [%1], 16;" :: "r"(s), "l"(g))
#define CP_COMMIT() asm volatile("cp.async.commit_group;" ::: "memory")
#define CP_WAIT(n)  asm volatile("cp.async.wait_group %0;" :: "n"(n) : "memory")

__device__ __forceinline__ void ldsm4(uint32_t addr, uint32_t* r) {
    asm volatile("ldmatrix.sync.aligned.m8n8.x4.shared.b16 {%0,%1,%2,%3}, [%4];"
                 : "=r"(r[0]), "=r"(r[1]), "=r"(r[2]), "=r"(r[3]) : "r"(addr));
}
__device__ __forceinline__ void mma_f16(float* d, const uint32_t* a,
                                        const uint32_t* b) {
    asm volatile(
        "mma.sync.aligned.m16n8k16.row.col.f32.f16.f16.f32 "
        "{%0,%1,%2,%3}, {%4,%5,%6,%7}, {%8,%9}, {%0,%1,%2,%3};"
        : "+f"(d[0]), "+f"(d[1]), "+f"(d[2]), "+f"(d[3])
        : "r"(a[0]), "r"(a[1]), "r"(a[2]), "r"(a[3]), "r"(b[0]), "r"(b[1]));
}

// ---------------------------------------------------------------------------
// fp16 split GEMM: C[b](M,N) = Ah/Al(M,K) @ Bth/Btl(b,N,K)^T + bias[M]
// Block 128x128, BK=32, 3-stage cp.async ring, 8 warps (4m x 2n).
// ---------------------------------------------------------------------------
#define STG_BYTES 40960
#define OPD_BYTES 10240
#define NSTAGE 3

__device__ __forceinline__ void stage_load(
    uint32_t sbase, const __half* gA_h, const __half* gA_l,
    const __half* gB_h, const __half* gB_l, int K, int kc, int tid)
{
    const int op = tid >> 6;
    const int t  = tid & 63;
    const __half* gp =
        (op == 0) ? gA_h : (op == 1) ? gA_l : (op == 2) ? gB_h : gB_l;
    const uint32_t sb = sbase + op * OPD_BYTES;
    const __half* gk = gp + kc * 32;
#pragma unroll
    for (int it = 0; it < 8; it++) {
        int chunk = t + it * 64;
        int row = chunk >> 2;
        int c   = chunk & 3;
        CP_ASYNC16(sb + row * 80 + c * 16, gk + (size_t)row * K + c * 8);
    }
}

__global__ __launch_bounds__(256, 1)
void gemm_f16(const __half* __restrict__ Ah, const __half* __restrict__ Al,
              const __half* __restrict__ Bth, const __half* __restrict__ Btl,
              const float* __restrict__ bias, float* __restrict__ C,
              int M, int N, int K)
{
    extern __shared__ __align__(16) char smem[];
    const uint32_t sm0 = smem_u32(smem);

    const int tid  = threadIdx.x;
    const int wid  = tid >> 5;
    const int lane = tid & 31;
    const int n0 = blockIdx.x * 128;
    const int m0 = blockIdx.y * 128;
    const int b  = blockIdx.z;

    const int wm = (wid >> 1) * 32;
    const int wn = (wid & 1) * 64;

    const __half* gA_h = Ah + (size_t)m0 * K;
    const __half* gA_l = Al + (size_t)m0 * K;
    const __half* gB_h = Bth + ((size_t)b * N + n0) * K;
    const __half* gB_l = Btl + ((size_t)b * N + n0) * K;

    float acc[2][8][4];
#pragma unroll
    for (int t = 0; t < 2; t++)
#pragma unroll
        for (int nt = 0; nt < 8; nt++)
#pragma unroll
            for (int i = 0; i < 4; i++) acc[t][nt][i] = 0.f;

    const int nk = K / 32;

    stage_load(sm0, gA_h, gA_l, gB_h, gB_l, K, 0, tid);
    CP_COMMIT();
    if (nk > 1) {
        stage_load(sm0 + STG_BYTES, gA_h, gA_l, gB_h, gB_l, K, 1, tid);
        CP_COMMIT();
    }

    const int a_row = lane & 15;
    const int a_hi  = (lane >> 4) * 16;
    const int b_row = ((lane >> 4) & 1) * 8 + (lane & 7);
    const int b_hi  = ((lane >> 3) & 1) * 16;

    for (int kc = 0; kc < nk; kc++) {
        if (kc + 2 < nk) {
            stage_load(sm0 + ((kc + 2) % NSTAGE) * STG_BYTES,
                       gA_h, gA_l, gB_h, gB_l, K, kc + 2, tid);
            CP_COMMIT();
        }
        if (kc + 2 < nk)      CP_WAIT(2);
        else if (kc + 1 < nk) CP_WAIT(1);
        else                  CP_WAIT(0);
        __syncthreads();

        const uint32_t sb  = sm0 + (kc % NSTAGE) * STG_BYTES;
        const uint32_t aAh = sb;
        const uint32_t aAl = sb + OPD_BYTES;
        const uint32_t aBh = sb + 2 * OPD_BYTES;
        const uint32_t aBl = sb + 3 * OPD_BYTES;

#pragma unroll
        for (int j = 0; j < 2; j++) {
            uint32_t ah[2][4], al[2][4];
#pragma unroll
            for (int t = 0; t < 2; t++) {
                uint32_t off = (uint32_t)(wm + t * 16 + a_row) * 80 + j * 32 + a_hi;
                ldsm4(aAh + off, ah[t]);
                ldsm4(aAl + off, al[t]);
            }
            uint32_t bh[4][4], bl[4][4];
#pragma unroll
            for (int p = 0; p < 4; p++) {
                uint32_t off = (uint32_t)(wn + p * 16 + b_row) * 80 + j * 32 + b_hi;
                ldsm4(aBh + off, bh[p]);
                ldsm4(aBl + off, bl[p]);
            }
#pragma unroll
            for (int t = 0; t < 2; t++)
#pragma unroll
                for (int nt = 0; nt < 8; nt++) {
                    const uint32_t* bhp = &bh[nt >> 1][(nt & 1) * 2];
                    const uint32_t* blp = &bl[nt >> 1][(nt & 1) * 2];
                    mma_f16(acc[t][nt], ah[t], bhp);
                    mma_f16(acc[t][nt], ah[t], blp);
                    mma_f16(acc[t][nt], al[t], bhp);
                }
        }
        __syncthreads();
    }

    const int l4 = lane >> 2;
    const int l2 = (lane & 3) * 2;
#pragma unroll
    for (int t = 0; t < 2; t++) {
        const int m_lo = m0 + wm + t * 16 + l4;
        const float bi_lo = bias[m_lo];
        const float bi_hi = bias[m_lo + 8];
        float* c_lo = C + ((size_t)b * M + m_lo) * N + n0 + wn + l2;
        float* c_hi = c_lo + (size_t)8 * N;
#pragma unroll
        for (int nt = 0; nt < 8; nt++) {
            float2 v0 = {acc[t][nt][0] + bi_lo, acc[t][nt][1] + bi_lo};
            float2 v1 = {acc[t][nt][2] + bi_hi, acc[t][nt][3] + bi_hi};
            *(float2*)(c_lo + nt * 8) = v0;
            *(float2*)(c_hi + nt * 8) = v1;
        }
    }
}

// ---------------------------------------------------------------------------
// weight split: hi = fp16(w), lo = fp16(w - hi)
// ---------------------------------------------------------------------------
__global__ void wsplit_kernel(const float* __restrict__ w,
                              __half* __restrict__ hi,
                              __half* __restrict__ lo, int n)
{
    int i = blockIdx.x * 256 + threadIdx.x;
    if (i < n) {
        float v = w[i];
        __half h = __float2half_rn(v);
        hi[i] = h;
        lo[i] = __float2half_rn(v - __half2float(h));
    }
}

// ---------------------------------------------------------------------------
// x transpose + split: x[b][k=256][n=4096] -> xt[b][n][k] fp16 hi/lo
// ---------------------------------------------------------------------------
__global__ void xt_kernel(const float* __restrict__ x,
                          __half* __restrict__ xth, __half* __restrict__ xtl)
{
    __shared__ float t[32][33];
    const int n0 = blockIdx.x * 32;
    const int k0 = blockIdx.y * 32;
    const int b  = blockIdx.z;
    const int tx = threadIdx.x, ty = threadIdx.y;

    const float* src = x + ((size_t)b * 256 + k0) * NPIX + n0;
#pragma unroll
    for (int r = ty; r < 32; r += 8)
        t[r][tx] = src[(size_t)r * NPIX + tx];
    __syncthreads();
#pragma unroll
    for (int r = ty; r < 32; r += 8) {
        float v = t[tx][r];
        size_t o = ((size_t)b * NPIX + n0 + r) * 256 + k0 + tx;
        __half h = __float2half_rn(v);
        xth[o] = h;
        xtl[o] = __float2half_rn(v - __half2float(h));
    }
}

// ---------------------------------------------------------------------------
// dwpw v2: two-phase.
// A: depthwise 3x3+5x5, f32x2 packed over pixel pairs -> d3s/d5s in smem.
// B: grouped pointwise 24->24, FFMA2 with prepacked (w,w) broadcasts.
// grid (16 ytiles, 32 groups, 8 batch), 256 threads, ~90KB dyn smem.
// ---------------------------------------------------------------------------
#define OFF_SIN   0                    // float[12][8][68]      26112
#define OFF_D3    26112                // float[24][256]        24576
#define OFF_D5    50688                // float[24][256]        24576
#define OFF_W5P   75264                // ull[24][25]            4800
#define OFF_W3P   80064                // ull[24][9]             1728
#define OFF_PWP   81792                // ull[2][24][24]         9216
#define OFF_PWB   91008                // ull[2][24]              384
#define OFF_DB5   91392                // ull[24]                 192
#define OFF_DB3   91584                // ull[24]                 192
#define DW_SMEM   91776

__global__ __launch_bounds__(256, 2)
void dwpw_kernel(const float* __restrict__ qkv,
                 const float* __restrict__ dw3_w, const float* __restrict__ dw3_b,
                 const float* __restrict__ pw3_w, const float* __restrict__ pw3_b,
                 const float* __restrict__ dw5_w, const float* __restrict__ dw5_b,
                 const float* __restrict__ pw5_w, const float* __restrict__ pw5_b,
                 float* __restrict__ s3, float* __restrict__ s5)
{
    extern __shared__ __align__(16) char sm[];
    float* sin_ = (float*)(sm + OFF_SIN);     // [12][8][68]
    float* d3s  = (float*)(sm + OFF_D3);      // [24][256]
    float* d5s  = (float*)(sm + OFF_D5);
    ull*   w5p  = (ull*)(sm + OFF_W5P);       // [24][25]
    ull*   w3p  = (ull*)(sm + OFF_W3P);       // [24][9]
    ull*   pwp  = (ull*)(sm + OFF_PWP);       // [2][24][24]
    ull*   pwb  = (ull*)(sm + OFF_PWB);       // [2][24]
    ull*   db5  = (ull*)(sm + OFF_DB5);       // [24]
    ull*   db3  = (ull*)(sm + OFF_DB3);

    const int ytile = blockIdx.x;
    const int g     = blockIdx.y;
    const int b     = blockIdx.z;
    const int tid   = threadIdx.x;
    const int y0    = ytile * 4;

    // ---- table init ----
    for (int i = tid; i < 600; i += 256) {
        float w = dw5_w[(g * 24 + i / 25) * 25 + i % 25];
        w5p[i] = pk2(w, w);
    }
    for (int i = tid; i < 216; i += 256) {
        float w = dw3_w[(g * 24 + i / 9) * 9 + i % 9];
        w3p[i] = pk2(w, w);
    }
    for (int i = tid; i < 576; i += 256) {
        float a = pw3_w[g * 576 + i];
        float c = pw5_w[g * 576 + i];
        pwp[i] = pk2(a, a);
        pwp[576 + i] = pk2(c, c);
    }
    if (tid < 24) {
        float b3 = pw3_b[g * 24 + tid], b5 = pw5_b[g * 24 + tid];
        pwb[tid] = pk2(b3, b3);
        pwb[24 + tid] = pk2(b5, b5);
        float d3b = dw3_b[g * 24 + tid], d5b = dw5_b[g * 24 + tid];
        db3[tid] = pk2(d3b, d3b);
        db5[tid] = pk2(d5b, d5b);
    }

    // ---- phase A: depthwise ----
    const int pp   = tid & 127;           // pixel pair
    const int half = tid >> 7;            // channel half (6 ch each)
    const int py   = pp >> 5;             // output row 0..3
    const int px0  = (pp & 31) * 2;       // output col (even)

    for (int ph = 0; ph < 2; ph++) {
        __syncthreads();                  // tables ready / prev sin_ consumed
        const int icb = ph * 12;
        const float* src = qkv + ((size_t)b * C3 + g * 24 + icb) * NPIX;
        for (int i = tid; i < 12 * 8 * 68; i += 256) {
            int xx = i % 68;
            int r  = (i / 68) & 7;
            int c  = i / (68 * 8);
            int yy = y0 - 2 + r;
            int xg = xx - 2;
            float v = 0.f;
            if ((unsigned)yy < 64u && (unsigned)xg < 64u)
                v = src[(size_t)c * NPIX + yy * WIDTH + xg];
            sin_[(c * 8 + r) * 68 + xx] = v;
        }
        __syncthreads();

        for (int i = 0; i < 6; i++) {
            const int icl = half * 6 + i;       // 0..11 within phase
            const int ic  = icb + icl;          // 0..23 global
            ull acc5 = db5[ic];
            ull acc3 = db3[ic];
#pragma unroll
            for (int dy = 0; dy < 5; dy++) {
                const float* row = &sin_[(icl * 8 + py + dy) * 68 + px0];
                // 6-wide window as 3 aligned 8B pairs (px0 even, rows 8B-aligned)
                ull p0 = *(const ull*)(row + 0);
                ull p1 = *(const ull*)(row + 2);
                ull p2 = *(const ull*)(row + 4);
                ull vv0 = p0;
                ull vv1 = pk2(f2hi(p0), f2lo(p1));
                ull vv2 = p1;
                ull vv3 = pk2(f2hi(p1), f2lo(p2));
                ull vv4 = p2;
                const ull* w5r = &w5p[ic * 25 + dy * 5];
                ffma2(acc5, w5r[0], vv0);
                ffma2(acc5, w5r[1], vv1);
                ffma2(acc5, w5r[2], vv2);
                ffma2(acc5, w5r[3], vv3);
                ffma2(acc5, w5r[4], vv4);
                if (dy >= 1 && dy <= 3) {
                    const ull* w3r = &w3p[ic * 9 + (dy - 1) * 3];
                    ffma2(acc3, w3r[0], vv1);
                    ffma2(acc3, w3r[1], vv2);
                    ffma2(acc3, w3r[2], vv3);
                }
            }
            *(ull*)&d3s[ic * 256 + pp * 2] = acc3;
            *(ull*)&d5s[ic * 256 + pp * 2] = acc5;
        }
    }
    __syncthreads();

    // ---- phase B: grouped pointwise ----
    const int conv = tid >> 7;            // 0: s3, 1: s5
    const int bp   = tid & 127;           // pixel pair
    const float* dsrc = conv ? d5s : d3s;
    const ull* wp = &pwp[conv * 576];
    const ull* bb = &pwb[conv * 24];
    float* outp = conv ? s5 : s3;

    ull d2[24];
#pragma unroll
    for (int ic = 0; ic < 24; ic++)
        d2[ic] = *(const ull*)&dsrc[ic * 256 + bp * 2];

    const int by = y0 + (bp >> 5);
    const int bx = (bp & 31) * 2;
    const size_t obase = ((size_t)b * C3 + g * 24) * NPIX + by * WIDTH + bx;

#pragma unroll
    for (int o = 0; o < 24; o++) {
        ull acc = bb[o];
        const ull* wrow = &wp[o * 24];
#pragma unroll
        for (int ic = 0; ic < 24; ic++)
            ffma2(acc, wrow[ic], d2[ic]);
        *(float2*)&outp[obase + (size_t)o * NPIX] =
            make_float2(f2lo(acc), f2hi(acc));
    }
}

// ---------------------------------------------------------------------------
// vk reduction
// ---------------------------------------------------------------------------
__global__ __launch_bounds__(256)
void vk_kernel(const float* __restrict__ qkv, const float* __restrict__ s3,
               const float* __restrict__ s5, float* __restrict__ vk)
{
    const int hh = blockIdx.x;
    const int b  = blockIdx.y;
    const int src_id = hh >> 5;
    const int g      = hh & 31;
    const float* base =
        (src_id == 0 ? qkv : (src_id == 1 ? s3 : s5)) +
        ((size_t)b * C3 + g * 24) * NPIX;

    float acc[9][8];
#pragma unroll
    for (int d = 0; d < 9; d++)
#pragma unroll
        for (int e = 0; e < 8; e++) acc[d][e] = 0.f;

    const int tid = threadIdx.x;
    for (int n = tid; n < NPIX; n += 256) {
        float kv[8], vv[8];
#pragma unroll
        for (int e = 0; e < 8; e++)
            kv[e] = fmaxf(base[(size_t)(8 + e) * NPIX + n], 0.f);
#pragma unroll
        for (int d = 0; d < 8; d++)
            vv[d] = base[(size_t)(16 + d) * NPIX + n];
#pragma unroll
        for (int d = 0; d < 8; d++)
#pragma unroll
            for (int e = 0; e < 8; e++)
                acc[d][e] += vv[d] * kv[e];
#pragma unroll
        for (int e = 0; e < 8; e++)
            acc[8][e] += kv[e];
    }

#pragma unroll
    for (int d = 0; d < 9; d++)
#pragma unroll
        for (int e = 0; e < 8; e++) {
            float v = acc[d][e];
            v += __shfl_xor_sync(0xffffffffu, v, 16);
            v += __shfl_xor_sync(0xffffffffu, v, 8);
            v += __shfl_xor_sync(0xffffffffu, v, 4);
            v += __shfl_xor_sync(0xffffffffu, v, 2);
            v += __shfl_xor_sync(0xffffffffu, v, 1);
            acc[d][e] = v;
        }

    __shared__ float red[8][72];
    const int wid  = tid >> 5;
    const int lane = tid & 31;
    if (lane == 0) {
#pragma unroll
        for (int d = 0; d < 9; d++)
#pragma unroll
            for (int e = 0; e < 8; e++)
                red[wid][d * 8 + e] = acc[d][e];
    }
    __syncthreads();
    if (tid < 72) {
        float s = 0.f;
#pragma unroll
        for (int w = 0; w < 8; w++) s += red[w][tid];
        vk[((size_t)b * 96 + hh) * 72 + tid] = s;
    }
}

// ---------------------------------------------------------------------------
// attention normalize -> transposed fp16-split B operand for proj GEMM
// ---------------------------------------------------------------------------
__global__ __launch_bounds__(256)
void att_kernel(const float* __restrict__ qkv, const float* __restrict__ s3,
                const float* __restrict__ s5, const float* __restrict__ vk,
                __half* __restrict__ atth, __half* __restrict__ attl)
{
    const int hh = blockIdx.x;
    const int b  = blockIdx.y;
    const int src_id = hh >> 5;
    const int g      = hh & 31;
    const float* base =
        (src_id == 0 ? qkv : (src_id == 1 ? s3 : s5)) +
        ((size_t)b * C3 + g * 24) * NPIX;

    __shared__ float vs[72];
    const int tid = threadIdx.x;
    if (tid < 72) vs[tid] = vk[((size_t)b * 96 + hh) * 72 + tid];
    __syncthreads();

    for (int n = tid; n < NPIX; n += 256) {
        float q[8];
#pragma unroll
        for (int e = 0; e < 8; e++)
            q[e] = fmaxf(base[(size_t)e * NPIX + n], 0.f);
        float den = 1e-15f;
#pragma unroll
        for (int e = 0; e < 8; e++) den += vs[64 + e] * q[e];
        float rd = __fdividef(1.f, den);

        __align__(16) __half hb[8];
        __align__(16) __half lb[8];
#pragma unroll
        for (int d = 0; d < 8; d++) {
            float num = 0.f;
#pragma unroll
            for (int e = 0; e < 8; e++) num += vs[d * 8 + e] * q[e];
            float val = num * rd;
            __half h = __float2half_rn(val);
            hb[d] = h;
            lb[d] = __float2half_rn(val - __half2float(h));
        }
        size_t o = ((size_t)b * NPIX + n) * C3 + hh * 8;
        *(uint4*)(atth + o) = *(const uint4*)hb;
        *(uint4*)(attl + o) = *(const uint4*)lb;
    }
}

// ---------------------------------------------------------------------------
extern "C" void kernel_launch(void* const* d_in, const int* in_sizes, int n_in,
                              void* d_out, int out_size)
{
    const float* x      = (const float*)d_in[0];
    const float* qkv_w  = (const float*)d_in[1];
    const float* qkv_b  = (const float*)d_in[2];
    const float* dw3_w  = (const float*)d_in[3];
    const float* dw3_b  = (const float*)d_in[4];
    const float* pw3_w  = (const float*)d_in[5];
    const float* pw3_b  = (const float*)d_in[6];
    const float* dw5_w  = (const float*)d_in[7];
    const float* dw5_b  = (const float*)d_in[8];
    const float* pw5_w  = (const float*)d_in[9];
    const float* pw5_b  = (const float*)d_in[10];
    const float* proj_w = (const float*)d_in[11];
    const float* proj_b = (const float*)d_in[12];
    float* out = (float*)d_out;

    void *p;
    cudaGetSymbolAddress(&p, g_qkv);  float* qkv = (float*)p;
    cudaGetSymbolAddress(&p, g_s3);   float* s3  = (float*)p;
    cudaGetSymbolAddress(&p, g_s5);   float* s5  = (float*)p;
    cudaGetSymbolAddress(&p, g_vk);   float* vkb = (float*)p;
    cudaGetSymbolAddress(&p, g_xt_h); __half* xth = (__half*)p;
    cudaGetSymbolAddress(&p, g_xt_l); __half* xtl = (__half*)p;
    cudaGetSymbolAddress(&p, g_at_h); __half* ath = (__half*)p;
    cudaGetSymbolAddress(&p, g_at_l); __half* atl = (__half*)p;
    cudaGetSymbolAddress(&p, g_wq_h); __half* wqh = (__half*)p;
    cudaGetSymbolAddress(&p, g_wq_l); __half* wql = (__half*)p;
    cudaGetSymbolAddress(&p, g_wp_h); __half* wph = (__half*)p;
    cudaGetSymbolAddress(&p, g_wp_l); __half* wpl = (__half*)p;

    cudaFuncSetAttribute(gemm_f16, cudaFuncAttributeMaxDynamicSharedMemorySize,
                         NSTAGE * STG_BYTES);
    cudaFuncSetAttribute(dwpw_kernel,
                         cudaFuncAttributeMaxDynamicSharedMemorySize, DW_SMEM);
    const int GSM = NSTAGE * STG_BYTES;

    // 0) weight splits + x transpose/split
    wsplit_kernel<<<(C3 * 256 + 255) / 256, 256>>>(qkv_w, wqh, wql, C3 * 256);
    wsplit_kernel<<<(256 * C3 + 255) / 256, 256>>>(proj_w, wph, wpl, 256 * C3);
    xt_kernel<<<dim3(128, 8, BATCH), dim3(32, 8)>>>(x, xth, xtl);

    // 1) qkv = Wq(768,256) @ x[b](256,4096) + b
    gemm_f16<<<dim3(NPIX / 128, C3 / 128, BATCH), 256, GSM>>>(
        wqh, wql, xth, xtl, qkv_b, qkv, C3, NPIX, 256);

    // 2) fused depthwise + grouped pointwise
    dwpw_kernel<<<dim3(16, 32, BATCH), 256, DW_SMEM>>>(
        qkv, dw3_w, dw3_b, pw3_w, pw3_b, dw5_w, dw5_b, pw5_w, pw5_b, s3, s5);

    // 3) vk reduction
    vk_kernel<<<dim3(96, BATCH), 256>>>(qkv, s3, s5, vkb);

    // 4) attention normalize -> transposed fp16 splits
    att_kernel<<<dim3(96, BATCH), 256>>>(qkv, s3, s5, vkb, ath, atl);

    // 5) out = Wp(256,768) @ att[b](768,4096) + b
    gemm_f16<<<dim3(NPIX / 128, 256 / 128, BATCH), 256, GSM>>>(
        wph, wpl, ath, atl, proj_b, out, 256, NPIX, C3);
}

// round 5
// speedup vs baseline: 1.7922x; 1.1860x over previous
#include <cuda_runtime.h>
#include <cuda_fp16.h>
#include <cstdint>

// ---------------------------------------------------------------------------
// LiteMLA on sm_103a. GEMMs: fp16 hi/lo split, 3 mma products, fp32 accum,
// B operand in natural [k][n] layout via ldmatrix.trans (coalesced producers).
// dwpw: depthwise f32x2 -> grouped pointwise FFMA2 -> fused vk outer-product.
// ---------------------------------------------------------------------------

#define BATCH 8
#define C3 768
#define NPIX 4096
#define WIDTH 64

__device__ float g_qkv[(size_t)BATCH * C3 * NPIX];
__device__ float g_s3q[(size_t)BATCH * 32 * 8 * NPIX];   // q channels only
__device__ float g_s5q[(size_t)BATCH * 32 * 8 * NPIX];
__device__ float g_vk [(size_t)BATCH * 96 * 72];

__device__ __half g_xt_h [(size_t)BATCH * 256 * NPIX];   // x split [b][k][n]
__device__ __half g_xt_l [(size_t)BATCH * 256 * NPIX];
__device__ __half g_at_h [(size_t)BATCH * C3 * NPIX];    // att split [b][k][n]
__device__ __half g_at_l [(size_t)BATCH * C3 * NPIX];
__device__ __half g_wq_h [C3 * 256];
__device__ __half g_wq_l [C3 * 256];
__device__ __half g_wp_h [256 * C3];
__device__ __half g_wp_l [256 * C3];

// ---------------------------------------------------------------------------
typedef unsigned long long ull;

__device__ __forceinline__ uint32_t smem_u32(const void* p) {
    uint32_t a;
    asm("{ .reg .u64 t; cvta.to.shared.u64 t, %1; cvt.u32.u64 %0, t; }"
        : "=r"(a) : "l"(p));
    return a;
}
__device__ __forceinline__ ull pk2(float lo, float hi) {
    ull r;
    asm("mov.b64 %0, {%1, %2};" : "=l"(r)
        : "r"(__float_as_uint(lo)), "r"(__float_as_uint(hi)));
    return r;
}
__device__ __forceinline__ void ffma2(ull& d, ull a, ull b) {
    asm("fma.rn.f32x2 %0, %1, %2, %0;" : "+l"(d) : "l"(a), "l"(b));
}
__device__ __forceinline__ float f2lo(ull v) {
    return __uint_as_float((unsigned)(v & 0xffffffffull));
}
__device__ __forceinline__ float f2hi(ull v) {
    return __uint_as_float((unsigned)(v >> 32));
}

#define CP_ASYNC16(s, g) \
    asm volatile("cp.async.cg.shared.global [%0], [%1], 16;" :: "r"(s), "l"(g))
#define CP_COMMIT() asm volatile("cp.async.commit_group;" ::: "memory")
#define CP_WAIT(n)  asm volatile("cp.async.wait_group %0;" :: "n"(n) : "memory")

__device__ __forceinline__ void ldsm4(uint32_t addr, uint32_t* r) {
    asm volatile("ldmatrix.sync.aligned.m8n8.x4.shared.b16 {%0,%1,%2,%3}, [%4];"
                 : "=r"(r[0]), "=r"(r[1]), "=r"(r[2]), "=r"(r[3]) : "r"(addr));
}
__device__ __forceinline__ void ldsm4t(uint32_t addr, uint32_t* r) {
    asm volatile("ldmatrix.sync.aligned.m8n8.x4.trans.shared.b16 {%0,%1,%2,%3}, [%4];"
                 : "=r"(r[0]), "=r"(r[1]), "=r"(r[2]), "=r"(r[3]) : "r"(addr));
}
__device__ __forceinline__ void mma_f16(float* d, const uint32_t* a,
                                        const uint32_t* b) {
    asm volatile(
        "mma.sync.aligned.m16n8k16.row.col.f32.f16.f16.f32 "
        "{%0,%1,%2,%3}, {%4,%5,%6,%7}, {%8,%9}, {%0,%1,%2,%3};"
        : "+f"(d[0]), "+f"(d[1]), "+f"(d[2]), "+f"(d[3])
        : "r"(a[0]), "r"(a[1]), "r"(a[2]), "r"(a[3]), "r"(b[0]), "r"(b[1]));
}

// ---------------------------------------------------------------------------
// fp16 split GEMM: C[b](M,N) = Ah/Al(M,K) @ Bh/Bl(b,K,N) + bias[M]
// A row-major [m][k] (pitch 80B smem); B natural [k][n] (pitch 272B smem,
// ldmatrix.trans fragments). Block 128x128, BK=32, 2-stage, 2 CTAs/SM.
// ---------------------------------------------------------------------------
#define A_PITCH 80
#define B_PITCH 272
#define OFF_AL  10240
#define OFF_BH  20480
#define OFF_BL  29184
#define STG2    37888

__device__ __forceinline__ void stage_load(
    uint32_t sbase, const __half* gA_h, const __half* gA_l,
    const __half* gB_h, const __half* gB_l, int K, int N, int kc, int tid)
{
    const int op = tid >> 6;
    const int t  = tid & 63;
    if (op < 2) {
        const __half* g = ((op == 0) ? gA_h : gA_l) + kc * 32;
        const uint32_t sb = sbase + op * OFF_AL;
#pragma unroll
        for (int it = 0; it < 8; it++) {
            int chunk = t + it * 64;
            int row = chunk >> 2, c = chunk & 3;
            CP_ASYNC16(sb + row * A_PITCH + c * 16, g + (size_t)row * K + c * 8);
        }
    } else {
        const __half* g = ((op == 2) ? gB_h : gB_l) + (size_t)kc * 32 * N;
        const uint32_t sb = sbase + ((op == 2) ? OFF_BH : OFF_BL);
#pragma unroll
        for (int it = 0; it < 8; it++) {
            int chunk = t + it * 64;
            int row = chunk >> 4, c = chunk & 15;
            CP_ASYNC16(sb + row * B_PITCH + c * 16, g + (size_t)row * N + c * 8);
        }
    }
}

__global__ __launch_bounds__(256, 2)
void gemm_f16(const __half* __restrict__ Ah, const __half* __restrict__ Al,
              const __half* __restrict__ Bmh, const __half* __restrict__ Bml,
              const float* __restrict__ bias, float* __restrict__ C,
              int M, int N, int K)
{
    extern __shared__ __align__(16) char smem[];
    const uint32_t sm0 = smem_u32(smem);

    const int tid  = threadIdx.x;
    const int wid  = tid >> 5;
    const int lane = tid & 31;
    const int n0 = blockIdx.x * 128;
    const int m0 = blockIdx.y * 128;
    const int b  = blockIdx.z;

    const int wm = (wid >> 1) * 32;
    const int wn = (wid & 1) * 64;

    const __half* gA_h = Ah + (size_t)m0 * K;
    const __half* gA_l = Al + (size_t)m0 * K;
    const __half* gB_h = Bmh + (size_t)b * K * N + n0;
    const __half* gB_l = Bml + (size_t)b * K * N + n0;

    float acc[2][8][4];
#pragma unroll
    for (int t = 0; t < 2; t++)
#pragma unroll
        for (int nt = 0; nt < 8; nt++)
#pragma unroll
            for (int i = 0; i < 4; i++) acc[t][nt][i] = 0.f;

    const int nk = K / 32;

    stage_load(sm0, gA_h, gA_l, gB_h, gB_l, K, N, 0, tid);
    CP_COMMIT();
    if (nk > 1) {
        stage_load(sm0 + STG2, gA_h, gA_l, gB_h, gB_l, K, N, 1, tid);
        CP_COMMIT();
    }

    // A fragment addressing (row-major, non-trans)
    const int a_row = lane & 15;
    const int a_hi  = (lane >> 4) * 16;
    // B fragment addressing (k-major rows, trans)
    const int b_kr = (lane & 7) + ((lane >> 3) & 1) * 8;   // k row within k16
    const int b_nc = (lane >> 4) * 8;                      // n col offset

    for (int kc = 0; kc < nk; kc++) {
        if (kc + 1 < nk) CP_WAIT(1); else CP_WAIT(0);
        __syncthreads();

        const uint32_t sb  = sm0 + (kc & 1) * STG2;
        const uint32_t aAh = sb;
        const uint32_t aAl = sb + OFF_AL;
        const uint32_t aBh = sb + OFF_BH;
        const uint32_t aBl = sb + OFF_BL;

#pragma unroll
        for (int j = 0; j < 2; j++) {
            uint32_t ah[2][4], al[2][4];
#pragma unroll
            for (int t = 0; t < 2; t++) {
                uint32_t off = (uint32_t)(wm + t * 16 + a_row) * A_PITCH + j * 32 + a_hi;
                ldsm4(aAh + off, ah[t]);
                ldsm4(aAl + off, al[t]);
            }
            uint32_t bh[4][4], bl[4][4];
#pragma unroll
            for (int p = 0; p < 4; p++) {
                uint32_t off = (uint32_t)(j * 16 + b_kr) * B_PITCH +
                               (uint32_t)(wn + p * 16 + b_nc) * 2;
                ldsm4t(aBh + off, bh[p]);
                ldsm4t(aBl + off, bl[p]);
            }
#pragma unroll
            for (int t = 0; t < 2; t++)
#pragma unroll
                for (int nt = 0; nt < 8; nt++) {
                    const uint32_t* bhp = &bh[nt >> 1][(nt & 1) * 2];
                    const uint32_t* blp = &bl[nt >> 1][(nt & 1) * 2];
                    mma_f16(acc[t][nt], ah[t], bhp);
                    mma_f16(acc[t][nt], ah[t], blp);
                    mma_f16(acc[t][nt], al[t], bhp);
                }
        }
        __syncthreads();
        if (kc + 2 < nk) {
            stage_load(sm0 + (kc & 1) * STG2, gA_h, gA_l, gB_h, gB_l,
                       K, N, kc + 2, tid);
            CP_COMMIT();
        }
    }

    const int l4 = lane >> 2;
    const int l2 = (lane & 3) * 2;
#pragma unroll
    for (int t = 0; t < 2; t++) {
        const int m_lo = m0 + wm + t * 16 + l4;
        const float bi_lo = bias[m_lo];
        const float bi_hi = bias[m_lo + 8];
        float* c_lo = C + ((size_t)b * M + m_lo) * N + n0 + wn + l2;
        float* c_hi = c_lo + (size_t)8 * N;
#pragma unroll
        for (int nt = 0; nt < 8; nt++) {
            float2 v0 = {acc[t][nt][0] + bi_lo, acc[t][nt][1] + bi_lo};
            float2 v1 = {acc[t][nt][2] + bi_hi, acc[t][nt][3] + bi_hi};
            *(float2*)(c_lo + nt * 8) = v0;
            *(float2*)(c_hi + nt * 8) = v1;
        }
    }
}

// ---------------------------------------------------------------------------
// elementwise split: hi = fp16(v), lo = fp16(v - hi)   (weights AND x)
// ---------------------------------------------------------------------------
__global__ void wsplit_kernel(const float* __restrict__ w,
                              __half* __restrict__ hi,
                              __half* __restrict__ lo, int n)
{
    int i = blockIdx.x * 256 + threadIdx.x;
    if (i < n) {
        float v = w[i];
        __half h = __float2half_rn(v);
        hi[i] = h;
        lo[i] = __float2half_rn(v - __half2float(h));
    }
}

__global__ void zero_vk_kernel(float* __restrict__ vk)
{
    int i = blockIdx.x * 256 + threadIdx.x;
    if (i < BATCH * 96 * 72) vk[i] = 0.f;
}

// ---------------------------------------------------------------------------
// dwpw v3: depthwise (f32x2) -> grouped pointwise (FFMA2) -> fused vk.
// Writes only q channels (o<8) of s3/s5 to compact global; k/v channels feed
// an in-block vk outer-product accumulated via atomicAdd.
// grid (16 ytiles, 32 groups, 8 batch), 256 threads.
// ---------------------------------------------------------------------------
#define OFF_SIN   0                    // float[12][8][68]      26112
#define OFF_D3    26112                // float[24][256] / kvq overlay
#define OFF_D5    50688                // float[24][256]
#define OFF_W5P   75264                // ull[24][25]            4800
#define OFF_W3P   80064                // ull[24][9]             1728
#define OFF_PWP   81792                // ull[2][24][24] / red overlay 9216
#define OFF_PWB   91008                // ull[2][24]              384
#define OFF_DB5   91392                // ull[24]                 192
#define OFF_DB3   91584                // ull[24]                 192
#define DW_SMEM   91776

__global__ __launch_bounds__(256, 2)
void dwpw_kernel(const float* __restrict__ qkv,
                 const float* __restrict__ dw3_w, const float* __restrict__ dw3_b,
                 const float* __restrict__ pw3_w, const float* __restrict__ pw3_b,
                 const float* __restrict__ dw5_w, const float* __restrict__ dw5_b,
                 const float* __restrict__ pw5_w, const float* __restrict__ pw5_b,
                 float* __restrict__ s3q, float* __restrict__ s5q,
                 float* __restrict__ vkg)
{
    extern __shared__ __align__(16) char sm[];
    float* sin_ = (float*)(sm + OFF_SIN);
    float* d3s  = (float*)(sm + OFF_D3);
    float* d5s  = (float*)(sm + OFF_D5);
    ull*   kvq  = (ull*)(sm + OFF_D3);       // overlay (phase B/C)
    float* red  = (float*)(sm + OFF_PWP);    // overlay (phase C) [2][16][72]
    ull*   w5p  = (ull*)(sm + OFF_W5P);
    ull*   w3p  = (ull*)(sm + OFF_W3P);
    ull*   pwp  = (ull*)(sm + OFF_PWP);
    ull*   pwb  = (ull*)(sm + OFF_PWB);
    ull*   db5  = (ull*)(sm + OFF_DB5);
    ull*   db3  = (ull*)(sm + OFF_DB3);

    const int ytile = blockIdx.x;
    const int g     = blockIdx.y;
    const int b     = blockIdx.z;
    const int tid   = threadIdx.x;
    const int y0    = ytile * 4;

    for (int i = tid; i < 600; i += 256) {
        float w = dw5_w[(g * 24 + i / 25) * 25 + i % 25];
        w5p[i] = pk2(w, w);
    }
    for (int i = tid; i < 216; i += 256) {
        float w = dw3_w[(g * 24 + i / 9) * 9 + i % 9];
        w3p[i] = pk2(w, w);
    }
    for (int i = tid; i < 576; i += 256) {
        float a = pw3_w[g * 576 + i];
        float c = pw5_w[g * 576 + i];
        pwp[i] = pk2(a, a);
        pwp[576 + i] = pk2(c, c);
    }
    if (tid < 24) {
        float b3 = pw3_b[g * 24 + tid], b5 = pw5_b[g * 24 + tid];
        pwb[tid] = pk2(b3, b3);
        pwb[24 + tid] = pk2(b5, b5);
        float d3b = dw3_b[g * 24 + tid], d5b = dw5_b[g * 24 + tid];
        db3[tid] = pk2(d3b, d3b);
        db5[tid] = pk2(d5b, d5b);
    }

    // ---- phase A: depthwise ----
    const int pp   = tid & 127;
    const int half = tid >> 7;
    const int py   = pp >> 5;
    const int px0  = (pp & 31) * 2;

    for (int ph = 0; ph < 2; ph++) {
        __syncthreads();
        const int icb = ph * 12;
        const float* src = qkv + ((size_t)b * C3 + g * 24 + icb) * NPIX;
        for (int i = tid; i < 12 * 8 * 68; i += 256) {
            int xx = i % 68;
            int r  = (i / 68) & 7;
            int c  = i / (68 * 8);
            int yy = y0 - 2 + r;
            int xg = xx - 2;
            float v = 0.f;
            if ((unsigned)yy < 64u && (unsigned)xg < 64u)
                v = src[(size_t)c * NPIX + yy * WIDTH + xg];
            sin_[(c * 8 + r) * 68 + xx] = v;
        }
        __syncthreads();

        for (int i = 0; i < 6; i++) {
            const int icl = half * 6 + i;
            const int ic  = icb + icl;
            ull acc5 = db5[ic];
            ull acc3 = db3[ic];
#pragma unroll
            for (int dy = 0; dy < 5; dy++) {
                const float* row = &sin_[(icl * 8 + py + dy) * 68 + px0];
                ull p0 = *(const ull*)(row + 0);
                ull p1 = *(const ull*)(row + 2);
                ull p2 = *(const ull*)(row + 4);
                ull vv1 = pk2(f2hi(p0), f2lo(p1));
                ull vv3 = pk2(f2hi(p1), f2lo(p2));
                const ull* w5r = &w5p[ic * 25 + dy * 5];
                ffma2(acc5, w5r[0], p0);
                ffma2(acc5, w5r[1], vv1);
                ffma2(acc5, w5r[2], p1);
                ffma2(acc5, w5r[3], vv3);
                ffma2(acc5, w5r[4], p2);
                if (dy >= 1 && dy <= 3) {
                    const ull* w3r = &w3p[ic * 9 + (dy - 1) * 3];
                    ffma2(acc3, w3r[0], vv1);
                    ffma2(acc3, w3r[1], p1);
                    ffma2(acc3, w3r[2], vv3);
                }
            }
            *(ull*)&d3s[ic * 256 + pp * 2] = acc3;
            *(ull*)&d5s[ic * 256 + pp * 2] = acc5;
        }
    }
    __syncthreads();

    // ---- phase B: grouped pointwise ----
    const int conv = tid >> 7;
    const int bp   = tid & 127;
    const float* dsrc = conv ? d5s : d3s;
    const ull* wp = &pwp[conv * 576];
    const ull* bb = &pwb[conv * 24];
    float* qout = conv ? s5q : s3q;

    ull d2[24];
#pragma unroll
    for (int ic = 0; ic < 24; ic++)
        d2[ic] = *(const ull*)&dsrc[ic * 256 + bp * 2];
    __syncthreads();   // d3s/d5s fully consumed; kvq overlay may be written

    const int by = y0 + (bp >> 5);
    const int bx = (bp & 31) * 2;
    const size_t qbase = (((size_t)b * 32 + g) * 8) * NPIX + by * WIDTH + bx;

#pragma unroll
    for (int o = 0; o < 24; o++) {
        ull acc = bb[o];
        const ull* wrow = &wp[o * 24];
#pragma unroll
        for (int ic = 0; ic < 24; ic++)
            ffma2(acc, wrow[ic], d2[ic]);
        if (o < 8) {
            *(float2*)&qout[qbase + (size_t)o * NPIX] =
                make_float2(f2lo(acc), f2hi(acc));
        } else {
            kvq[(conv * 16 + (o - 8)) * 128 + bp] = acc;
        }
    }
    __syncthreads();

    // ---- phase C: vk outer product + reduce + atomicAdd ----
    {
        const int w    = tid >> 5;
        const int lane = tid & 31;
        const int cv   = w >> 2;          // conv
        const int sub  = w & 3;
        const int pair = sub * 32 + lane;

        ull kvv[16];
#pragma unroll
        for (int ch = 0; ch < 16; ch++)
            kvv[ch] = kvq[(cv * 16 + ch) * 128 + pair];

        float acc[9][8];
#pragma unroll
        for (int d = 0; d < 9; d++)
#pragma unroll
            for (int e = 0; e < 8; e++) acc[d][e] = 0.f;

#pragma unroll
        for (int hx = 0; hx < 2; hx++) {
            float kk[8], vv[8];
#pragma unroll
            for (int e = 0; e < 8; e++)
                kk[e] = fmaxf(hx ? f2hi(kvv[e]) : f2lo(kvv[e]), 0.f);
#pragma unroll
            for (int d = 0; d < 8; d++)
                vv[d] = hx ? f2hi(kvv[8 + d]) : f2lo(kvv[8 + d]);
#pragma unroll
            for (int d = 0; d < 8; d++)
#pragma unroll
                for (int e = 0; e < 8; e++)
                    acc[d][e] += vv[d] * kk[e];
#pragma unroll
            for (int e = 0; e < 8; e++)
                acc[8][e] += kk[e];
        }

        // partial butterfly (3 levels): lanes 0..3 hold partials mod 4
#pragma unroll
        for (int d = 0; d < 9; d++)
#pragma unroll
            for (int e = 0; e < 8; e++) {
                float v = acc[d][e];
                v += __shfl_xor_sync(0xffffffffu, v, 16);
                v += __shfl_xor_sync(0xffffffffu, v, 8);
                v += __shfl_xor_sync(0xffffffffu, v, 4);
                acc[d][e] = v;
            }
        if (lane < 4) {
            float* rp = &red[((cv * 16) + sub * 4 + lane) * 72];
#pragma unroll
            for (int d = 0; d < 9; d++)
#pragma unroll
                for (int e = 0; e < 8; e++)
                    rp[d * 8 + e] = acc[d][e];
        }
    }
    __syncthreads();

    if (tid < 144) {
        const int cv  = tid / 72;
        const int idx = tid % 72;
        float s = 0.f;
#pragma unroll
        for (int j = 0; j < 16; j++)
            s += red[(cv * 16 + j) * 72 + idx];
        atomicAdd(&vkg[((size_t)b * 96 + 32 + cv * 32 + g) * 72 + idx], s);
    }
}

// ---------------------------------------------------------------------------
// vk reduction for qkv source heads (0..31)
// ---------------------------------------------------------------------------
__global__ __launch_bounds__(256)
void vk_kernel(const float* __restrict__ qkv, float* __restrict__ vk)
{
    const int g = blockIdx.x;     // head 0..31
    const int b = blockIdx.y;
    const float* base = qkv + ((size_t)b * C3 + g * 24) * NPIX;

    float acc[9][8];
#pragma unroll
    for (int d = 0; d < 9; d++)
#pragma unroll
        for (int e = 0; e < 8; e++) acc[d][e] = 0.f;

    const int tid = threadIdx.x;
    for (int n = tid; n < NPIX; n += 256) {
        float kv[8], vv[8];
#pragma unroll
        for (int e = 0; e < 8; e++)
            kv[e] = fmaxf(base[(size_t)(8 + e) * NPIX + n], 0.f);
#pragma unroll
        for (int d = 0; d < 8; d++)
            vv[d] = base[(size_t)(16 + d) * NPIX + n];
#pragma unroll
        for (int d = 0; d < 8; d++)
#pragma unroll
            for (int e = 0; e < 8; e++)
                acc[d][e] += vv[d] * kv[e];
#pragma unroll
        for (int e = 0; e < 8; e++)
            acc[8][e] += kv[e];
    }

#pragma unroll
    for (int d = 0; d < 9; d++)
#pragma unroll
        for (int e = 0; e < 8; e++) {
            float v = acc[d][e];
            v += __shfl_xor_sync(0xffffffffu, v, 16);
            v += __shfl_xor_sync(0xffffffffu, v, 8);
            v += __shfl_xor_sync(0xffffffffu, v, 4);
            v += __shfl_xor_sync(0xffffffffu, v, 2);
            v += __shfl_xor_sync(0xffffffffu, v, 1);
            acc[d][e] = v;
        }

    __shared__ float red[8][72];
    const int wid  = tid >> 5;
    const int lane = tid & 31;
    if (lane == 0) {
#pragma unroll
        for (int d = 0; d < 9; d++)
#pragma unroll
            for (int e = 0; e < 8; e++)
                red[wid][d * 8 + e] = acc[d][e];
    }
    __syncthreads();
    if (tid < 72) {
        float s = 0.f;
#pragma unroll
        for (int w = 0; w < 8; w++) s += red[w][tid];
        vk[((size_t)b * 96 + g) * 72 + tid] = s;
    }
}

// ---------------------------------------------------------------------------
// attention normalize -> channel-major fp16 split [b][768][4096] (coalesced)
// ---------------------------------------------------------------------------
__global__ __launch_bounds__(256)
void att_kernel(const float* __restrict__ qkv, const float* __restrict__ s3q,
                const float* __restrict__ s5q, const float* __restrict__ vk,
                __half* __restrict__ atth, __half* __restrict__ attl)
{
    const int hh = blockIdx.x;
    const int b  = blockIdx.y;
    const int src_id = hh >> 5;
    const int g      = hh & 31;
    const float* base;
    if (src_id == 0)      base = qkv + ((size_t)b * C3 + g * 24) * NPIX;
    else if (src_id == 1) base = s3q + (((size_t)b * 32 + g) * 8) * NPIX;
    else                  base = s5q + (((size_t)b * 32 + g) * 8) * NPIX;

    __shared__ float vs[72];
    const int tid = threadIdx.x;
    if (tid < 72) vs[tid] = vk[((size_t)b * 96 + hh) * 72 + tid];
    __syncthreads();

    __half* oh = atth + ((size_t)b * C3 + hh * 8) * NPIX;
    __half* ol = attl + ((size_t)b * C3 + hh * 8) * NPIX;

    for (int n2 = tid; n2 < NPIX / 2; n2 += 256) {
        const int n = n2 * 2;
        float q0[8], q1[8];
#pragma unroll
        for (int e = 0; e < 8; e++) {
            float2 qq = *(const float2*)(base + (size_t)e * NPIX + n);
            q0[e] = fmaxf(qq.x, 0.f);
            q1[e] = fmaxf(qq.y, 0.f);
        }
        float den0 = 1e-15f, den1 = 1e-15f;
#pragma unroll
        for (int e = 0; e < 8; e++) {
            den0 += vs[64 + e] * q0[e];
            den1 += vs[64 + e] * q1[e];
        }
        float rd0 = __fdividef(1.f, den0);
        float rd1 = __fdividef(1.f, den1);
#pragma unroll
        for (int d = 0; d < 8; d++) {
            float num0 = 0.f, num1 = 0.f;
#pragma unroll
            for (int e = 0; e < 8; e++) {
                num0 += vs[d * 8 + e] * q0[e];
                num1 += vs[d * 8 + e] * q1[e];
            }
            float v0 = num0 * rd0, v1 = num1 * rd1;
            __half h0 = __float2half_rn(v0), h1 = __float2half_rn(v1);
            __half l0 = __float2half_rn(v0 - __half2float(h0));
            __half l1 = __float2half_rn(v1 - __half2float(h1));
            __half2 hp; hp.x = h0; hp.y = h1;
            __half2 lp; lp.x = l0; lp.y = l1;
            *(__half2*)(oh + (size_t)d * NPIX + n) = hp;
            *(__half2*)(ol + (size_t)d * NPIX + n) = lp;
        }
    }
}

// ---------------------------------------------------------------------------
extern "C" void kernel_launch(void* const* d_in, const int* in_sizes, int n_in,
                              void* d_out, int out_size)
{
    const float* x      = (const float*)d_in[0];
    const float* qkv_w  = (const float*)d_in[1];
    const float* qkv_b  = (const float*)d_in[2];
    const float* dw3_w  = (const float*)d_in[3];
    const float* dw3_b  = (const float*)d_in[4];
    const float* pw3_w  = (const float*)d_in[5];
    const float* pw3_b  = (const float*)d_in[6];
    const float* dw5_w  = (const float*)d_in[7];
    const float* dw5_b  = (const float*)d_in[8];
    const float* pw5_w  = (const float*)d_in[9];
    const float* pw5_b  = (const float*)d_in[10];
    const float* proj_w = (const float*)d_in[11];
    const float* proj_b = (const float*)d_in[12];
    float* out = (float*)d_out;

    void *p;
    cudaGetSymbolAddress(&p, g_qkv);  float* qkv = (float*)p;
    cudaGetSymbolAddress(&p, g_s3q);  float* s3q = (float*)p;
    cudaGetSymbolAddress(&p, g_s5q);  float* s5q = (float*)p;
    cudaGetSymbolAddress(&p, g_vk);   float* vkb = (float*)p;
    cudaGetSymbolAddress(&p, g_xt_h); __half* xth = (__half*)p;
    cudaGetSymbolAddress(&p, g_xt_l); __half* xtl = (__half*)p;
    cudaGetSymbolAddress(&p, g_at_h); __half* ath = (__half*)p;
    cudaGetSymbolAddress(&p, g_at_l); __half* atl = (__half*)p;
    cudaGetSymbolAddress(&p, g_wq_h); __half* wqh = (__half*)p;
    cudaGetSymbolAddress(&p, g_wq_l); __half* wql = (__half*)p;
    cudaGetSymbolAddress(&p, g_wp_h); __half* wph = (__half*)p;
    cudaGetSymbolAddress(&p, g_wp_l); __half* wpl = (__half*)p;

    cudaFuncSetAttribute(gemm_f16, cudaFuncAttributeMaxDynamicSharedMemorySize,
                         2 * STG2);
    cudaFuncSetAttribute(dwpw_kernel,
                         cudaFuncAttributeMaxDynamicSharedMemorySize, DW_SMEM);
    const int GSM = 2 * STG2;

    // 0) splits (weights + x, no transpose needed — B is [k][n] now)
    wsplit_kernel<<<(C3 * 256 + 255) / 256, 256>>>(qkv_w, wqh, wql, C3 * 256);
    wsplit_kernel<<<(256 * C3 + 255) / 256, 256>>>(proj_w, wph, wpl, 256 * C3);
    wsplit_kernel<<<(BATCH * 256 * NPIX + 255) / 256, 256>>>(
        x, xth, xtl, BATCH * 256 * NPIX);

    // 1) qkv = Wq(768,256) @ x[b](256,4096) + b
    gemm_f16<<<dim3(NPIX / 128, C3 / 128, BATCH), 256, GSM>>>(
        wqh, wql, xth, xtl, qkv_b, qkv, C3, NPIX, 256);

    // 2) zero vk accumulators, then fused dwpw (+ s3/s5 vk via atomics)
    zero_vk_kernel<<<(BATCH * 96 * 72 + 255) / 256, 256>>>(vkb);
    dwpw_kernel<<<dim3(16, 32, BATCH), 256, DW_SMEM>>>(
        qkv, dw3_w, dw3_b, pw3_w, pw3_b, dw5_w, dw5_b, pw5_w, pw5_b,
        s3q, s5q, vkb);

    // 3) vk for qkv-source heads
    vk_kernel<<<dim3(32, BATCH), 256>>>(qkv, vkb);

    // 4) attention normalize -> channel-major fp16 splits
    att_kernel<<<dim3(96, BATCH), 256>>>(qkv, s3q, s5q, vkb, ath, atl);

    // 5) out = Wp(256,768) @ att[b](768,4096) + b
    gemm_f16<<<dim3(NPIX / 128, 256 / 128, BATCH), 256, GSM>>>(
        wph, wpl, ath, atl, proj_b, out, 256, NPIX, C3);
}

// round 6
// speedup vs baseline: 1.8579x; 1.0366x over previous
#include <cuda_runtime.h>
#include <cuda_fp16.h>
#include <cstdint>

// ---------------------------------------------------------------------------
// LiteMLA on sm_103a. GEMMs: fp16 hi/lo split, 3 mma products, fp32 accum,
// B operand in natural [k][n] layout via ldmatrix.trans (coalesced producers).
// dwpw: depthwise f32x2 (channel x 8px threads) -> pointwise FFMA2 -> fused vk.
// ---------------------------------------------------------------------------

#define BATCH 8
#define C3 768
#define NPIX 4096
#define WIDTH 64

__device__ float g_qkv[(size_t)BATCH * C3 * NPIX];
__device__ float g_s3q[(size_t)BATCH * 32 * 8 * NPIX];   // q channels only
__device__ float g_s5q[(size_t)BATCH * 32 * 8 * NPIX];
__device__ float g_vk [(size_t)BATCH * 96 * 72];

__device__ __half g_xt_h [(size_t)BATCH * 256 * NPIX];   // x split [b][k][n]
__device__ __half g_xt_l [(size_t)BATCH * 256 * NPIX];
__device__ __half g_at_h [(size_t)BATCH * C3 * NPIX];    // att split [b][k][n]
__device__ __half g_at_l [(size_t)BATCH * C3 * NPIX];
__device__ __half g_wq_h [C3 * 256];
__device__ __half g_wq_l [C3 * 256];
__device__ __half g_wp_h [256 * C3];
__device__ __half g_wp_l [256 * C3];

// ---------------------------------------------------------------------------
typedef unsigned long long ull;

__device__ __forceinline__ uint32_t smem_u32(const void* p) {
    uint32_t a;
    asm("{ .reg .u64 t; cvta.to.shared.u64 t, %1; cvt.u32.u64 %0, t; }"
        : "=r"(a) : "l"(p));
    return a;
}
__device__ __forceinline__ ull pk2(float lo, float hi) {
    ull r;
    asm("mov.b64 %0, {%1, %2};" : "=l"(r)
        : "r"(__float_as_uint(lo)), "r"(__float_as_uint(hi)));
    return r;
}
__device__ __forceinline__ void ffma2(ull& d, ull a, ull b) {
    asm("fma.rn.f32x2 %0, %1, %2, %0;" : "+l"(d) : "l"(a), "l"(b));
}
__device__ __forceinline__ float f2lo(ull v) {
    return __uint_as_float((unsigned)(v & 0xffffffffull));
}
__device__ __forceinline__ float f2hi(ull v) {
    return __uint_as_float((unsigned)(v >> 32));
}

#define CP_ASYNC16(s, g) \
    asm volatile("cp.async.cg.shared.global [%0], [%1], 16;" :: "r"(s), "l"(g))
#define CP_COMMIT() asm volatile("cp.async.commit_group;" ::: "memory")
#define CP_WAIT(n)  asm volatile("cp.async.wait_group %0;" :: "n"(n) : "memory")

__device__ __forceinline__ void ldsm4(uint32_t addr, uint32_t* r) {
    asm volatile("ldmatrix.sync.aligned.m8n8.x4.shared.b16 {%0,%1,%2,%3}, [%4];"
                 : "=r"(r[0]), "=r"(r[1]), "=r"(r[2]), "=r"(r[3]) : "r"(addr));
}
__device__ __forceinline__ void ldsm4t(uint32_t addr, uint32_t* r) {
    asm volatile("ldmatrix.sync.aligned.m8n8.x4.trans.shared.b16 {%0,%1,%2,%3}, [%4];"
                 : "=r"(r[0]), "=r"(r[1]), "=r"(r[2]), "=r"(r[3]) : "r"(addr));
}
__device__ __forceinline__ void mma_f16(float* d, const uint32_t* a,
                                        const uint32_t* b) {
    asm volatile(
        "mma.sync.aligned.m16n8k16.row.col.f32.f16.f16.f32 "
        "{%0,%1,%2,%3}, {%4,%5,%6,%7}, {%8,%9}, {%0,%1,%2,%3};"
        : "+f"(d[0]), "+f"(d[1]), "+f"(d[2]), "+f"(d[3])
        : "r"(a[0]), "r"(a[1]), "r"(a[2]), "r"(a[3]), "r"(b[0]), "r"(b[1]));
}

// ---------------------------------------------------------------------------
// fp16 split GEMM: C[b](M,N) = Ah/Al(M,K) @ Bh/Bl(b,K,N) + bias[M]
// Block 128x128, BK=32, 2-stage, 2 CTAs/SM.  (unchanged from R5)
// ---------------------------------------------------------------------------
#define A_PITCH 80
#define B_PITCH 272
#define OFF_AL  10240
#define OFF_BH  20480
#define OFF_BL  29184
#define STG2    37888

__device__ __forceinline__ void stage_load(
    uint32_t sbase, const __half* gA_h, const __half* gA_l,
    const __half* gB_h, const __half* gB_l, int K, int N, int kc, int tid)
{
    const int op = tid >> 6;
    const int t  = tid & 63;
    if (op < 2) {
        const __half* g = ((op == 0) ? gA_h : gA_l) + kc * 32;
        const uint32_t sb = sbase + op * OFF_AL;
#pragma unroll
        for (int it = 0; it < 8; it++) {
            int chunk = t + it * 64;
            int row = chunk >> 2, c = chunk & 3;
            CP_ASYNC16(sb + row * A_PITCH + c * 16, g + (size_t)row * K + c * 8);
        }
    } else {
        const __half* g = ((op == 2) ? gB_h : gB_l) + (size_t)kc * 32 * N;
        const uint32_t sb = sbase + ((op == 2) ? OFF_BH : OFF_BL);
#pragma unroll
        for (int it = 0; it < 8; it++) {
            int chunk = t + it * 64;
            int row = chunk >> 4, c = chunk & 15;
            CP_ASYNC16(sb + row * B_PITCH + c * 16, g + (size_t)row * N + c * 8);
        }
    }
}

__global__ __launch_bounds__(256, 2)
void gemm_f16(const __half* __restrict__ Ah, const __half* __restrict__ Al,
              const __half* __restrict__ Bmh, const __half* __restrict__ Bml,
              const float* __restrict__ bias, float* __restrict__ C,
              int M, int N, int K)
{
    extern __shared__ __align__(16) char smem[];
    const uint32_t sm0 = smem_u32(smem);

    const int tid  = threadIdx.x;
    const int wid  = tid >> 5;
    const int lane = tid & 31;
    const int n0 = blockIdx.x * 128;
    const int m0 = blockIdx.y * 128;
    const int b  = blockIdx.z;

    const int wm = (wid >> 1) * 32;
    const int wn = (wid & 1) * 64;

    const __half* gA_h = Ah + (size_t)m0 * K;
    const __half* gA_l = Al + (size_t)m0 * K;
    const __half* gB_h = Bmh + (size_t)b * K * N + n0;
    const __half* gB_l = Bml + (size_t)b * K * N + n0;

    float acc[2][8][4];
#pragma unroll
    for (int t = 0; t < 2; t++)
#pragma unroll
        for (int nt = 0; nt < 8; nt++)
#pragma unroll
            for (int i = 0; i < 4; i++) acc[t][nt][i] = 0.f;

    const int nk = K / 32;

    stage_load(sm0, gA_h, gA_l, gB_h, gB_l, K, N, 0, tid);
    CP_COMMIT();
    if (nk > 1) {
        stage_load(sm0 + STG2, gA_h, gA_l, gB_h, gB_l, K, N, 1, tid);
        CP_COMMIT();
    }

    const int a_row = lane & 15;
    const int a_hi  = (lane >> 4) * 16;
    const int b_kr = (lane & 7) + ((lane >> 3) & 1) * 8;
    const int b_nc = (lane >> 4) * 8;

    for (int kc = 0; kc < nk; kc++) {
        if (kc + 1 < nk) CP_WAIT(1); else CP_WAIT(0);
        __syncthreads();

        const uint32_t sb  = sm0 + (kc & 1) * STG2;
        const uint32_t aAh = sb;
        const uint32_t aAl = sb + OFF_AL;
        const uint32_t aBh = sb + OFF_BH;
        const uint32_t aBl = sb + OFF_BL;

#pragma unroll
        for (int j = 0; j < 2; j++) {
            uint32_t ah[2][4], al[2][4];
#pragma unroll
            for (int t = 0; t < 2; t++) {
                uint32_t off = (uint32_t)(wm + t * 16 + a_row) * A_PITCH + j * 32 + a_hi;
                ldsm4(aAh + off, ah[t]);
                ldsm4(aAl + off, al[t]);
            }
            uint32_t bh[4][4], bl[4][4];
#pragma unroll
            for (int p = 0; p < 4; p++) {
                uint32_t off = (uint32_t)(j * 16 + b_kr) * B_PITCH +
                               (uint32_t)(wn + p * 16 + b_nc) * 2;
                ldsm4t(aBh + off, bh[p]);
                ldsm4t(aBl + off, bl[p]);
            }
#pragma unroll
            for (int t = 0; t < 2; t++)
#pragma unroll
                for (int nt = 0; nt < 8; nt++) {
                    const uint32_t* bhp = &bh[nt >> 1][(nt & 1) * 2];
                    const uint32_t* blp = &bl[nt >> 1][(nt & 1) * 2];
                    mma_f16(acc[t][nt], ah[t], bhp);
                    mma_f16(acc[t][nt], ah[t], blp);
                    mma_f16(acc[t][nt], al[t], bhp);
                }
        }
        __syncthreads();
        if (kc + 2 < nk) {
            stage_load(sm0 + (kc & 1) * STG2, gA_h, gA_l, gB_h, gB_l,
                       K, N, kc + 2, tid);
            CP_COMMIT();
        }
    }

    const int l4 = lane >> 2;
    const int l2 = (lane & 3) * 2;
#pragma unroll
    for (int t = 0; t < 2; t++) {
        const int m_lo = m0 + wm + t * 16 + l4;
        const float bi_lo = bias[m_lo];
        const float bi_hi = bias[m_lo + 8];
        float* c_lo = C + ((size_t)b * M + m_lo) * N + n0 + wn + l2;
        float* c_hi = c_lo + (size_t)8 * N;
#pragma unroll
        for (int nt = 0; nt < 8; nt++) {
            float2 v0 = {acc[t][nt][0] + bi_lo, acc[t][nt][1] + bi_lo};
            float2 v1 = {acc[t][nt][2] + bi_hi, acc[t][nt][3] + bi_hi};
            *(float2*)(c_lo + nt * 8) = v0;
            *(float2*)(c_hi + nt * 8) = v1;
        }
    }
}

// ---------------------------------------------------------------------------
__global__ void wsplit_kernel(const float* __restrict__ w,
                              __half* __restrict__ hi,
                              __half* __restrict__ lo, int n)
{
    int i = blockIdx.x * 256 + threadIdx.x;
    if (i < n) {
        float v = w[i];
        __half h = __float2half_rn(v);
        hi[i] = h;
        lo[i] = __float2half_rn(v - __half2float(h));
    }
}

__global__ void zero_vk_kernel(float* __restrict__ vk)
{
    int i = blockIdx.x * 256 + threadIdx.x;
    if (i < BATCH * 96 * 72) vk[i] = 0.f;
}

// ---------------------------------------------------------------------------
// dwpw v4: phase A remapped to (channel x 8-px row segment) threads.
// 256 threads = 8 ch x (4 rows x 8 x-octets); 3 channel-group iterations.
// ---------------------------------------------------------------------------
#define OFF_SIN   0                    // float[8][8][68]       17408
#define OFF_D3    17408                // float[24][256] / kvq overlay
#define OFF_D5    41984                // float[24][256]
#define OFF_W5P   66560                // ull[24][25]            4800
#define OFF_W3P   71360                // ull[24][9]             1728
#define OFF_PWP   73088                // ull[2][24][24] / red   9216
#define OFF_PWB   82304                // ull[2][24]              384
#define OFF_DB5   82688                // ull[24]                 192
#define OFF_DB3   82880                // ull[24]                 192
#define DW_SMEM   83072

__global__ __launch_bounds__(256, 2)
void dwpw_kernel(const float* __restrict__ qkv,
                 const float* __restrict__ dw3_w, const float* __restrict__ dw3_b,
                 const float* __restrict__ pw3_w, const float* __restrict__ pw3_b,
                 const float* __restrict__ dw5_w, const float* __restrict__ dw5_b,
                 const float* __restrict__ pw5_w, const float* __restrict__ pw5_b,
                 float* __restrict__ s3q, float* __restrict__ s5q,
                 float* __restrict__ vkg)
{
    extern __shared__ __align__(16) char sm[];
    float* sin_ = (float*)(sm + OFF_SIN);
    float* d3s  = (float*)(sm + OFF_D3);
    float* d5s  = (float*)(sm + OFF_D5);
    ull*   kvq  = (ull*)(sm + OFF_D3);       // overlay (phase B/C)
    float* red  = (float*)(sm + OFF_PWP);    // overlay (phase C) [2][16][72]
    ull*   w5p  = (ull*)(sm + OFF_W5P);
    ull*   w3p  = (ull*)(sm + OFF_W3P);
    ull*   pwp  = (ull*)(sm + OFF_PWP);
    ull*   pwb  = (ull*)(sm + OFF_PWB);
    ull*   db5  = (ull*)(sm + OFF_DB5);
    ull*   db3  = (ull*)(sm + OFF_DB3);

    const int ytile = blockIdx.x;
    const int g     = blockIdx.y;
    const int b     = blockIdx.z;
    const int tid   = threadIdx.x;
    const int y0    = ytile * 4;

    for (int i = tid; i < 600; i += 256) {
        float w = dw5_w[(g * 24 + i / 25) * 25 + i % 25];
        w5p[i] = pk2(w, w);
    }
    for (int i = tid; i < 216; i += 256) {
        float w = dw3_w[(g * 24 + i / 9) * 9 + i % 9];
        w3p[i] = pk2(w, w);
    }
    for (int i = tid; i < 576; i += 256) {
        float a = pw3_w[g * 576 + i];
        float c = pw5_w[g * 576 + i];
        pwp[i] = pk2(a, a);
        pwp[576 + i] = pk2(c, c);
    }
    if (tid < 24) {
        float b3 = pw3_b[g * 24 + tid], b5 = pw5_b[g * 24 + tid];
        pwb[tid] = pk2(b3, b3);
        pwb[24 + tid] = pk2(b5, b5);
        float d3b = dw3_b[g * 24 + tid], d5b = dw5_b[g * 24 + tid];
        db3[tid] = pk2(d3b, d3b);
        db5[tid] = pk2(d5b, d5b);
    }

    // ---- phase A: depthwise, thread = 1 ch x 8 px ----
    const int c  = tid >> 5;              // channel within group (0..7)
    const int t  = tid & 31;
    const int py = t >> 3;                // output row 0..3
    const int xo = (t & 7) * 8;           // x-octet start (even)

    for (int grp = 0; grp < 3; grp++) {
        __syncthreads();                  // tables ready / prev sin_ consumed
        const int icb = grp * 8;
        const float* src = qkv + ((size_t)b * C3 + g * 24 + icb) * NPIX;
        for (int i = tid; i < 8 * 8 * 68; i += 256) {
            int xx = i % 68;
            int r  = (i / 68) & 7;
            int cc = i / (68 * 8);
            int yy = y0 - 2 + r;
            int xg = xx - 2;
            float v = 0.f;
            if ((unsigned)yy < 64u && (unsigned)xg < 64u)
                v = src[(size_t)cc * NPIX + yy * WIDTH + xg];
            sin_[(cc * 8 + r) * 68 + xx] = v;
        }
        __syncthreads();

        const int ch = icb + c;           // 0..23
        ull acc5[4], acc3[4];
        {
            ull b5v = db5[ch], b3v = db3[ch];
#pragma unroll
            for (int j = 0; j < 4; j++) { acc5[j] = b5v; acc3[j] = b3v; }
        }
#pragma unroll
        for (int dy = 0; dy < 5; dy++) {
            const ull* row = (const ull*)&sin_[(c * 8 + py + dy) * 68 + xo];
            ull r0 = row[0], r1 = row[1], r2 = row[2],
                r3 = row[3], r4 = row[4], r5 = row[5];
            ull m0 = pk2(f2hi(r0), f2lo(r1));
            ull m1 = pk2(f2hi(r1), f2lo(r2));
            ull m2 = pk2(f2hi(r2), f2lo(r3));
            ull m3 = pk2(f2hi(r3), f2lo(r4));
            ull m4 = pk2(f2hi(r4), f2lo(r5));
            const ull* w5r = &w5p[ch * 25 + dy * 5];
            ull w0 = w5r[0], w1 = w5r[1], w2 = w5r[2], w3v = w5r[3], w4 = w5r[4];

            ffma2(acc5[0], w0, r0); ffma2(acc5[0], w1, m0); ffma2(acc5[0], w2, r1);
            ffma2(acc5[0], w3v, m1); ffma2(acc5[0], w4, r2);
            ffma2(acc5[1], w0, r1); ffma2(acc5[1], w1, m1); ffma2(acc5[1], w2, r2);
            ffma2(acc5[1], w3v, m2); ffma2(acc5[1], w4, r3);
            ffma2(acc5[2], w0, r2); ffma2(acc5[2], w1, m2); ffma2(acc5[2], w2, r3);
            ffma2(acc5[2], w3v, m3); ffma2(acc5[2], w4, r4);
            ffma2(acc5[3], w0, r3); ffma2(acc5[3], w1, m3); ffma2(acc5[3], w2, r4);
            ffma2(acc5[3], w3v, m4); ffma2(acc5[3], w4, r5);

            if (dy >= 1 && dy <= 3) {
                const ull* w3r = &w3p[ch * 9 + (dy - 1) * 3];
                ull u0 = w3r[0], u1 = w3r[1], u2 = w3r[2];
                ffma2(acc3[0], u0, m0); ffma2(acc3[0], u1, r1); ffma2(acc3[0], u2, m1);
                ffma2(acc3[1], u0, m1); ffma2(acc3[1], u1, r2); ffma2(acc3[1], u2, m2);
                ffma2(acc3[2], u0, m2); ffma2(acc3[2], u1, r3); ffma2(acc3[2], u2, m3);
                ffma2(acc3[3], u0, m3); ffma2(acc3[3], u1, r4); ffma2(acc3[3], u2, m4);
            }
        }
        const int ppb = py * 32 + (xo >> 1);
#pragma unroll
        for (int j = 0; j < 4; j++) {
            *(ull*)&d3s[ch * 256 + (ppb + j) * 2] = acc3[j];
            *(ull*)&d5s[ch * 256 + (ppb + j) * 2] = acc5[j];
        }
    }
    __syncthreads();

    // ---- phase B: grouped pointwise ----
    const int conv = tid >> 7;
    const int bp   = tid & 127;
    const float* dsrc = conv ? d5s : d3s;
    const ull* wp = &pwp[conv * 576];
    const ull* bb = &pwb[conv * 24];
    float* qout = conv ? s5q : s3q;

    ull d2[24];
#pragma unroll
    for (int ic = 0; ic < 24; ic++)
        d2[ic] = *(const ull*)&dsrc[ic * 256 + bp * 2];
    __syncthreads();   // d3s/d5s fully consumed; kvq overlay may be written

    const int by = y0 + (bp >> 5);
    const int bx = (bp & 31) * 2;
    const size_t qbase = (((size_t)b * 32 + g) * 8) * NPIX + by * WIDTH + bx;

#pragma unroll
    for (int o = 0; o < 24; o++) {
        ull acc = bb[o];
        const ull* wrow = &wp[o * 24];
#pragma unroll
        for (int ic = 0; ic < 24; ic++)
            ffma2(acc, wrow[ic], d2[ic]);
        if (o < 8) {
            *(float2*)&qout[qbase + (size_t)o * NPIX] =
                make_float2(f2lo(acc), f2hi(acc));
        } else {
            kvq[(conv * 16 + (o - 8)) * 128 + bp] = acc;
        }
    }
    __syncthreads();

    // ---- phase C: vk outer product + reduce + atomicAdd ----
    {
        const int w    = tid >> 5;
        const int lane = tid & 31;
        const int cv   = w >> 2;
        const int sub  = w & 3;
        const int pair = sub * 32 + lane;

        ull kvv[16];
#pragma unroll
        for (int ch = 0; ch < 16; ch++)
            kvv[ch] = kvq[(cv * 16 + ch) * 128 + pair];

        float acc[9][8];
#pragma unroll
        for (int d = 0; d < 9; d++)
#pragma unroll
            for (int e = 0; e < 8; e++) acc[d][e] = 0.f;

#pragma unroll
        for (int hx = 0; hx < 2; hx++) {
            float kk[8], vv[8];
#pragma unroll
            for (int e = 0; e < 8; e++)
                kk[e] = fmaxf(hx ? f2hi(kvv[e]) : f2lo(kvv[e]), 0.f);
#pragma unroll
            for (int d = 0; d < 8; d++)
                vv[d] = hx ? f2hi(kvv[8 + d]) : f2lo(kvv[8 + d]);
#pragma unroll
            for (int d = 0; d < 8; d++)
#pragma unroll
                for (int e = 0; e < 8; e++)
                    acc[d][e] += vv[d] * kk[e];
#pragma unroll
            for (int e = 0; e < 8; e++)
                acc[8][e] += kk[e];
        }

#pragma unroll
        for (int d = 0; d < 9; d++)
#pragma unroll
            for (int e = 0; e < 8; e++) {
                float v = acc[d][e];
                v += __shfl_xor_sync(0xffffffffu, v, 16);
                v += __shfl_xor_sync(0xffffffffu, v, 8);
                v += __shfl_xor_sync(0xffffffffu, v, 4);
                acc[d][e] = v;
            }
        if (lane < 4) {
            float* rp = &red[((cv * 16) + sub * 4 + lane) * 72];
#pragma unroll
            for (int d = 0; d < 9; d++)
#pragma unroll
                for (int e = 0; e < 8; e++)
                    rp[d * 8 + e] = acc[d][e];
        }
    }
    __syncthreads();

    if (tid < 144) {
        const int cv  = tid / 72;
        const int idx = tid % 72;
        float s = 0.f;
#pragma unroll
        for (int j = 0; j < 16; j++)
            s += red[(cv * 16 + j) * 72 + idx];
        atomicAdd(&vkg[((size_t)b * 96 + 32 + cv * 32 + g) * 72 + idx], s);
    }
}

// ---------------------------------------------------------------------------
// vk reduction for qkv source heads (0..31)
// ---------------------------------------------------------------------------
__global__ __launch_bounds__(256)
void vk_kernel(const float* __restrict__ qkv, float* __restrict__ vk)
{
    const int g = blockIdx.x;
    const int b = blockIdx.y;
    const float* base = qkv + ((size_t)b * C3 + g * 24) * NPIX;

    float acc[9][8];
#pragma unroll
    for (int d = 0; d < 9; d++)
#pragma unroll
        for (int e = 0; e < 8; e++) acc[d][e] = 0.f;

    const int tid = threadIdx.x;
    for (int n = tid; n < NPIX; n += 256) {
        float kv[8], vv[8];
#pragma unroll
        for (int e = 0; e < 8; e++)
            kv[e] = fmaxf(base[(size_t)(8 + e) * NPIX + n], 0.f);
#pragma unroll
        for (int d = 0; d < 8; d++)
            vv[d] = base[(size_t)(16 + d) * NPIX + n];
#pragma unroll
        for (int d = 0; d < 8; d++)
#pragma unroll
            for (int e = 0; e < 8; e++)
                acc[d][e] += vv[d] * kv[e];
#pragma unroll
        for (int e = 0; e < 8; e++)
            acc[8][e] += kv[e];
    }

#pragma unroll
    for (int d = 0; d < 9; d++)
#pragma unroll
        for (int e = 0; e < 8; e++) {
            float v = acc[d][e];
            v += __shfl_xor_sync(0xffffffffu, v, 16);
            v += __shfl_xor_sync(0xffffffffu, v, 8);
            v += __shfl_xor_sync(0xffffffffu, v, 4);
            v += __shfl_xor_sync(0xffffffffu, v, 2);
            v += __shfl_xor_sync(0xffffffffu, v, 1);
            acc[d][e] = v;
        }

    __shared__ float red[8][72];
    const int wid  = tid >> 5;
    const int lane = tid & 31;
    if (lane == 0) {
#pragma unroll
        for (int d = 0; d < 9; d++)
#pragma unroll
            for (int e = 0; e < 8; e++)
                red[wid][d * 8 + e] = acc[d][e];
    }
    __syncthreads();
    if (tid < 72) {
        float s = 0.f;
#pragma unroll
        for (int w = 0; w < 8; w++) s += red[w][tid];
        vk[((size_t)b * 96 + g) * 72 + tid] = s;
    }
}

// ---------------------------------------------------------------------------
// attention normalize -> channel-major fp16 split (coalesced)
// ---------------------------------------------------------------------------
__global__ __launch_bounds__(256)
void att_kernel(const float* __restrict__ qkv, const float* __restrict__ s3q,
                const float* __restrict__ s5q, const float* __restrict__ vk,
                __half* __restrict__ atth, __half* __restrict__ attl)
{
    const int hh = blockIdx.x;
    const int b  = blockIdx.y;
    const int src_id = hh >> 5;
    const int g      = hh & 31;
    const float* base;
    if (src_id == 0)      base = qkv + ((size_t)b * C3 + g * 24) * NPIX;
    else if (src_id == 1) base = s3q + (((size_t)b * 32 + g) * 8) * NPIX;
    else                  base = s5q + (((size_t)b * 32 + g) * 8) * NPIX;

    __shared__ float vs[72];
    const int tid = threadIdx.x;
    if (tid < 72) vs[tid] = vk[((size_t)b * 96 + hh) * 72 + tid];
    __syncthreads();

    __half* oh = atth + ((size_t)b * C3 + hh * 8) * NPIX;
    __half* ol = attl + ((size_t)b * C3 + hh * 8) * NPIX;

    for (int n2 = tid; n2 < NPIX / 2; n2 += 256) {
        const int n = n2 * 2;
        float q0[8], q1[8];
#pragma unroll
        for (int e = 0; e < 8; e++) {
            float2 qq = *(const float2*)(base + (size_t)e * NPIX + n);
            q0[e] = fmaxf(qq.x, 0.f);
            q1[e] = fmaxf(qq.y, 0.f);
        }
        float den0 = 1e-15f, den1 = 1e-15f;
#pragma unroll
        for (int e = 0; e < 8; e++) {
            den0 += vs[64 + e] * q0[e];
            den1 += vs[64 + e] * q1[e];
        }
        float rd0 = __fdividef(1.f, den0);
        float rd1 = __fdividef(1.f, den1);
#pragma unroll
        for (int d = 0; d < 8; d++) {
            float num0 = 0.f, num1 = 0.f;
#pragma unroll
            for (int e = 0; e < 8; e++) {
                num0 += vs[d * 8 + e] * q0[e];
                num1 += vs[d * 8 + e] * q1[e];
            }
            float v0 = num0 * rd0, v1 = num1 * rd1;
            __half h0 = __float2half_rn(v0), h1 = __float2half_rn(v1);
            __half l0 = __float2half_rn(v0 - __half2float(h0));
            __half l1 = __float2half_rn(v1 - __half2float(h1));
            __half2 hp; hp.x = h0; hp.y = h1;
            __half2 lp; lp.x = l0; lp.y = l1;
            *(__half2*)(oh + (size_t)d * NPIX + n) = hp;
            *(__half2*)(ol + (size_t)d * NPIX + n) = lp;
        }
    }
}

// ---------------------------------------------------------------------------
extern "C" void kernel_launch(void* const* d_in, const int* in_sizes, int n_in,
                              void* d_out, int out_size)
{
    const float* x      = (const float*)d_in[0];
    const float* qkv_w  = (const float*)d_in[1];
    const float* qkv_b  = (const float*)d_in[2];
    const float* dw3_w  = (const float*)d_in[3];
    const float* dw3_b  = (const float*)d_in[4];
    const float* pw3_w  = (const float*)d_in[5];
    const float* pw3_b  = (const float*)d_in[6];
    const float* dw5_w  = (const float*)d_in[7];
    const float* dw5_b  = (const float*)d_in[8];
    const float* pw5_w  = (const float*)d_in[9];
    const float* pw5_b  = (const float*)d_in[10];
    const float* proj_w = (const float*)d_in[11];
    const float* proj_b = (const float*)d_in[12];
    float* out = (float*)d_out;

    void *p;
    cudaGetSymbolAddress(&p, g_qkv);  float* qkv = (float*)p;
    cudaGetSymbolAddress(&p, g_s3q);  float* s3q = (float*)p;
    cudaGetSymbolAddress(&p, g_s5q);  float* s5q = (float*)p;
    cudaGetSymbolAddress(&p, g_vk);   float* vkb = (float*)p;
    cudaGetSymbolAddress(&p, g_xt_h); __half* xth = (__half*)p;
    cudaGetSymbolAddress(&p, g_xt_l); __half* xtl = (__half*)p;
    cudaGetSymbolAddress(&p, g_at_h); __half* ath = (__half*)p;
    cudaGetSymbolAddress(&p, g_at_l); __half* atl = (__half*)p;
    cudaGetSymbolAddress(&p, g_wq_h); __half* wqh = (__half*)p;
    cudaGetSymbolAddress(&p, g_wq_l); __half* wql = (__half*)p;
    cudaGetSymbolAddress(&p, g_wp_h); __half* wph = (__half*)p;
    cudaGetSymbolAddress(&p, g_wp_l); __half* wpl = (__half*)p;

    cudaFuncSetAttribute(gemm_f16, cudaFuncAttributeMaxDynamicSharedMemorySize,
                         2 * STG2);
    cudaFuncSetAttribute(dwpw_kernel,
                         cudaFuncAttributeMaxDynamicSharedMemorySize, DW_SMEM);
    const int GSM = 2 * STG2;

    // 0) splits (weights + x)
    wsplit_kernel<<<(C3 * 256 + 255) / 256, 256>>>(qkv_w, wqh, wql, C3 * 256);
    wsplit_kernel<<<(256 * C3 + 255) / 256, 256>>>(proj_w, wph, wpl, 256 * C3);
    wsplit_kernel<<<(BATCH * 256 * NPIX + 255) / 256, 256>>>(
        x, xth, xtl, BATCH * 256 * NPIX);

    // 1) qkv = Wq(768,256) @ x[b](256,4096) + b
    gemm_f16<<<dim3(NPIX / 128, C3 / 128, BATCH), 256, GSM>>>(
        wqh, wql, xth, xtl, qkv_b, qkv, C3, NPIX, 256);

    // 2) zero vk accumulators, then fused dwpw (+ s3/s5 vk via atomics)
    zero_vk_kernel<<<(BATCH * 96 * 72 + 255) / 256, 256>>>(vkb);
    dwpw_kernel<<<dim3(16, 32, BATCH), 256, DW_SMEM>>>(
        qkv, dw3_w, dw3_b, pw3_w, pw3_b, dw5_w, dw5_b, pw5_w, pw5_b,
        s3q, s5q, vkb);

    // 3) vk for qkv-source heads
    vk_kernel<<<dim3(32, BATCH), 256>>>(qkv, vkb);

    // 4) attention normalize -> channel-major fp16 splits
    att_kernel<<<dim3(96, BATCH), 256>>>(qkv, s3q, s5q, vkb, ath, atl);

    // 5) out = Wp(256,768) @ att[b](768,4096) + b
    gemm_f16<<<dim3(NPIX / 128, 256 / 128, BATCH), 256, GSM>>>(
        wph, wpl, ath, atl, proj_b, out, 256, NPIX, C3);
}

// round 7
// speedup vs baseline: 1.9376x; 1.0429x over previous
#include <cuda_runtime.h>
#include <cuda_fp16.h>
#include <cstdint>

// ---------------------------------------------------------------------------
// LiteMLA on sm_103a.
// qkv GEMM: fp16 hi/lo split x hi/lo (3 mma products, amplified error path).
// proj GEMM: weights hi/lo x att hi-only (2 products, unamplified path),
//            3-stage cp.async pipeline.
// dwpw: depthwise f32x2 -> grouped pointwise FFMA2 -> fused vk (s3/s5 heads
//       AND qkv heads — vk_kernel eliminated).
// ---------------------------------------------------------------------------

#define BATCH 8
#define C3 768
#define NPIX 4096
#define WIDTH 64

__device__ float g_qkv[(size_t)BATCH * C3 * NPIX];
__device__ float g_s3q[(size_t)BATCH * 32 * 8 * NPIX];   // q channels only
__device__ float g_s5q[(size_t)BATCH * 32 * 8 * NPIX];
__device__ float g_vk [(size_t)BATCH * 96 * 72];

__device__ __half g_xt_h [(size_t)BATCH * 256 * NPIX];   // x split [b][k][n]
__device__ __half g_xt_l [(size_t)BATCH * 256 * NPIX];
__device__ __half g_at_h [(size_t)BATCH * C3 * NPIX];    // att fp16 [b][k][n]
__device__ __half g_wq_h [C3 * 256];
__device__ __half g_wq_l [C3 * 256];
__device__ __half g_wp_h [256 * C3];
__device__ __half g_wp_l [256 * C3];

// ---------------------------------------------------------------------------
typedef unsigned long long ull;

__device__ __forceinline__ uint32_t smem_u32(const void* p) {
    uint32_t a;
    asm("{ .reg .u64 t; cvta.to.shared.u64 t, %1; cvt.u32.u64 %0, t; }"
        : "=r"(a) : "l"(p));
    return a;
}
__device__ __forceinline__ ull pk2(float lo, float hi) {
    ull r;
    asm("mov.b64 %0, {%1, %2};" : "=l"(r)
        : "r"(__float_as_uint(lo)), "r"(__float_as_uint(hi)));
    return r;
}
__device__ __forceinline__ void ffma2(ull& d, ull a, ull b) {
    asm("fma.rn.f32x2 %0, %1, %2, %0;" : "+l"(d) : "l"(a), "l"(b));
}
__device__ __forceinline__ float f2lo(ull v) {
    return __uint_as_float((unsigned)(v & 0xffffffffull));
}
__device__ __forceinline__ float f2hi(ull v) {
    return __uint_as_float((unsigned)(v >> 32));
}

#define CP_ASYNC16(s, g) \
    asm volatile("cp.async.cg.shared.global [%0], [%1], 16;" :: "r"(s), "l"(g))
#define CP_COMMIT() asm volatile("cp.async.commit_group;" ::: "memory")
#define CP_WAIT(n)  asm volatile("cp.async.wait_group %0;" :: "n"(n) : "memory")

__device__ __forceinline__ void ldsm4(uint32_t addr, uint32_t* r) {
    asm volatile("ldmatrix.sync.aligned.m8n8.x4.shared.b16 {%0,%1,%2,%3}, [%4];"
                 : "=r"(r[0]), "=r"(r[1]), "=r"(r[2]), "=r"(r[3]) : "r"(addr));
}
__device__ __forceinline__ void ldsm4t(uint32_t addr, uint32_t* r) {
    asm volatile("ldmatrix.sync.aligned.m8n8.x4.trans.shared.b16 {%0,%1,%2,%3}, [%4];"
                 : "=r"(r[0]), "=r"(r[1]), "=r"(r[2]), "=r"(r[3]) : "r"(addr));
}
__device__ __forceinline__ void mma_f16(float* d, const uint32_t* a,
                                        const uint32_t* b) {
    asm volatile(
        "mma.sync.aligned.m16n8k16.row.col.f32.f16.f16.f32 "
        "{%0,%1,%2,%3}, {%4,%5,%6,%7}, {%8,%9}, {%0,%1,%2,%3};"
        : "+f"(d[0]), "+f"(d[1]), "+f"(d[2]), "+f"(d[3])
        : "r"(a[0]), "r"(a[1]), "r"(a[2]), "r"(a[3]), "r"(b[0]), "r"(b[1]));
}

#define A_PITCH 80
#define B_PITCH 272

// ---------------------------------------------------------------------------
// 3-product GEMM (qkv): C[b] = (Ah+Al)(M,K) @ (Bh+Bl)(b,K,N) + bias
// 2-stage, 2 CTAs/SM.  (unchanged from R5/R6)
// ---------------------------------------------------------------------------
#define OFF_AL  10240
#define OFF_BH  20480
#define OFF_BL  29184
#define STG2    37888

__device__ __forceinline__ void stage_load(
    uint32_t sbase, const __half* gA_h, const __half* gA_l,
    const __half* gB_h, const __half* gB_l, int K, int N, int kc, int tid)
{
    const int op = tid >> 6;
    const int t  = tid & 63;
    if (op < 2) {
        const __half* g = ((op == 0) ? gA_h : gA_l) + kc * 32;
        const uint32_t sb = sbase + op * OFF_AL;
#pragma unroll
        for (int it = 0; it < 8; it++) {
            int chunk = t + it * 64;
            int row = chunk >> 2, c = chunk & 3;
            CP_ASYNC16(sb + row * A_PITCH + c * 16, g + (size_t)row * K + c * 8);
        }
    } else {
        const __half* g = ((op == 2) ? gB_h : gB_l) + (size_t)kc * 32 * N;
        const uint32_t sb = sbase + ((op == 2) ? OFF_BH : OFF_BL);
#pragma unroll
        for (int it = 0; it < 8; it++) {
            int chunk = t + it * 64;
            int row = chunk >> 4, c = chunk & 15;
            CP_ASYNC16(sb + row * B_PITCH + c * 16, g + (size_t)row * N + c * 8);
        }
    }
}

__global__ __launch_bounds__(256, 2)
void gemm_f16(const __half* __restrict__ Ah, const __half* __restrict__ Al,
              const __half* __restrict__ Bmh, const __half* __restrict__ Bml,
              const float* __restrict__ bias, float* __restrict__ C,
              int M, int N, int K)
{
    extern __shared__ __align__(16) char smem[];
    const uint32_t sm0 = smem_u32(smem);

    const int tid  = threadIdx.x;
    const int wid  = tid >> 5;
    const int lane = tid & 31;
    const int n0 = blockIdx.x * 128;
    const int m0 = blockIdx.y * 128;
    const int b  = blockIdx.z;

    const int wm = (wid >> 1) * 32;
    const int wn = (wid & 1) * 64;

    const __half* gA_h = Ah + (size_t)m0 * K;
    const __half* gA_l = Al + (size_t)m0 * K;
    const __half* gB_h = Bmh + (size_t)b * K * N + n0;
    const __half* gB_l = Bml + (size_t)b * K * N + n0;

    float acc[2][8][4];
#pragma unroll
    for (int t = 0; t < 2; t++)
#pragma unroll
        for (int nt = 0; nt < 8; nt++)
#pragma unroll
            for (int i = 0; i < 4; i++) acc[t][nt][i] = 0.f;

    const int nk = K / 32;

    stage_load(sm0, gA_h, gA_l, gB_h, gB_l, K, N, 0, tid);
    CP_COMMIT();
    if (nk > 1) {
        stage_load(sm0 + STG2, gA_h, gA_l, gB_h, gB_l, K, N, 1, tid);
        CP_COMMIT();
    }

    const int a_row = lane & 15;
    const int a_hi  = (lane >> 4) * 16;
    const int b_kr = (lane & 7) + ((lane >> 3) & 1) * 8;
    const int b_nc = (lane >> 4) * 8;

    for (int kc = 0; kc < nk; kc++) {
        if (kc + 1 < nk) CP_WAIT(1); else CP_WAIT(0);
        __syncthreads();

        const uint32_t sb  = sm0 + (kc & 1) * STG2;
        const uint32_t aAh = sb;
        const uint32_t aAl = sb + OFF_AL;
        const uint32_t aBh = sb + OFF_BH;
        const uint32_t aBl = sb + OFF_BL;

#pragma unroll
        for (int j = 0; j < 2; j++) {
            uint32_t ah[2][4], al[2][4];
#pragma unroll
            for (int t = 0; t < 2; t++) {
                uint32_t off = (uint32_t)(wm + t * 16 + a_row) * A_PITCH + j * 32 + a_hi;
                ldsm4(aAh + off, ah[t]);
                ldsm4(aAl + off, al[t]);
            }
            uint32_t bh[4][4], bl[4][4];
#pragma unroll
            for (int p = 0; p < 4; p++) {
                uint32_t off = (uint32_t)(j * 16 + b_kr) * B_PITCH +
                               (uint32_t)(wn + p * 16 + b_nc) * 2;
                ldsm4t(aBh + off, bh[p]);
                ldsm4t(aBl + off, bl[p]);
            }
#pragma unroll
            for (int t = 0; t < 2; t++)
#pragma unroll
                for (int nt = 0; nt < 8; nt++) {
                    const uint32_t* bhp = &bh[nt >> 1][(nt & 1) * 2];
                    const uint32_t* blp = &bl[nt >> 1][(nt & 1) * 2];
                    mma_f16(acc[t][nt], ah[t], bhp);
                    mma_f16(acc[t][nt], ah[t], blp);
                    mma_f16(acc[t][nt], al[t], bhp);
                }
        }
        __syncthreads();
        if (kc + 2 < nk) {
            stage_load(sm0 + (kc & 1) * STG2, gA_h, gA_l, gB_h, gB_l,
                       K, N, kc + 2, tid);
            CP_COMMIT();
        }
    }

    const int l4 = lane >> 2;
    const int l2 = (lane & 3) * 2;
#pragma unroll
    for (int t = 0; t < 2; t++) {
        const int m_lo = m0 + wm + t * 16 + l4;
        const float bi_lo = bias[m_lo];
        const float bi_hi = bias[m_lo + 8];
        float* c_lo = C + ((size_t)b * M + m_lo) * N + n0 + wn + l2;
        float* c_hi = c_lo + (size_t)8 * N;
#pragma unroll
        for (int nt = 0; nt < 8; nt++) {
            float2 v0 = {acc[t][nt][0] + bi_lo, acc[t][nt][1] + bi_lo};
            float2 v1 = {acc[t][nt][2] + bi_hi, acc[t][nt][3] + bi_hi};
            *(float2*)(c_lo + nt * 8) = v0;
            *(float2*)(c_hi + nt * 8) = v1;
        }
    }
}

// ---------------------------------------------------------------------------
// 2-product GEMM (proj): C[b] = (Ah+Al)(M,K) @ Bh(b,K,N) + bias
// 3-stage cp.async ring (29184 B/stage), 2 CTAs/SM.
// ---------------------------------------------------------------------------
#define P2_AL   10240
#define P2_BH   20480
#define P2_STG  29184

__device__ __forceinline__ void stage_load_2p(
    uint32_t sbase, const __half* gA_h, const __half* gA_l,
    const __half* gB_h, int K, int N, int kc, int tid)
{
    if (tid < 128) {
        const int op = tid >> 6;
        const int t  = tid & 63;
        const __half* g = ((op == 0) ? gA_h : gA_l) + kc * 32;
        const uint32_t sb = sbase + op * P2_AL;
#pragma unroll
        for (int it = 0; it < 8; it++) {
            int chunk = t + it * 64;
            int row = chunk >> 2, c = chunk & 3;
            CP_ASYNC16(sb + row * A_PITCH + c * 16, g + (size_t)row * K + c * 8);
        }
    } else {
        const int t = tid - 128;
        const __half* g = gB_h + (size_t)kc * 32 * N;
        const uint32_t sb = sbase + P2_BH;
#pragma unroll
        for (int it = 0; it < 4; it++) {
            int chunk = t + it * 128;
            int row = chunk >> 4, c = chunk & 15;
            CP_ASYNC16(sb + row * B_PITCH + c * 16, g + (size_t)row * N + c * 8);
        }
    }
}

__global__ __launch_bounds__(256, 2)
void gemm_f16_2p(const __half* __restrict__ Ah, const __half* __restrict__ Al,
                 const __half* __restrict__ Bmh,
                 const float* __restrict__ bias, float* __restrict__ C,
                 int M, int N, int K)
{
    extern __shared__ __align__(16) char smem[];
    const uint32_t sm0 = smem_u32(smem);

    const int tid  = threadIdx.x;
    const int wid  = tid >> 5;
    const int lane = tid & 31;
    const int n0 = blockIdx.x * 128;
    const int m0 = blockIdx.y * 128;
    const int b  = blockIdx.z;

    const int wm = (wid >> 1) * 32;
    const int wn = (wid & 1) * 64;

    const __half* gA_h = Ah + (size_t)m0 * K;
    const __half* gA_l = Al + (size_t)m0 * K;
    const __half* gB_h = Bmh + (size_t)b * K * N + n0;

    float acc[2][8][4];
#pragma unroll
    for (int t = 0; t < 2; t++)
#pragma unroll
        for (int nt = 0; nt < 8; nt++)
#pragma unroll
            for (int i = 0; i < 4; i++) acc[t][nt][i] = 0.f;

    const int nk = K / 32;

    stage_load_2p(sm0, gA_h, gA_l, gB_h, K, N, 0, tid);
    CP_COMMIT();
    if (nk > 1) {
        stage_load_2p(sm0 + P2_STG, gA_h, gA_l, gB_h, K, N, 1, tid);
        CP_COMMIT();
    }

    const int a_row = lane & 15;
    const int a_hi  = (lane >> 4) * 16;
    const int b_kr = (lane & 7) + ((lane >> 3) & 1) * 8;
    const int b_nc = (lane >> 4) * 8;

    for (int kc = 0; kc < nk; kc++) {
        if (kc + 2 < nk) {
            stage_load_2p(sm0 + ((kc + 2) % 3) * P2_STG,
                          gA_h, gA_l, gB_h, K, N, kc + 2, tid);
            CP_COMMIT();
        }
        if (kc + 2 < nk)      CP_WAIT(2);
        else if (kc + 1 < nk) CP_WAIT(1);
        else                  CP_WAIT(0);
        __syncthreads();

        const uint32_t sb  = sm0 + (kc % 3) * P2_STG;
        const uint32_t aAh = sb;
        const uint32_t aAl = sb + P2_AL;
        const uint32_t aBh = sb + P2_BH;

#pragma unroll
        for (int j = 0; j < 2; j++) {
            uint32_t ah[2][4], al[2][4];
#pragma unroll
            for (int t = 0; t < 2; t++) {
                uint32_t off = (uint32_t)(wm + t * 16 + a_row) * A_PITCH + j * 32 + a_hi;
                ldsm4(aAh + off, ah[t]);
                ldsm4(aAl + off, al[t]);
            }
            uint32_t bh[4][4];
#pragma unroll
            for (int p = 0; p < 4; p++) {
                uint32_t off = (uint32_t)(j * 16 + b_kr) * B_PITCH +
                               (uint32_t)(wn + p * 16 + b_nc) * 2;
                ldsm4t(aBh + off, bh[p]);
            }
#pragma unroll
            for (int t = 0; t < 2; t++)
#pragma unroll
                for (int nt = 0; nt < 8; nt++) {
                    const uint32_t* bhp = &bh[nt >> 1][(nt & 1) * 2];
                    mma_f16(acc[t][nt], ah[t], bhp);
                    mma_f16(acc[t][nt], al[t], bhp);
                }
        }
        __syncthreads();
    }

    const int l4 = lane >> 2;
    const int l2 = (lane & 3) * 2;
#pragma unroll
    for (int t = 0; t < 2; t++) {
        const int m_lo = m0 + wm + t * 16 + l4;
        const float bi_lo = bias[m_lo];
        const float bi_hi = bias[m_lo + 8];
        float* c_lo = C + ((size_t)b * M + m_lo) * N + n0 + wn + l2;
        float* c_hi = c_lo + (size_t)8 * N;
#pragma unroll
        for (int nt = 0; nt < 8; nt++) {
            float2 v0 = {acc[t][nt][0] + bi_lo, acc[t][nt][1] + bi_lo};
            float2 v1 = {acc[t][nt][2] + bi_hi, acc[t][nt][3] + bi_hi};
            *(float2*)(c_lo + nt * 8) = v0;
            *(float2*)(c_hi + nt * 8) = v1;
        }
    }
}

// ---------------------------------------------------------------------------
__global__ void wsplit_kernel(const float* __restrict__ w,
                              __half* __restrict__ hi,
                              __half* __restrict__ lo, int n)
{
    int i = blockIdx.x * 256 + threadIdx.x;
    if (i < n) {
        float v = w[i];
        __half h = __float2half_rn(v);
        hi[i] = h;
        lo[i] = __float2half_rn(v - __half2float(h));
    }
}

__global__ void zero_vk_kernel(float* __restrict__ vk)
{
    int i = blockIdx.x * 256 + threadIdx.x;
    if (i < BATCH * 96 * 72) vk[i] = 0.f;
}

// ---------------------------------------------------------------------------
// dwpw v5: phase A (channel x 8px threads) + stash of raw k channels,
// fused qkv-head vk (grp2), phase B pointwise, phase C s3/s5 vk.
// ---------------------------------------------------------------------------
#define OFF_SIN   0                    // float[8][8][68]       17408
#define OFF_D3    17408                // float[24][256] / kvq overlay
#define OFF_D5    41984                // float[24][256]
#define OFF_W5P   66560                // ull[24][25]            4800
#define OFF_W3P   71360                // ull[24][9]             1728
#define OFF_PWP   73088                // ull[2][24][24] / red   9216
#define OFF_PWB   82304                // ull[2][24]              384
#define OFF_DB5   82688                // ull[24]                 192
#define OFF_DB3   82880                // ull[24]                 192
#define OFF_STASH 83072                // float[8][256]          8192
#define DW_SMEM   91264

__global__ __launch_bounds__(256, 2)
void dwpw_kernel(const float* __restrict__ qkv,
                 const float* __restrict__ dw3_w, const float* __restrict__ dw3_b,
                 const float* __restrict__ pw3_w, const float* __restrict__ pw3_b,
                 const float* __restrict__ dw5_w, const float* __restrict__ dw5_b,
                 const float* __restrict__ pw5_w, const float* __restrict__ pw5_b,
                 float* __restrict__ s3q, float* __restrict__ s5q,
                 float* __restrict__ vkg)
{
    extern __shared__ __align__(16) char sm[];
    float* sin_  = (float*)(sm + OFF_SIN);
    float* d3s   = (float*)(sm + OFF_D3);
    float* d5s   = (float*)(sm + OFF_D5);
    ull*   kvq   = (ull*)(sm + OFF_D3);      // overlay (phase B/C)
    float* red   = (float*)(sm + OFF_PWP);   // overlay (phase C)
    float* stash = (float*)(sm + OFF_STASH); // raw k channels, center rows
    ull*   w5p   = (ull*)(sm + OFF_W5P);
    ull*   w3p   = (ull*)(sm + OFF_W3P);
    ull*   pwp   = (ull*)(sm + OFF_PWP);
    ull*   pwb   = (ull*)(sm + OFF_PWB);
    ull*   db5   = (ull*)(sm + OFF_DB5);
    ull*   db3   = (ull*)(sm + OFF_DB3);

    const int ytile = blockIdx.x;
    const int g     = blockIdx.y;
    const int b     = blockIdx.z;
    const int tid   = threadIdx.x;
    const int y0    = ytile * 4;

    for (int i = tid; i < 600; i += 256) {
        float w = dw5_w[(g * 24 + i / 25) * 25 + i % 25];
        w5p[i] = pk2(w, w);
    }
    for (int i = tid; i < 216; i += 256) {
        float w = dw3_w[(g * 24 + i / 9) * 9 + i % 9];
        w3p[i] = pk2(w, w);
    }
    for (int i = tid; i < 576; i += 256) {
        float a = pw3_w[g * 576 + i];
        float c = pw5_w[g * 576 + i];
        pwp[i] = pk2(a, a);
        pwp[576 + i] = pk2(c, c);
    }
    if (tid < 24) {
        float b3 = pw3_b[g * 24 + tid], b5 = pw5_b[g * 24 + tid];
        pwb[tid] = pk2(b3, b3);
        pwb[24 + tid] = pk2(b5, b5);
        float d3b = dw3_b[g * 24 + tid], d5b = dw5_b[g * 24 + tid];
        db3[tid] = pk2(d3b, d3b);
        db5[tid] = pk2(d5b, d5b);
    }

    // ---- phase A: depthwise, thread = 1 ch x 8 px ----
    const int c  = tid >> 5;
    const int t  = tid & 31;
    const int py = t >> 3;
    const int xo = (t & 7) * 8;

    for (int grp = 0; grp < 3; grp++) {
        __syncthreads();
        const int icb = grp * 8;
        const float* src = qkv + ((size_t)b * C3 + g * 24 + icb) * NPIX;
        for (int i = tid; i < 8 * 8 * 68; i += 256) {
            int xx = i % 68;
            int r  = (i / 68) & 7;
            int cc = i / (68 * 8);
            int yy = y0 - 2 + r;
            int xg = xx - 2;
            float v = 0.f;
            if ((unsigned)yy < 64u && (unsigned)xg < 64u)
                v = src[(size_t)cc * NPIX + yy * WIDTH + xg];
            sin_[(cc * 8 + r) * 68 + xx] = v;
        }
        __syncthreads();

        const int ch = icb + c;
        ull acc5[4], acc3[4];
        {
            ull b5v = db5[ch], b3v = db3[ch];
#pragma unroll
            for (int j = 0; j < 4; j++) { acc5[j] = b5v; acc3[j] = b3v; }
        }
#pragma unroll
        for (int dy = 0; dy < 5; dy++) {
            const ull* row = (const ull*)&sin_[(c * 8 + py + dy) * 68 + xo];
            ull r0 = row[0], r1 = row[1], r2 = row[2],
                r3 = row[3], r4 = row[4], r5 = row[5];
            ull m0 = pk2(f2hi(r0), f2lo(r1));
            ull m1 = pk2(f2hi(r1), f2lo(r2));
            ull m2 = pk2(f2hi(r2), f2lo(r3));
            ull m3 = pk2(f2hi(r3), f2lo(r4));
            ull m4 = pk2(f2hi(r4), f2lo(r5));
            const ull* w5r = &w5p[ch * 25 + dy * 5];
            ull w0 = w5r[0], w1 = w5r[1], w2 = w5r[2], w3v = w5r[3], w4 = w5r[4];

            ffma2(acc5[0], w0, r0); ffma2(acc5[0], w1, m0); ffma2(acc5[0], w2, r1);
            ffma2(acc5[0], w3v, m1); ffma2(acc5[0], w4, r2);
            ffma2(acc5[1], w0, r1); ffma2(acc5[1], w1, m1); ffma2(acc5[1], w2, r2);
            ffma2(acc5[1], w3v, m2); ffma2(acc5[1], w4, r3);
            ffma2(acc5[2], w0, r2); ffma2(acc5[2], w1, m2); ffma2(acc5[2], w2, r3);
            ffma2(acc5[2], w3v, m3); ffma2(acc5[2], w4, r4);
            ffma2(acc5[3], w0, r3); ffma2(acc5[3], w1, m3); ffma2(acc5[3], w2, r4);
            ffma2(acc5[3], w3v, m4); ffma2(acc5[3], w4, r5);

            if (dy >= 1 && dy <= 3) {
                const ull* w3r = &w3p[ch * 9 + (dy - 1) * 3];
                ull u0 = w3r[0], u1 = w3r[1], u2 = w3r[2];
                ffma2(acc3[0], u0, m0); ffma2(acc3[0], u1, r1); ffma2(acc3[0], u2, m1);
                ffma2(acc3[1], u0, m1); ffma2(acc3[1], u1, r2); ffma2(acc3[1], u2, m2);
                ffma2(acc3[2], u0, m2); ffma2(acc3[2], u1, r3); ffma2(acc3[2], u2, m3);
                ffma2(acc3[3], u0, m3); ffma2(acc3[3], u1, r4); ffma2(acc3[3], u2, m4);
            }
        }
        const int ppb = py * 32 + (xo >> 1);
#pragma unroll
        for (int j = 0; j < 4; j++) {
            *(ull*)&d3s[ch * 256 + (ppb + j) * 2] = acc3[j];
            *(ull*)&d5s[ch * 256 + (ppb + j) * 2] = acc5[j];
        }

        if (grp == 1) {
            // stash raw k channels (center 4 rows) for the qkv-head vk
            for (int i = tid; i < 8 * 256; i += 256) {
                int cc = i >> 8, px = i & 255;
                stash[i] = sin_[(cc * 8 + 2 + (px >> 6)) * 68 + 2 + (px & 63)];
            }
        }

        if (grp == 2) {
            // ---- fused vk for qkv-source head g (k from stash, v from sin_) ----
            const int px = tid;
            const int vy = px >> 6;
            const int vx = px & 63;
            float kk[8], vv[8];
#pragma unroll
            for (int e = 0; e < 8; e++)
                kk[e] = fmaxf(stash[e * 256 + px], 0.f);
#pragma unroll
            for (int d = 0; d < 8; d++)
                vv[d] = sin_[(d * 8 + 2 + vy) * 68 + 2 + vx];

            float vacc[9][8];
#pragma unroll
            for (int d = 0; d < 8; d++)
#pragma unroll
                for (int e = 0; e < 8; e++)
                    vacc[d][e] = vv[d] * kk[e];
#pragma unroll
            for (int e = 0; e < 8; e++) vacc[8][e] = kk[e];

#pragma unroll
            for (int d = 0; d < 9; d++)
#pragma unroll
                for (int e = 0; e < 8; e++) {
                    float v = vacc[d][e];
                    v += __shfl_xor_sync(0xffffffffu, v, 16);
                    v += __shfl_xor_sync(0xffffffffu, v, 8);
                    v += __shfl_xor_sync(0xffffffffu, v, 4);
                    v += __shfl_xor_sync(0xffffffffu, v, 2);
                    v += __shfl_xor_sync(0xffffffffu, v, 1);
                    vacc[d][e] = v;
                }
            __syncthreads();   // stash reads done -> reuse as reduction buffer
            const int w    = tid >> 5;
            const int lane = tid & 31;
            if (lane == 0) {
#pragma unroll
                for (int d = 0; d < 9; d++)
#pragma unroll
                    for (int e = 0; e < 8; e++)
                        stash[w * 72 + d * 8 + e] = vacc[d][e];
            }
            __syncthreads();
            if (tid < 72) {
                float s = 0.f;
#pragma unroll
                for (int j = 0; j < 8; j++) s += stash[j * 72 + tid];
                atomicAdd(&vkg[((size_t)b * 96 + g) * 72 + tid], s);
            }
        }
    }
    __syncthreads();

    // ---- phase B: grouped pointwise ----
    const int conv = tid >> 7;
    const int bp   = tid & 127;
    const float* dsrc = conv ? d5s : d3s;
    const ull* wp = &pwp[conv * 576];
    const ull* bb = &pwb[conv * 24];
    float* qout = conv ? s5q : s3q;

    ull d2[24];
#pragma unroll
    for (int ic = 0; ic < 24; ic++)
        d2[ic] = *(const ull*)&dsrc[ic * 256 + bp * 2];
    __syncthreads();   // d3s/d5s fully consumed; kvq overlay may be written

    const int by = y0 + (bp >> 5);
    const int bx = (bp & 31) * 2;
    const size_t qbase = (((size_t)b * 32 + g) * 8) * NPIX + by * WIDTH + bx;

#pragma unroll
    for (int o = 0; o < 24; o++) {
        ull acc = bb[o];
        const ull* wrow = &wp[o * 24];
#pragma unroll
        for (int ic = 0; ic < 24; ic++)
            ffma2(acc, wrow[ic], d2[ic]);
        if (o < 8) {
            *(float2*)&qout[qbase + (size_t)o * NPIX] =
                make_float2(f2lo(acc), f2hi(acc));
        } else {
            kvq[(conv * 16 + (o - 8)) * 128 + bp] = acc;
        }
    }
    __syncthreads();

    // ---- phase C: s3/s5 vk outer product + reduce + atomicAdd ----
    {
        const int w    = tid >> 5;
        const int lane = tid & 31;
        const int cv   = w >> 2;
        const int sub  = w & 3;
        const int pair = sub * 32 + lane;

        ull kvv[16];
#pragma unroll
        for (int ch = 0; ch < 16; ch++)
            kvv[ch] = kvq[(cv * 16 + ch) * 128 + pair];

        float acc[9][8];
#pragma unroll
        for (int d = 0; d < 9; d++)
#pragma unroll
            for (int e = 0; e < 8; e++) acc[d][e] = 0.f;

#pragma unroll
        for (int hx = 0; hx < 2; hx++) {
            float kk[8], vv[8];
#pragma unroll
            for (int e = 0; e < 8; e++)
                kk[e] = fmaxf(hx ? f2hi(kvv[e]) : f2lo(kvv[e]), 0.f);
#pragma unroll
            for (int d = 0; d < 8; d++)
                vv[d] = hx ? f2hi(kvv[8 + d]) : f2lo(kvv[8 + d]);
#pragma unroll
            for (int d = 0; d < 8; d++)
#pragma unroll
                for (int e = 0; e < 8; e++)
                    acc[d][e] += vv[d] * kk[e];
#pragma unroll
            for (int e = 0; e < 8; e++)
                acc[8][e] += kk[e];
        }

#pragma unroll
        for (int d = 0; d < 9; d++)
#pragma unroll
            for (int e = 0; e < 8; e++) {
                float v = acc[d][e];
                v += __shfl_xor_sync(0xffffffffu, v, 16);
                v += __shfl_xor_sync(0xffffffffu, v, 8);
                v += __shfl_xor_sync(0xffffffffu, v, 4);
                acc[d][e] = v;
            }
        if (lane < 4) {
            float* rp = &red[((cv * 16) + sub * 4 + lane) * 72];
#pragma unroll
            for (int d = 0; d < 9; d++)
#pragma unroll
                for (int e = 0; e < 8; e++)
                    rp[d * 8 + e] = acc[d][e];
        }
    }
    __syncthreads();

    if (tid < 144) {
        const int cv  = tid / 72;
        const int idx = tid % 72;
        float s = 0.f;
#pragma unroll
        for (int j = 0; j < 16; j++)
            s += red[(cv * 16 + j) * 72 + idx];
        atomicAdd(&vkg[((size_t)b * 96 + 32 + cv * 32 + g) * 72 + idx], s);
    }
}

// ---------------------------------------------------------------------------
// attention normalize -> channel-major fp16 (hi only, coalesced)
// ---------------------------------------------------------------------------
__global__ __launch_bounds__(256)
void att_kernel(const float* __restrict__ qkv, const float* __restrict__ s3q,
                const float* __restrict__ s5q, const float* __restrict__ vk,
                __half* __restrict__ atth)
{
    const int hh = blockIdx.x;
    const int b  = blockIdx.y;
    const int src_id = hh >> 5;
    const int g      = hh & 31;
    const float* base;
    if (src_id == 0)      base = qkv + ((size_t)b * C3 + g * 24) * NPIX;
    else if (src_id == 1) base = s3q + (((size_t)b * 32 + g) * 8) * NPIX;
    else                  base = s5q + (((size_t)b * 32 + g) * 8) * NPIX;

    __shared__ float vs[72];
    const int tid = threadIdx.x;
    if (tid < 72) vs[tid] = vk[((size_t)b * 96 + hh) * 72 + tid];
    __syncthreads();

    __half* oh = atth + ((size_t)b * C3 + hh * 8) * NPIX;

    for (int n2 = tid; n2 < NPIX / 2; n2 += 256) {
        const int n = n2 * 2;
        float q0[8], q1[8];
#pragma unroll
        for (int e = 0; e < 8; e++) {
            float2 qq = *(const float2*)(base + (size_t)e * NPIX + n);
            q0[e] = fmaxf(qq.x, 0.f);
            q1[e] = fmaxf(qq.y, 0.f);
        }
        float den0 = 1e-15f, den1 = 1e-15f;
#pragma unroll
        for (int e = 0; e < 8; e++) {
            den0 += vs[64 + e] * q0[e];
            den1 += vs[64 + e] * q1[e];
        }
        float rd0 = __fdividef(1.f, den0);
        float rd1 = __fdividef(1.f, den1);
#pragma unroll
        for (int d = 0; d < 8; d++) {
            float num0 = 0.f, num1 = 0.f;
#pragma unroll
            for (int e = 0; e < 8; e++) {
                num0 += vs[d * 8 + e] * q0[e];
                num1 += vs[d * 8 + e] * q1[e];
            }
            __half2 hp;
            hp.x = __float2half_rn(num0 * rd0);
            hp.y = __float2half_rn(num1 * rd1);
            *(__half2*)(oh + (size_t)d * NPIX + n) = hp;
        }
    }
}

// ---------------------------------------------------------------------------
extern "C" void kernel_launch(void* const* d_in, const int* in_sizes, int n_in,
                              void* d_out, int out_size)
{
    const float* x      = (const float*)d_in[0];
    const float* qkv_w  = (const float*)d_in[1];
    const float* qkv_b  = (const float*)d_in[2];
    const float* dw3_w  = (const float*)d_in[3];
    const float* dw3_b  = (const float*)d_in[4];
    const float* pw3_w  = (const float*)d_in[5];
    const float* pw3_b  = (const float*)d_in[6];
    const float* dw5_w  = (const float*)d_in[7];
    const float* dw5_b  = (const float*)d_in[8];
    const float* pw5_w  = (const float*)d_in[9];
    const float* pw5_b  = (const float*)d_in[10];
    const float* proj_w = (const float*)d_in[11];
    const float* proj_b = (const float*)d_in[12];
    float* out = (float*)d_out;

    void *p;
    cudaGetSymbolAddress(&p, g_qkv);  float* qkv = (float*)p;
    cudaGetSymbolAddress(&p, g_s3q);  float* s3q = (float*)p;
    cudaGetSymbolAddress(&p, g_s5q);  float* s5q = (float*)p;
    cudaGetSymbolAddress(&p, g_vk);   float* vkb = (float*)p;
    cudaGetSymbolAddress(&p, g_xt_h); __half* xth = (__half*)p;
    cudaGetSymbolAddress(&p, g_xt_l); __half* xtl = (__half*)p;
    cudaGetSymbolAddress(&p, g_at_h); __half* ath = (__half*)p;
    cudaGetSymbolAddress(&p, g_wq_h); __half* wqh = (__half*)p;
    cudaGetSymbolAddress(&p, g_wq_l); __half* wql = (__half*)p;
    cudaGetSymbolAddress(&p, g_wp_h); __half* wph = (__half*)p;
    cudaGetSymbolAddress(&p, g_wp_l); __half* wpl = (__half*)p;

    cudaFuncSetAttribute(gemm_f16, cudaFuncAttributeMaxDynamicSharedMemorySize,
                         2 * STG2);
    cudaFuncSetAttribute(gemm_f16_2p,
                         cudaFuncAttributeMaxDynamicSharedMemorySize, 3 * P2_STG);
    cudaFuncSetAttribute(dwpw_kernel,
                         cudaFuncAttributeMaxDynamicSharedMemorySize, DW_SMEM);

    // 0) splits (weights + x)
    wsplit_kernel<<<(C3 * 256 + 255) / 256, 256>>>(qkv_w, wqh, wql, C3 * 256);
    wsplit_kernel<<<(256 * C3 + 255) / 256, 256>>>(proj_w, wph, wpl, 256 * C3);
    wsplit_kernel<<<(BATCH * 256 * NPIX + 255) / 256, 256>>>(
        x, xth, xtl, BATCH * 256 * NPIX);

    // 1) qkv = Wq(768,256) @ x[b](256,4096) + b   (3-product)
    gemm_f16<<<dim3(NPIX / 128, C3 / 128, BATCH), 256, 2 * STG2>>>(
        wqh, wql, xth, xtl, qkv_b, qkv, C3, NPIX, 256);

    // 2) zero vk, then fused dwpw (s3/s5 conv + ALL vk reductions)
    zero_vk_kernel<<<(BATCH * 96 * 72 + 255) / 256, 256>>>(vkb);
    dwpw_kernel<<<dim3(16, 32, BATCH), 256, DW_SMEM>>>(
        qkv, dw3_w, dw3_b, pw3_w, pw3_b, dw5_w, dw5_b, pw5_w, pw5_b,
        s3q, s5q, vkb);

    // 3) attention normalize -> fp16 att (hi only)
    att_kernel<<<dim3(96, BATCH), 256>>>(qkv, s3q, s5q, vkb, ath);

    // 4) out = Wp(256,768) @ att[b](768,4096) + b   (2-product, 3-stage)
    gemm_f16_2p<<<dim3(NPIX / 128, 256 / 128, BATCH), 256, 3 * P2_STG>>>(
        wph, wpl, ath, proj_b, out, 256, NPIX, C3);
}

// round 8
// speedup vs baseline: 1.9796x; 1.0217x over previous
#include <cuda_runtime.h>
#include <cuda_fp16.h>
#include <cstdint>

// ---------------------------------------------------------------------------
// LiteMLA on sm_103a.
// qkv GEMM: fp16 hi/lo split x hi/lo (3 mma products, amplified error path).
// proj GEMM: weights hi/lo x att hi-only (2 products), 3-stage pipeline.
// dwpw: depthwise f32x2 -> register-tiled pointwise FFMA2 -> fused vk (all).
// att: 4 CTA/SM, packed-f32x2, z-split grid.
// ---------------------------------------------------------------------------

#define BATCH 8
#define C3 768
#define NPIX 4096
#define WIDTH 64

__device__ float g_qkv[(size_t)BATCH * C3 * NPIX];
__device__ float g_s3q[(size_t)BATCH * 32 * 8 * NPIX];   // q channels only
__device__ float g_s5q[(size_t)BATCH * 32 * 8 * NPIX];
__device__ float g_vk [(size_t)BATCH * 96 * 72];

__device__ __half g_xt_h [(size_t)BATCH * 256 * NPIX];   // x split [b][k][n]
__device__ __half g_xt_l [(size_t)BATCH * 256 * NPIX];
__device__ __half g_at_h [(size_t)BATCH * C3 * NPIX];    // att fp16 [b][k][n]
__device__ __half g_wq_h [C3 * 256];
__device__ __half g_wq_l [C3 * 256];
__device__ __half g_wp_h [256 * C3];
__device__ __half g_wp_l [256 * C3];

// ---------------------------------------------------------------------------
typedef unsigned long long ull;

__device__ __forceinline__ uint32_t smem_u32(const void* p) {
    uint32_t a;
    asm("{ .reg .u64 t; cvta.to.shared.u64 t, %1; cvt.u32.u64 %0, t; }"
        : "=r"(a) : "l"(p));
    return a;
}
__device__ __forceinline__ ull pk2(float lo, float hi) {
    ull r;
    asm("mov.b64 %0, {%1, %2};" : "=l"(r)
        : "r"(__float_as_uint(lo)), "r"(__float_as_uint(hi)));
    return r;
}
__device__ __forceinline__ void ffma2(ull& d, ull a, ull b) {
    asm("fma.rn.f32x2 %0, %1, %2, %0;" : "+l"(d) : "l"(a), "l"(b));
}
__device__ __forceinline__ float f2lo(ull v) {
    return __uint_as_float((unsigned)(v & 0xffffffffull));
}
__device__ __forceinline__ float f2hi(ull v) {
    return __uint_as_float((unsigned)(v >> 32));
}

#define CP_ASYNC16(s, g) \
    asm volatile("cp.async.cg.shared.global [%0], [%1], 16;" :: "r"(s), "l"(g))
#define CP_COMMIT() asm volatile("cp.async.commit_group;" ::: "memory")
#define CP_WAIT(n)  asm volatile("cp.async.wait_group %0;" :: "n"(n) : "memory")

__device__ __forceinline__ void ldsm4(uint32_t addr, uint32_t* r) {
    asm volatile("ldmatrix.sync.aligned.m8n8.x4.shared.b16 {%0,%1,%2,%3}, [%4];"
                 : "=r"(r[0]), "=r"(r[1]), "=r"(r[2]), "=r"(r[3]) : "r"(addr));
}
__device__ __forceinline__ void ldsm4t(uint32_t addr, uint32_t* r) {
    asm volatile("ldmatrix.sync.aligned.m8n8.x4.trans.shared.b16 {%0,%1,%2,%3}, [%4];"
                 : "=r"(r[0]), "=r"(r[1]), "=r"(r[2]), "=r"(r[3]) : "r"(addr));
}
__device__ __forceinline__ void mma_f16(float* d, const uint32_t* a,
                                        const uint32_t* b) {
    asm volatile(
        "mma.sync.aligned.m16n8k16.row.col.f32.f16.f16.f32 "
        "{%0,%1,%2,%3}, {%4,%5,%6,%7}, {%8,%9}, {%0,%1,%2,%3};"
        : "+f"(d[0]), "+f"(d[1]), "+f"(d[2]), "+f"(d[3])
        : "r"(a[0]), "r"(a[1]), "r"(a[2]), "r"(a[3]), "r"(b[0]), "r"(b[1]));
}

#define A_PITCH 80
#define B_PITCH 272

// ---------------------------------------------------------------------------
// 3-product GEMM (qkv): C[b] = (Ah+Al)(M,K) @ (Bh+Bl)(b,K,N) + bias
// ---------------------------------------------------------------------------
#define OFF_AL  10240
#define OFF_BH  20480
#define OFF_BL  29184
#define STG2    37888

__device__ __forceinline__ void stage_load(
    uint32_t sbase, const __half* gA_h, const __half* gA_l,
    const __half* gB_h, const __half* gB_l, int K, int N, int kc, int tid)
{
    const int op = tid >> 6;
    const int t  = tid & 63;
    if (op < 2) {
        const __half* g = ((op == 0) ? gA_h : gA_l) + kc * 32;
        const uint32_t sb = sbase + op * OFF_AL;
#pragma unroll
        for (int it = 0; it < 8; it++) {
            int chunk = t + it * 64;
            int row = chunk >> 2, c = chunk & 3;
            CP_ASYNC16(sb + row * A_PITCH + c * 16, g + (size_t)row * K + c * 8);
        }
    } else {
        const __half* g = ((op == 2) ? gB_h : gB_l) + (size_t)kc * 32 * N;
        const uint32_t sb = sbase + ((op == 2) ? OFF_BH : OFF_BL);
#pragma unroll
        for (int it = 0; it < 8; it++) {
            int chunk = t + it * 64;
            int row = chunk >> 4, c = chunk & 15;
            CP_ASYNC16(sb + row * B_PITCH + c * 16, g + (size_t)row * N + c * 8);
        }
    }
}

__global__ __launch_bounds__(256, 2)
void gemm_f16(const __half* __restrict__ Ah, const __half* __restrict__ Al,
              const __half* __restrict__ Bmh, const __half* __restrict__ Bml,
              const float* __restrict__ bias, float* __restrict__ C,
              int M, int N, int K)
{
    extern __shared__ __align__(16) char smem[];
    const uint32_t sm0 = smem_u32(smem);

    const int tid  = threadIdx.x;
    const int wid  = tid >> 5;
    const int lane = tid & 31;
    const int n0 = blockIdx.x * 128;
    const int m0 = blockIdx.y * 128;
    const int b  = blockIdx.z;

    const int wm = (wid >> 1) * 32;
    const int wn = (wid & 1) * 64;

    const __half* gA_h = Ah + (size_t)m0 * K;
    const __half* gA_l = Al + (size_t)m0 * K;
    const __half* gB_h = Bmh + (size_t)b * K * N + n0;
    const __half* gB_l = Bml + (size_t)b * K * N + n0;

    float acc[2][8][4];
#pragma unroll
    for (int t = 0; t < 2; t++)
#pragma unroll
        for (int nt = 0; nt < 8; nt++)
#pragma unroll
            for (int i = 0; i < 4; i++) acc[t][nt][i] = 0.f;

    const int nk = K / 32;

    stage_load(sm0, gA_h, gA_l, gB_h, gB_l, K, N, 0, tid);
    CP_COMMIT();
    if (nk > 1) {
        stage_load(sm0 + STG2, gA_h, gA_l, gB_h, gB_l, K, N, 1, tid);
        CP_COMMIT();
    }

    const int a_row = lane & 15;
    const int a_hi  = (lane >> 4) * 16;
    const int b_kr = (lane & 7) + ((lane >> 3) & 1) * 8;
    const int b_nc = (lane >> 4) * 8;

    for (int kc = 0; kc < nk; kc++) {
        if (kc + 1 < nk) CP_WAIT(1); else CP_WAIT(0);
        __syncthreads();

        const uint32_t sb  = sm0 + (kc & 1) * STG2;
        const uint32_t aAh = sb;
        const uint32_t aAl = sb + OFF_AL;
        const uint32_t aBh = sb + OFF_BH;
        const uint32_t aBl = sb + OFF_BL;

#pragma unroll
        for (int j = 0; j < 2; j++) {
            uint32_t ah[2][4], al[2][4];
#pragma unroll
            for (int t = 0; t < 2; t++) {
                uint32_t off = (uint32_t)(wm + t * 16 + a_row) * A_PITCH + j * 32 + a_hi;
                ldsm4(aAh + off, ah[t]);
                ldsm4(aAl + off, al[t]);
            }
            uint32_t bh[4][4], bl[4][4];
#pragma unroll
            for (int p = 0; p < 4; p++) {
                uint32_t off = (uint32_t)(j * 16 + b_kr) * B_PITCH +
                               (uint32_t)(wn + p * 16 + b_nc) * 2;
                ldsm4t(aBh + off, bh[p]);
                ldsm4t(aBl + off, bl[p]);
            }
#pragma unroll
            for (int t = 0; t < 2; t++)
#pragma unroll
                for (int nt = 0; nt < 8; nt++) {
                    const uint32_t* bhp = &bh[nt >> 1][(nt & 1) * 2];
                    const uint32_t* blp = &bl[nt >> 1][(nt & 1) * 2];
                    mma_f16(acc[t][nt], ah[t], bhp);
                    mma_f16(acc[t][nt], ah[t], blp);
                    mma_f16(acc[t][nt], al[t], bhp);
                }
        }
        __syncthreads();
        if (kc + 2 < nk) {
            stage_load(sm0 + (kc & 1) * STG2, gA_h, gA_l, gB_h, gB_l,
                       K, N, kc + 2, tid);
            CP_COMMIT();
        }
    }

    const int l4 = lane >> 2;
    const int l2 = (lane & 3) * 2;
#pragma unroll
    for (int t = 0; t < 2; t++) {
        const int m_lo = m0 + wm + t * 16 + l4;
        const float bi_lo = bias[m_lo];
        const float bi_hi = bias[m_lo + 8];
        float* c_lo = C + ((size_t)b * M + m_lo) * N + n0 + wn + l2;
        float* c_hi = c_lo + (size_t)8 * N;
#pragma unroll
        for (int nt = 0; nt < 8; nt++) {
            float2 v0 = {acc[t][nt][0] + bi_lo, acc[t][nt][1] + bi_lo};
            float2 v1 = {acc[t][nt][2] + bi_hi, acc[t][nt][3] + bi_hi};
            *(float2*)(c_lo + nt * 8) = v0;
            *(float2*)(c_hi + nt * 8) = v1;
        }
    }
}

// ---------------------------------------------------------------------------
// 2-product GEMM (proj): C[b] = (Ah+Al)(M,K) @ Bh(b,K,N) + bias, 3-stage.
// ---------------------------------------------------------------------------
#define P2_AL   10240
#define P2_BH   20480
#define P2_STG  29184

__device__ __forceinline__ void stage_load_2p(
    uint32_t sbase, const __half* gA_h, const __half* gA_l,
    const __half* gB_h, int K, int N, int kc, int tid)
{
    if (tid < 128) {
        const int op = tid >> 6;
        const int t  = tid & 63;
        const __half* g = ((op == 0) ? gA_h : gA_l) + kc * 32;
        const uint32_t sb = sbase + op * P2_AL;
#pragma unroll
        for (int it = 0; it < 8; it++) {
            int chunk = t + it * 64;
            int row = chunk >> 2, c = chunk & 3;
            CP_ASYNC16(sb + row * A_PITCH + c * 16, g + (size_t)row * K + c * 8);
        }
    } else {
        const int t = tid - 128;
        const __half* g = gB_h + (size_t)kc * 32 * N;
        const uint32_t sb = sbase + P2_BH;
#pragma unroll
        for (int it = 0; it < 4; it++) {
            int chunk = t + it * 128;
            int row = chunk >> 4, c = chunk & 15;
            CP_ASYNC16(sb + row * B_PITCH + c * 16, g + (size_t)row * N + c * 8);
        }
    }
}

__global__ __launch_bounds__(256, 2)
void gemm_f16_2p(const __half* __restrict__ Ah, const __half* __restrict__ Al,
                 const __half* __restrict__ Bmh,
                 const float* __restrict__ bias, float* __restrict__ C,
                 int M, int N, int K)
{
    extern __shared__ __align__(16) char smem[];
    const uint32_t sm0 = smem_u32(smem);

    const int tid  = threadIdx.x;
    const int wid  = tid >> 5;
    const int lane = tid & 31;
    const int n0 = blockIdx.x * 128;
    const int m0 = blockIdx.y * 128;
    const int b  = blockIdx.z;

    const int wm = (wid >> 1) * 32;
    const int wn = (wid & 1) * 64;

    const __half* gA_h = Ah + (size_t)m0 * K;
    const __half* gA_l = Al + (size_t)m0 * K;
    const __half* gB_h = Bmh + (size_t)b * K * N + n0;

    float acc[2][8][4];
#pragma unroll
    for (int t = 0; t < 2; t++)
#pragma unroll
        for (int nt = 0; nt < 8; nt++)
#pragma unroll
            for (int i = 0; i < 4; i++) acc[t][nt][i] = 0.f;

    const int nk = K / 32;

    stage_load_2p(sm0, gA_h, gA_l, gB_h, K, N, 0, tid);
    CP_COMMIT();
    if (nk > 1) {
        stage_load_2p(sm0 + P2_STG, gA_h, gA_l, gB_h, K, N, 1, tid);
        CP_COMMIT();
    }

    const int a_row = lane & 15;
    const int a_hi  = (lane >> 4) * 16;
    const int b_kr = (lane & 7) + ((lane >> 3) & 1) * 8;
    const int b_nc = (lane >> 4) * 8;

    for (int kc = 0; kc < nk; kc++) {
        if (kc + 2 < nk) {
            stage_load_2p(sm0 + ((kc + 2) % 3) * P2_STG,
                          gA_h, gA_l, gB_h, K, N, kc + 2, tid);
            CP_COMMIT();
        }
        if (kc + 2 < nk)      CP_WAIT(2);
        else if (kc + 1 < nk) CP_WAIT(1);
        else                  CP_WAIT(0);
        __syncthreads();

        const uint32_t sb  = sm0 + (kc % 3) * P2_STG;
        const uint32_t aAh = sb;
        const uint32_t aAl = sb + P2_AL;
        const uint32_t aBh = sb + P2_BH;

#pragma unroll
        for (int j = 0; j < 2; j++) {
            uint32_t ah[2][4], al[2][4];
#pragma unroll
            for (int t = 0; t < 2; t++) {
                uint32_t off = (uint32_t)(wm + t * 16 + a_row) * A_PITCH + j * 32 + a_hi;
                ldsm4(aAh + off, ah[t]);
                ldsm4(aAl + off, al[t]);
            }
            uint32_t bh[4][4];
#pragma unroll
            for (int p = 0; p < 4; p++) {
                uint32_t off = (uint32_t)(j * 16 + b_kr) * B_PITCH +
                               (uint32_t)(wn + p * 16 + b_nc) * 2;
                ldsm4t(aBh + off, bh[p]);
            }
#pragma unroll
            for (int t = 0; t < 2; t++)
#pragma unroll
                for (int nt = 0; nt < 8; nt++) {
                    const uint32_t* bhp = &bh[nt >> 1][(nt & 1) * 2];
                    mma_f16(acc[t][nt], ah[t], bhp);
                    mma_f16(acc[t][nt], al[t], bhp);
                }
        }
        __syncthreads();
    }

    const int l4 = lane >> 2;
    const int l2 = (lane & 3) * 2;
#pragma unroll
    for (int t = 0; t < 2; t++) {
        const int m_lo = m0 + wm + t * 16 + l4;
        const float bi_lo = bias[m_lo];
        const float bi_hi = bias[m_lo + 8];
        float* c_lo = C + ((size_t)b * M + m_lo) * N + n0 + wn + l2;
        float* c_hi = c_lo + (size_t)8 * N;
#pragma unroll
        for (int nt = 0; nt < 8; nt++) {
            float2 v0 = {acc[t][nt][0] + bi_lo, acc[t][nt][1] + bi_lo};
            float2 v1 = {acc[t][nt][2] + bi_hi, acc[t][nt][3] + bi_hi};
            *(float2*)(c_lo + nt * 8) = v0;
            *(float2*)(c_hi + nt * 8) = v1;
        }
    }
}

// ---------------------------------------------------------------------------
__global__ void wsplit_kernel(const float* __restrict__ w,
                              __half* __restrict__ hi,
                              __half* __restrict__ lo, int n)
{
    int i = blockIdx.x * 256 + threadIdx.x;
    if (i < n) {
        float v = w[i];
        __half h = __float2half_rn(v);
        hi[i] = h;
        lo[i] = __float2half_rn(v - __half2float(h));
    }
}

__global__ void zero_vk_kernel(float* __restrict__ vk)
{
    int i = blockIdx.x * 256 + threadIdx.x;
    if (i < BATCH * 96 * 72) vk[i] = 0.f;
}

// ---------------------------------------------------------------------------
// dwpw v6: phase A (channel x 8px) + fused qkv-head vk + register-tiled
// pointwise (6 outs x 4 pairs per thread) + s3/s5 vk.
// ---------------------------------------------------------------------------
#define OFF_SIN   0                    // float[8][8][68]       17408
#define OFF_D3    17408                // float[24][256] / kvq overlay
#define OFF_D5    41984                // float[24][256]
#define OFF_W5P   66560                // ull[24][25]            4800
#define OFF_W3P   71360                // ull[24][9]             1728
#define OFF_PWP   73088                // ull[2][24][24] / red   9216
#define OFF_PWB   82304                // ull[2][24]              384
#define OFF_DB5   82688                // ull[24]                 192
#define OFF_DB3   82880                // ull[24]                 192
#define OFF_STASH 83072                // float[8][256]          8192
#define DW_SMEM   91264

__global__ __launch_bounds__(256, 2)
void dwpw_kernel(const float* __restrict__ qkv,
                 const float* __restrict__ dw3_w, const float* __restrict__ dw3_b,
                 const float* __restrict__ pw3_w, const float* __restrict__ pw3_b,
                 const float* __restrict__ dw5_w, const float* __restrict__ dw5_b,
                 const float* __restrict__ pw5_w, const float* __restrict__ pw5_b,
                 float* __restrict__ s3q, float* __restrict__ s5q,
                 float* __restrict__ vkg)
{
    extern __shared__ __align__(16) char sm[];
    float* sin_  = (float*)(sm + OFF_SIN);
    float* d3s   = (float*)(sm + OFF_D3);
    float* d5s   = (float*)(sm + OFF_D5);
    ull*   kvq   = (ull*)(sm + OFF_D3);      // overlay (after phase B)
    float* red   = (float*)(sm + OFF_PWP);   // overlay (phase C)
    float* stash = (float*)(sm + OFF_STASH);
    ull*   w5p   = (ull*)(sm + OFF_W5P);
    ull*   w3p   = (ull*)(sm + OFF_W3P);
    ull*   pwp   = (ull*)(sm + OFF_PWP);
    ull*   pwb   = (ull*)(sm + OFF_PWB);
    ull*   db5   = (ull*)(sm + OFF_DB5);
    ull*   db3   = (ull*)(sm + OFF_DB3);

    const int ytile = blockIdx.x;
    const int g     = blockIdx.y;
    const int b     = blockIdx.z;
    const int tid   = threadIdx.x;
    const int y0    = ytile * 4;

    for (int i = tid; i < 600; i += 256) {
        float w = dw5_w[(g * 24 + i / 25) * 25 + i % 25];
        w5p[i] = pk2(w, w);
    }
    for (int i = tid; i < 216; i += 256) {
        float w = dw3_w[(g * 24 + i / 9) * 9 + i % 9];
        w3p[i] = pk2(w, w);
    }
    for (int i = tid; i < 576; i += 256) {
        float a = pw3_w[g * 576 + i];
        float c = pw5_w[g * 576 + i];
        pwp[i] = pk2(a, a);
        pwp[576 + i] = pk2(c, c);
    }
    if (tid < 24) {
        float b3 = pw3_b[g * 24 + tid], b5 = pw5_b[g * 24 + tid];
        pwb[tid] = pk2(b3, b3);
        pwb[24 + tid] = pk2(b5, b5);
        float d3b = dw3_b[g * 24 + tid], d5b = dw5_b[g * 24 + tid];
        db3[tid] = pk2(d3b, d3b);
        db5[tid] = pk2(d5b, d5b);
    }

    // ---- phase A: depthwise, thread = 1 ch x 8 px ----
    const int c  = tid >> 5;
    const int t  = tid & 31;
    const int py = t >> 3;
    const int xo = (t & 7) * 8;

    for (int grp = 0; grp < 3; grp++) {
        __syncthreads();
        const int icb = grp * 8;
        const float* src = qkv + ((size_t)b * C3 + g * 24 + icb) * NPIX;
        for (int i = tid; i < 8 * 8 * 68; i += 256) {
            int xx = i % 68;
            int r  = (i / 68) & 7;
            int cc = i / (68 * 8);
            int yy = y0 - 2 + r;
            int xg = xx - 2;
            float v = 0.f;
            if ((unsigned)yy < 64u && (unsigned)xg < 64u)
                v = src[(size_t)cc * NPIX + yy * WIDTH + xg];
            sin_[(cc * 8 + r) * 68 + xx] = v;
        }
        __syncthreads();

        const int ch = icb + c;
        ull acc5[4], acc3[4];
        {
            ull b5v = db5[ch], b3v = db3[ch];
#pragma unroll
            for (int j = 0; j < 4; j++) { acc5[j] = b5v; acc3[j] = b3v; }
        }
#pragma unroll
        for (int dy = 0; dy < 5; dy++) {
            const ull* row = (const ull*)&sin_[(c * 8 + py + dy) * 68 + xo];
            ull r0 = row[0], r1 = row[1], r2 = row[2],
                r3 = row[3], r4 = row[4], r5 = row[5];
            ull m0 = pk2(f2hi(r0), f2lo(r1));
            ull m1 = pk2(f2hi(r1), f2lo(r2));
            ull m2 = pk2(f2hi(r2), f2lo(r3));
            ull m3 = pk2(f2hi(r3), f2lo(r4));
            ull m4 = pk2(f2hi(r4), f2lo(r5));
            const ull* w5r = &w5p[ch * 25 + dy * 5];
            ull w0 = w5r[0], w1 = w5r[1], w2 = w5r[2], w3v = w5r[3], w4 = w5r[4];

            ffma2(acc5[0], w0, r0); ffma2(acc5[0], w1, m0); ffma2(acc5[0], w2, r1);
            ffma2(acc5[0], w3v, m1); ffma2(acc5[0], w4, r2);
            ffma2(acc5[1], w0, r1); ffma2(acc5[1], w1, m1); ffma2(acc5[1], w2, r2);
            ffma2(acc5[1], w3v, m2); ffma2(acc5[1], w4, r3);
            ffma2(acc5[2], w0, r2); ffma2(acc5[2], w1, m2); ffma2(acc5[2], w2, r3);
            ffma2(acc5[2], w3v, m3); ffma2(acc5[2], w4, r4);
            ffma2(acc5[3], w0, r3); ffma2(acc5[3], w1, m3); ffma2(acc5[3], w2, r4);
            ffma2(acc5[3], w3v, m4); ffma2(acc5[3], w4, r5);

            if (dy >= 1 && dy <= 3) {
                const ull* w3r = &w3p[ch * 9 + (dy - 1) * 3];
                ull u0 = w3r[0], u1 = w3r[1], u2 = w3r[2];
                ffma2(acc3[0], u0, m0); ffma2(acc3[0], u1, r1); ffma2(acc3[0], u2, m1);
                ffma2(acc3[1], u0, m1); ffma2(acc3[1], u1, r2); ffma2(acc3[1], u2, m2);
                ffma2(acc3[2], u0, m2); ffma2(acc3[2], u1, r3); ffma2(acc3[2], u2, m3);
                ffma2(acc3[3], u0, m3); ffma2(acc3[3], u1, r4); ffma2(acc3[3], u2, m4);
            }
        }
        const int ppb = py * 32 + (xo >> 1);
#pragma unroll
        for (int j = 0; j < 4; j++) {
            *(ull*)&d3s[ch * 256 + (ppb + j) * 2] = acc3[j];
            *(ull*)&d5s[ch * 256 + (ppb + j) * 2] = acc5[j];
        }

        if (grp == 1) {
            for (int i = tid; i < 8 * 256; i += 256) {
                int cc = i >> 8, px = i & 255;
                stash[i] = sin_[(cc * 8 + 2 + (px >> 6)) * 68 + 2 + (px & 63)];
            }
        }

        if (grp == 2) {
            // fused vk for qkv-source head g (k from stash, v from sin_)
            const int px = tid;
            const int vy = px >> 6;
            const int vx = px & 63;
            float kk[8], vv[8];
#pragma unroll
            for (int e = 0; e < 8; e++)
                kk[e] = fmaxf(stash[e * 256 + px], 0.f);
#pragma unroll
            for (int d = 0; d < 8; d++)
                vv[d] = sin_[(d * 8 + 2 + vy) * 68 + 2 + vx];

            float vacc[9][8];
#pragma unroll
            for (int d = 0; d < 8; d++)
#pragma unroll
                for (int e = 0; e < 8; e++)
                    vacc[d][e] = vv[d] * kk[e];
#pragma unroll
            for (int e = 0; e < 8; e++) vacc[8][e] = kk[e];

#pragma unroll
            for (int d = 0; d < 9; d++)
#pragma unroll
                for (int e = 0; e < 8; e++) {
                    float v = vacc[d][e];
                    v += __shfl_xor_sync(0xffffffffu, v, 16);
                    v += __shfl_xor_sync(0xffffffffu, v, 8);
                    v += __shfl_xor_sync(0xffffffffu, v, 4);
                    v += __shfl_xor_sync(0xffffffffu, v, 2);
                    v += __shfl_xor_sync(0xffffffffu, v, 1);
                    vacc[d][e] = v;
                }
            __syncthreads();
            const int w    = tid >> 5;
            const int lane = tid & 31;
            if (lane == 0) {
#pragma unroll
                for (int d = 0; d < 9; d++)
#pragma unroll
                    for (int e = 0; e < 8; e++)
                        stash[w * 72 + d * 8 + e] = vacc[d][e];
            }
            __syncthreads();
            if (tid < 72) {
                float s = 0.f;
#pragma unroll
                for (int j = 0; j < 8; j++) s += stash[j * 72 + tid];
                atomicAdd(&vkg[((size_t)b * 96 + g) * 72 + tid], s);
            }
        }
    }
    __syncthreads();

    // ---- phase B: register-tiled grouped pointwise (6 outs x 4 pairs) ----
    const int conv = tid >> 7;
    const int tt   = tid & 127;
    const int og   = tt >> 5;            // output group: o in og*6..og*6+5
    const int pg   = tt & 31;            // pairs pg*4..pg*4+3
    const float* dsrc = conv ? d5s : d3s;
    const ull* wp = &pwp[conv * 576];
    const ull* bb = &pwb[conv * 24];
    float* qout = conv ? s5q : s3q;

    ull acc[6][4];
#pragma unroll
    for (int j = 0; j < 6; j++) {
        ull bv = bb[og * 6 + j];
#pragma unroll
        for (int i = 0; i < 4; i++) acc[j][i] = bv;
    }

#pragma unroll
    for (int ic = 0; ic < 24; ic++) {
        const ulonglong2 dA = *(const ulonglong2*)&dsrc[ic * 256 + pg * 8];
        const ulonglong2 dB = *(const ulonglong2*)&dsrc[ic * 256 + pg * 8 + 4];
        ull dv[4] = {dA.x, dA.y, dB.x, dB.y};
#pragma unroll
        for (int j = 0; j < 6; j++) {
            ull wv = wp[(og * 6 + j) * 24 + ic];
#pragma unroll
            for (int i = 0; i < 4; i++)
                ffma2(acc[j][i], wv, dv[i]);
        }
    }
    __syncthreads();   // d3s/d5s fully consumed; kvq overlay writable

    {
        const int pair0 = pg * 4;
        const int by = y0 + (pair0 >> 5);
        const int bx = (pair0 & 31) * 2;
        const size_t qbase = (((size_t)b * 32 + g) * 8) * NPIX + by * WIDTH + bx;
#pragma unroll
        for (int j = 0; j < 6; j++) {
            const int o = og * 6 + j;
            if (o < 8) {
#pragma unroll
                for (int i = 0; i < 4; i++)
                    *(float2*)&qout[qbase + (size_t)o * NPIX + i * 2] =
                        make_float2(f2lo(acc[j][i]), f2hi(acc[j][i]));
            } else {
#pragma unroll
                for (int i = 0; i < 4; i++)
                    kvq[(conv * 16 + (o - 8)) * 128 + pair0 + i] = acc[j][i];
            }
        }
    }
    __syncthreads();

    // ---- phase C: s3/s5 vk outer product + reduce + atomicAdd ----
    {
        const int w    = tid >> 5;
        const int lane = tid & 31;
        const int cv   = w >> 2;
        const int sub  = w & 3;
        const int pair = sub * 32 + lane;

        ull kvv[16];
#pragma unroll
        for (int ch = 0; ch < 16; ch++)
            kvv[ch] = kvq[(cv * 16 + ch) * 128 + pair];

        float acc2[9][8];
#pragma unroll
        for (int d = 0; d < 9; d++)
#pragma unroll
            for (int e = 0; e < 8; e++) acc2[d][e] = 0.f;

#pragma unroll
        for (int hx = 0; hx < 2; hx++) {
            float kk[8], vv[8];
#pragma unroll
            for (int e = 0; e < 8; e++)
                kk[e] = fmaxf(hx ? f2hi(kvv[e]) : f2lo(kvv[e]), 0.f);
#pragma unroll
            for (int d = 0; d < 8; d++)
                vv[d] = hx ? f2hi(kvv[8 + d]) : f2lo(kvv[8 + d]);
#pragma unroll
            for (int d = 0; d < 8; d++)
#pragma unroll
                for (int e = 0; e < 8; e++)
                    acc2[d][e] += vv[d] * kk[e];
#pragma unroll
            for (int e = 0; e < 8; e++)
                acc2[8][e] += kk[e];
        }

#pragma unroll
        for (int d = 0; d < 9; d++)
#pragma unroll
            for (int e = 0; e < 8; e++) {
                float v = acc2[d][e];
                v += __shfl_xor_sync(0xffffffffu, v, 16);
                v += __shfl_xor_sync(0xffffffffu, v, 8);
                v += __shfl_xor_sync(0xffffffffu, v, 4);
                acc2[d][e] = v;
            }
        if (lane < 4) {
            float* rp = &red[((cv * 16) + sub * 4 + lane) * 72];
#pragma unroll
            for (int d = 0; d < 9; d++)
#pragma unroll
                for (int e = 0; e < 8; e++)
                    rp[d * 8 + e] = acc2[d][e];
        }
    }
    __syncthreads();

    if (tid < 144) {
        const int cv  = tid / 72;
        const int idx = tid % 72;
        float s = 0.f;
#pragma unroll
        for (int j = 0; j < 16; j++)
            s += red[(cv * 16 + j) * 72 + idx];
        atomicAdd(&vkg[((size_t)b * 96 + 32 + cv * 32 + g) * 72 + idx], s);
    }
}

// ---------------------------------------------------------------------------
// attention normalize v2: 4 CTAs/SM, packed f32x2, z-split grid.
// grid (96, BATCH, 4), 256 threads, 2 iterations/thread.
// ---------------------------------------------------------------------------
__global__ __launch_bounds__(256, 4)
void att_kernel(const float* __restrict__ qkv, const float* __restrict__ s3q,
                const float* __restrict__ s5q, const float* __restrict__ vk,
                __half* __restrict__ atth)
{
    const int hh = blockIdx.x;
    const int b  = blockIdx.y;
    const int n0 = blockIdx.z * (NPIX / 4);
    const int src_id = hh >> 5;
    const int g      = hh & 31;
    const float* base;
    if (src_id == 0)      base = qkv + ((size_t)b * C3 + g * 24) * NPIX;
    else if (src_id == 1) base = s3q + (((size_t)b * 32 + g) * 8) * NPIX;
    else                  base = s5q + (((size_t)b * 32 + g) * 8) * NPIX;

    __shared__ ull vsp[72];
    const int tid = threadIdx.x;
    if (tid < 72) {
        float v = vk[((size_t)b * 96 + hh) * 72 + tid];
        vsp[tid] = pk2(v, v);
    }
    __syncthreads();

    __half* oh = atth + ((size_t)b * C3 + hh * 8) * NPIX;

#pragma unroll
    for (int it = 0; it < 2; it++) {
        const int n = n0 + (tid + it * 256) * 2;
        ull qp[8];
#pragma unroll
        for (int e = 0; e < 8; e++) {
            ull raw = *(const ull*)(base + (size_t)e * NPIX + n);
            qp[e] = pk2(fmaxf(f2lo(raw), 0.f), fmaxf(f2hi(raw), 0.f));
        }
        ull den = pk2(1e-15f, 1e-15f);
#pragma unroll
        for (int e = 0; e < 8; e++) ffma2(den, vsp[64 + e], qp[e]);
        const float rd0 = __fdividef(1.f, f2lo(den));
        const float rd1 = __fdividef(1.f, f2hi(den));
#pragma unroll
        for (int d = 0; d < 8; d++) {
            ull num = 0ull;
#pragma unroll
            for (int e = 0; e < 8; e++) ffma2(num, vsp[d * 8 + e], qp[e]);
            __half2 hp;
            hp.x = __float2half_rn(f2lo(num) * rd0);
            hp.y = __float2half_rn(f2hi(num) * rd1);
            *(__half2*)(oh + (size_t)d * NPIX + n) = hp;
        }
    }
}

// ---------------------------------------------------------------------------
extern "C" void kernel_launch(void* const* d_in, const int* in_sizes, int n_in,
                              void* d_out, int out_size)
{
    const float* x      = (const float*)d_in[0];
    const float* qkv_w  = (const float*)d_in[1];
    const float* qkv_b  = (const float*)d_in[2];
    const float* dw3_w  = (const float*)d_in[3];
    const float* dw3_b  = (const float*)d_in[4];
    const float* pw3_w  = (const float*)d_in[5];
    const float* pw3_b  = (const float*)d_in[6];
    const float* dw5_w  = (const float*)d_in[7];
    const float* dw5_b  = (const float*)d_in[8];
    const float* pw5_w  = (const float*)d_in[9];
    const float* pw5_b  = (const float*)d_in[10];
    const float* proj_w = (const float*)d_in[11];
    const float* proj_b = (const float*)d_in[12];
    float* out = (float*)d_out;

    void *p;
    cudaGetSymbolAddress(&p, g_qkv);  float* qkv = (float*)p;
    cudaGetSymbolAddress(&p, g_s3q);  float* s3q = (float*)p;
    cudaGetSymbolAddress(&p, g_s5q);  float* s5q = (float*)p;
    cudaGetSymbolAddress(&p, g_vk);   float* vkb = (float*)p;
    cudaGetSymbolAddress(&p, g_xt_h); __half* xth = (__half*)p;
    cudaGetSymbolAddress(&p, g_xt_l); __half* xtl = (__half*)p;
    cudaGetSymbolAddress(&p, g_at_h); __half* ath = (__half*)p;
    cudaGetSymbolAddress(&p, g_wq_h); __half* wqh = (__half*)p;
    cudaGetSymbolAddress(&p, g_wq_l); __half* wql = (__half*)p;
    cudaGetSymbolAddress(&p, g_wp_h); __half* wph = (__half*)p;
    cudaGetSymbolAddress(&p, g_wp_l); __half* wpl = (__half*)p;

    cudaFuncSetAttribute(gemm_f16, cudaFuncAttributeMaxDynamicSharedMemorySize,
                         2 * STG2);
    cudaFuncSetAttribute(gemm_f16_2p,
                         cudaFuncAttributeMaxDynamicSharedMemorySize, 3 * P2_STG);
    cudaFuncSetAttribute(dwpw_kernel,
                         cudaFuncAttributeMaxDynamicSharedMemorySize, DW_SMEM);

    // 0) splits (weights + x)
    wsplit_kernel<<<(C3 * 256 + 255) / 256, 256>>>(qkv_w, wqh, wql, C3 * 256);
    wsplit_kernel<<<(256 * C3 + 255) / 256, 256>>>(proj_w, wph, wpl, 256 * C3);
    wsplit_kernel<<<(BATCH * 256 * NPIX + 255) / 256, 256>>>(
        x, xth, xtl, BATCH * 256 * NPIX);

    // 1) qkv = Wq(768,256) @ x[b](256,4096) + b   (3-product)
    gemm_f16<<<dim3(NPIX / 128, C3 / 128, BATCH), 256, 2 * STG2>>>(
        wqh, wql, xth, xtl, qkv_b, qkv, C3, NPIX, 256);

    // 2) zero vk, then fused dwpw (s3/s5 conv + ALL vk reductions)
    zero_vk_kernel<<<(BATCH * 96 * 72 + 255) / 256, 256>>>(vkb);
    dwpw_kernel<<<dim3(16, 32, BATCH), 256, DW_SMEM>>>(
        qkv, dw3_w, dw3_b, pw3_w, pw3_b, dw5_w, dw5_b, pw5_w, pw5_b,
        s3q, s5q, vkb);

    // 3) attention normalize -> fp16 att (hi only)
    att_kernel<<<dim3(96, BATCH, 4), 256>>>(qkv, s3q, s5q, vkb, ath);

    // 4) out = Wp(256,768) @ att[b](768,4096) + b   (2-product, 3-stage)
    gemm_f16_2p<<<dim3(NPIX / 128, 256 / 128, BATCH), 256, 3 * P2_STG>>>(
        wph, wpl, ath, proj_b, out, 256, NPIX, C3);
}

// round 9
// speedup vs baseline: 2.0616x; 1.0414x over previous
#include <cuda_runtime.h>
#include <cuda_fp16.h>
#include <cstdint>

// ---------------------------------------------------------------------------
// LiteMLA on sm_103a.
// Two-stream batch-split pipeline (b0-3 / b4-7) to overlap stage tails.
// qkv GEMM: fp16 hi/lo x hi/lo, 3 mma products, 3-stage cp.async ring.
// proj GEMM: weights hi/lo x att fp16, 2 products, 3-stage ring.
// dwpw: depthwise f32x2 -> register-tiled pointwise -> fused vk (all heads).
// ---------------------------------------------------------------------------

#define BATCH 8
#define C3 768
#define NPIX 4096
#define WIDTH 64

__device__ float g_qkv[(size_t)BATCH * C3 * NPIX];
__device__ float g_s3q[(size_t)BATCH * 32 * 8 * NPIX];   // q channels only
__device__ float g_s5q[(size_t)BATCH * 32 * 8 * NPIX];
__device__ float g_vk [(size_t)BATCH * 96 * 72];

__device__ __half g_xt_h [(size_t)BATCH * 256 * NPIX];   // x split [b][k][n]
__device__ __half g_xt_l [(size_t)BATCH * 256 * NPIX];
__device__ __half g_at_h [(size_t)BATCH * C3 * NPIX];    // att fp16 [b][k][n]
__device__ __half g_wq_h [C3 * 256];
__device__ __half g_wq_l [C3 * 256];
__device__ __half g_wp_h [256 * C3];
__device__ __half g_wp_l [256 * C3];

// ---------------------------------------------------------------------------
typedef unsigned long long ull;

__device__ __forceinline__ uint32_t smem_u32(const void* p) {
    uint32_t a;
    asm("{ .reg .u64 t; cvta.to.shared.u64 t, %1; cvt.u32.u64 %0, t; }"
        : "=r"(a) : "l"(p));
    return a;
}
__device__ __forceinline__ ull pk2(float lo, float hi) {
    ull r;
    asm("mov.b64 %0, {%1, %2};" : "=l"(r)
        : "r"(__float_as_uint(lo)), "r"(__float_as_uint(hi)));
    return r;
}
__device__ __forceinline__ void ffma2(ull& d, ull a, ull b) {
    asm("fma.rn.f32x2 %0, %1, %2, %0;" : "+l"(d) : "l"(a), "l"(b));
}
__device__ __forceinline__ float f2lo(ull v) {
    return __uint_as_float((unsigned)(v & 0xffffffffull));
}
__device__ __forceinline__ float f2hi(ull v) {
    return __uint_as_float((unsigned)(v >> 32));
}

#define CP_ASYNC16(s, g) \
    asm volatile("cp.async.cg.shared.global [%0], [%1], 16;" :: "r"(s), "l"(g))
#define CP_COMMIT() asm volatile("cp.async.commit_group;" ::: "memory")
#define CP_WAIT(n)  asm volatile("cp.async.wait_group %0;" :: "n"(n) : "memory")

__device__ __forceinline__ void ldsm4(uint32_t addr, uint32_t* r) {
    asm volatile("ldmatrix.sync.aligned.m8n8.x4.shared.b16 {%0,%1,%2,%3}, [%4];"
                 : "=r"(r[0]), "=r"(r[1]), "=r"(r[2]), "=r"(r[3]) : "r"(addr));
}
__device__ __forceinline__ void ldsm4t(uint32_t addr, uint32_t* r) {
    asm volatile("ldmatrix.sync.aligned.m8n8.x4.trans.shared.b16 {%0,%1,%2,%3}, [%4];"
                 : "=r"(r[0]), "=r"(r[1]), "=r"(r[2]), "=r"(r[3]) : "r"(addr));
}
__device__ __forceinline__ void mma_f16(float* d, const uint32_t* a,
                                        const uint32_t* b) {
    asm volatile(
        "mma.sync.aligned.m16n8k16.row.col.f32.f16.f16.f32 "
        "{%0,%1,%2,%3}, {%4,%5,%6,%7}, {%8,%9}, {%0,%1,%2,%3};"
        : "+f"(d[0]), "+f"(d[1]), "+f"(d[2]), "+f"(d[3])
        : "r"(a[0]), "r"(a[1]), "r"(a[2]), "r"(a[3]), "r"(b[0]), "r"(b[1]));
}

#define A_PITCH 80
#define B_PITCH 272

// ---------------------------------------------------------------------------
// 3-product GEMM (qkv): C[b] = (Ah+Al)(M,K) @ (Bh+Bl)(b,K,N) + bias
// 3-stage cp.async ring, 2 CTAs/SM (3 * 37888 = 111 KB).
// ---------------------------------------------------------------------------
#define OFF_AL  10240
#define OFF_BH  20480
#define OFF_BL  29184
#define STG2    37888

__device__ __forceinline__ void stage_load(
    uint32_t sbase, const __half* gA_h, const __half* gA_l,
    const __half* gB_h, const __half* gB_l, int K, int N, int kc, int tid)
{
    const int op = tid >> 6;
    const int t  = tid & 63;
    if (op < 2) {
        const __half* g = ((op == 0) ? gA_h : gA_l) + kc * 32;
        const uint32_t sb = sbase + op * OFF_AL;
#pragma unroll
        for (int it = 0; it < 8; it++) {
            int chunk = t + it * 64;
            int row = chunk >> 2, c = chunk & 3;
            CP_ASYNC16(sb + row * A_PITCH + c * 16, g + (size_t)row * K + c * 8);
        }
    } else {
        const __half* g = ((op == 2) ? gB_h : gB_l) + (size_t)kc * 32 * N;
        const uint32_t sb = sbase + ((op == 2) ? OFF_BH : OFF_BL);
#pragma unroll
        for (int it = 0; it < 8; it++) {
            int chunk = t + it * 64;
            int row = chunk >> 4, c = chunk & 15;
            CP_ASYNC16(sb + row * B_PITCH + c * 16, g + (size_t)row * N + c * 8);
        }
    }
}

__global__ __launch_bounds__(256, 2)
void gemm_f16(const __half* __restrict__ Ah, const __half* __restrict__ Al,
              const __half* __restrict__ Bmh, const __half* __restrict__ Bml,
              const float* __restrict__ bias, float* __restrict__ C,
              int M, int N, int K)
{
    extern __shared__ __align__(16) char smem[];
    const uint32_t sm0 = smem_u32(smem);

    const int tid  = threadIdx.x;
    const int wid  = tid >> 5;
    const int lane = tid & 31;
    const int n0 = blockIdx.x * 128;
    const int m0 = blockIdx.y * 128;
    const int b  = blockIdx.z;

    const int wm = (wid >> 1) * 32;
    const int wn = (wid & 1) * 64;

    const __half* gA_h = Ah + (size_t)m0 * K;
    const __half* gA_l = Al + (size_t)m0 * K;
    const __half* gB_h = Bmh + (size_t)b * K * N + n0;
    const __half* gB_l = Bml + (size_t)b * K * N + n0;

    float acc[2][8][4];
#pragma unroll
    for (int t = 0; t < 2; t++)
#pragma unroll
        for (int nt = 0; nt < 8; nt++)
#pragma unroll
            for (int i = 0; i < 4; i++) acc[t][nt][i] = 0.f;

    const int nk = K / 32;

    stage_load(sm0, gA_h, gA_l, gB_h, gB_l, K, N, 0, tid);
    CP_COMMIT();
    if (nk > 1) {
        stage_load(sm0 + STG2, gA_h, gA_l, gB_h, gB_l, K, N, 1, tid);
        CP_COMMIT();
    }

    const int a_row = lane & 15;
    const int a_hi  = (lane >> 4) * 16;
    const int b_kr = (lane & 7) + ((lane >> 3) & 1) * 8;
    const int b_nc = (lane >> 4) * 8;

    for (int kc = 0; kc < nk; kc++) {
        if (kc + 2 < nk) {
            stage_load(sm0 + ((kc + 2) % 3) * STG2,
                       gA_h, gA_l, gB_h, gB_l, K, N, kc + 2, tid);
            CP_COMMIT();
        }
        if (kc + 2 < nk)      CP_WAIT(2);
        else if (kc + 1 < nk) CP_WAIT(1);
        else                  CP_WAIT(0);
        __syncthreads();

        const uint32_t sb  = sm0 + (kc % 3) * STG2;
        const uint32_t aAh = sb;
        const uint32_t aAl = sb + OFF_AL;
        const uint32_t aBh = sb + OFF_BH;
        const uint32_t aBl = sb + OFF_BL;

#pragma unroll
        for (int j = 0; j < 2; j++) {
            uint32_t ah[2][4], al[2][4];
#pragma unroll
            for (int t = 0; t < 2; t++) {
                uint32_t off = (uint32_t)(wm + t * 16 + a_row) * A_PITCH + j * 32 + a_hi;
                ldsm4(aAh + off, ah[t]);
                ldsm4(aAl + off, al[t]);
            }
            uint32_t bh[4][4], bl[4][4];
#pragma unroll
            for (int p = 0; p < 4; p++) {
                uint32_t off = (uint32_t)(j * 16 + b_kr) * B_PITCH +
                               (uint32_t)(wn + p * 16 + b_nc) * 2;
                ldsm4t(aBh + off, bh[p]);
                ldsm4t(aBl + off, bl[p]);
            }
#pragma unroll
            for (int t = 0; t < 2; t++)
#pragma unroll
                for (int nt = 0; nt < 8; nt++) {
                    const uint32_t* bhp = &bh[nt >> 1][(nt & 1) * 2];
                    const uint32_t* blp = &bl[nt >> 1][(nt & 1) * 2];
                    mma_f16(acc[t][nt], ah[t], bhp);
                    mma_f16(acc[t][nt], ah[t], blp);
                    mma_f16(acc[t][nt], al[t], bhp);
                }
        }
        __syncthreads();
    }

    const int l4 = lane >> 2;
    const int l2 = (lane & 3) * 2;
#pragma unroll
    for (int t = 0; t < 2; t++) {
        const int m_lo = m0 + wm + t * 16 + l4;
        const float bi_lo = bias[m_lo];
        const float bi_hi = bias[m_lo + 8];
        float* c_lo = C + ((size_t)b * M + m_lo) * N + n0 + wn + l2;
        float* c_hi = c_lo + (size_t)8 * N;
#pragma unroll
        for (int nt = 0; nt < 8; nt++) {
            float2 v0 = {acc[t][nt][0] + bi_lo, acc[t][nt][1] + bi_lo};
            float2 v1 = {acc[t][nt][2] + bi_hi, acc[t][nt][3] + bi_hi};
            *(float2*)(c_lo + nt * 8) = v0;
            *(float2*)(c_hi + nt * 8) = v1;
        }
    }
}

// ---------------------------------------------------------------------------
// 2-product GEMM (proj): C[b] = (Ah+Al)(M,K) @ Bh(b,K,N) + bias, 3-stage.
// ---------------------------------------------------------------------------
#define P2_AL   10240
#define P2_BH   20480
#define P2_STG  29184

__device__ __forceinline__ void stage_load_2p(
    uint32_t sbase, const __half* gA_h, const __half* gA_l,
    const __half* gB_h, int K, int N, int kc, int tid)
{
    if (tid < 128) {
        const int op = tid >> 6;
        const int t  = tid & 63;
        const __half* g = ((op == 0) ? gA_h : gA_l) + kc * 32;
        const uint32_t sb = sbase + op * P2_AL;
#pragma unroll
        for (int it = 0; it < 8; it++) {
            int chunk = t + it * 64;
            int row = chunk >> 2, c = chunk & 3;
            CP_ASYNC16(sb + row * A_PITCH + c * 16, g + (size_t)row * K + c * 8);
        }
    } else {
        const int t = tid - 128;
        const __half* g = gB_h + (size_t)kc * 32 * N;
        const uint32_t sb = sbase + P2_BH;
#pragma unroll
        for (int it = 0; it < 4; it++) {
            int chunk = t + it * 128;
            int row = chunk >> 4, c = chunk & 15;
            CP_ASYNC16(sb + row * B_PITCH + c * 16, g + (size_t)row * N + c * 8);
        }
    }
}

__global__ __launch_bounds__(256, 2)
void gemm_f16_2p(const __half* __restrict__ Ah, const __half* __restrict__ Al,
                 const __half* __restrict__ Bmh,
                 const float* __restrict__ bias, float* __restrict__ C,
                 int M, int N, int K)
{
    extern __shared__ __align__(16) char smem[];
    const uint32_t sm0 = smem_u32(smem);

    const int tid  = threadIdx.x;
    const int wid  = tid >> 5;
    const int lane = tid & 31;
    const int n0 = blockIdx.x * 128;
    const int m0 = blockIdx.y * 128;
    const int b  = blockIdx.z;

    const int wm = (wid >> 1) * 32;
    const int wn = (wid & 1) * 64;

    const __half* gA_h = Ah + (size_t)m0 * K;
    const __half* gA_l = Al + (size_t)m0 * K;
    const __half* gB_h = Bmh + (size_t)b * K * N + n0;

    float acc[2][8][4];
#pragma unroll
    for (int t = 0; t < 2; t++)
#pragma unroll
        for (int nt = 0; nt < 8; nt++)
#pragma unroll
            for (int i = 0; i < 4; i++) acc[t][nt][i] = 0.f;

    const int nk = K / 32;

    stage_load_2p(sm0, gA_h, gA_l, gB_h, K, N, 0, tid);
    CP_COMMIT();
    if (nk > 1) {
        stage_load_2p(sm0 + P2_STG, gA_h, gA_l, gB_h, K, N, 1, tid);
        CP_COMMIT();
    }

    const int a_row = lane & 15;
    const int a_hi  = (lane >> 4) * 16;
    const int b_kr = (lane & 7) + ((lane >> 3) & 1) * 8;
    const int b_nc = (lane >> 4) * 8;

    for (int kc = 0; kc < nk; kc++) {
        if (kc + 2 < nk) {
            stage_load_2p(sm0 + ((kc + 2) % 3) * P2_STG,
                          gA_h, gA_l, gB_h, K, N, kc + 2, tid);
            CP_COMMIT();
        }
        if (kc + 2 < nk)      CP_WAIT(2);
        else if (kc + 1 < nk) CP_WAIT(1);
        else                  CP_WAIT(0);
        __syncthreads();

        const uint32_t sb  = sm0 + (kc % 3) * P2_STG;
        const uint32_t aAh = sb;
        const uint32_t aAl = sb + P2_AL;
        const uint32_t aBh = sb + P2_BH;

#pragma unroll
        for (int j = 0; j < 2; j++) {
            uint32_t ah[2][4], al[2][4];
#pragma unroll
            for (int t = 0; t < 2; t++) {
                uint32_t off = (uint32_t)(wm + t * 16 + a_row) * A_PITCH + j * 32 + a_hi;
                ldsm4(aAh + off, ah[t]);
                ldsm4(aAl + off, al[t]);
            }
            uint32_t bh[4][4];
#pragma unroll
            for (int p = 0; p < 4; p++) {
                uint32_t off = (uint32_t)(j * 16 + b_kr) * B_PITCH +
                               (uint32_t)(wn + p * 16 + b_nc) * 2;
                ldsm4t(aBh + off, bh[p]);
            }
#pragma unroll
            for (int t = 0; t < 2; t++)
#pragma unroll
                for (int nt = 0; nt < 8; nt++) {
                    const uint32_t* bhp = &bh[nt >> 1][(nt & 1) * 2];
                    mma_f16(acc[t][nt], ah[t], bhp);
                    mma_f16(acc[t][nt], al[t], bhp);
                }
        }
        __syncthreads();
    }

    const int l4 = lane >> 2;
    const int l2 = (lane & 3) * 2;
#pragma unroll
    for (int t = 0; t < 2; t++) {
        const int m_lo = m0 + wm + t * 16 + l4;
        const float bi_lo = bias[m_lo];
        const float bi_hi = bias[m_lo + 8];
        float* c_lo = C + ((size_t)b * M + m_lo) * N + n0 + wn + l2;
        float* c_hi = c_lo + (size_t)8 * N;
#pragma unroll
        for (int nt = 0; nt < 8; nt++) {
            float2 v0 = {acc[t][nt][0] + bi_lo, acc[t][nt][1] + bi_lo};
            float2 v1 = {acc[t][nt][2] + bi_hi, acc[t][nt][3] + bi_hi};
            *(float2*)(c_lo + nt * 8) = v0;
            *(float2*)(c_hi + nt * 8) = v1;
        }
    }
}

// ---------------------------------------------------------------------------
__global__ void wsplit_kernel(const float* __restrict__ w,
                              __half* __restrict__ hi,
                              __half* __restrict__ lo, int n)
{
    int i = blockIdx.x * 256 + threadIdx.x;
    if (i < n) {
        float v = w[i];
        __half h = __float2half_rn(v);
        hi[i] = h;
        lo[i] = __float2half_rn(v - __half2float(h));
    }
}

// ---------------------------------------------------------------------------
// dwpw: phase A (channel x 8px) + fused qkv-head vk + register-tiled
// pointwise + s3/s5 vk.  (unchanged from R8)
// ---------------------------------------------------------------------------
#define OFF_SIN   0
#define OFF_D3    17408
#define OFF_D5    41984
#define OFF_W5P   66560
#define OFF_W3P   71360
#define OFF_PWP   73088
#define OFF_PWB   82304
#define OFF_DB5   82688
#define OFF_DB3   82880
#define OFF_STASH 83072
#define DW_SMEM   91264

__global__ __launch_bounds__(256, 2)
void dwpw_kernel(const float* __restrict__ qkv,
                 const float* __restrict__ dw3_w, const float* __restrict__ dw3_b,
                 const float* __restrict__ pw3_w, const float* __restrict__ pw3_b,
                 const float* __restrict__ dw5_w, const float* __restrict__ dw5_b,
                 const float* __restrict__ pw5_w, const float* __restrict__ pw5_b,
                 float* __restrict__ s3q, float* __restrict__ s5q,
                 float* __restrict__ vkg)
{
    extern __shared__ __align__(16) char sm[];
    float* sin_  = (float*)(sm + OFF_SIN);
    float* d3s   = (float*)(sm + OFF_D3);
    float* d5s   = (float*)(sm + OFF_D5);
    ull*   kvq   = (ull*)(sm + OFF_D3);
    float* red   = (float*)(sm + OFF_PWP);
    float* stash = (float*)(sm + OFF_STASH);
    ull*   w5p   = (ull*)(sm + OFF_W5P);
    ull*   w3p   = (ull*)(sm + OFF_W3P);
    ull*   pwp   = (ull*)(sm + OFF_PWP);
    ull*   pwb   = (ull*)(sm + OFF_PWB);
    ull*   db5   = (ull*)(sm + OFF_DB5);
    ull*   db3   = (ull*)(sm + OFF_DB3);

    const int ytile = blockIdx.x;
    const int g     = blockIdx.y;
    const int b     = blockIdx.z;
    const int tid   = threadIdx.x;
    const int y0    = ytile * 4;

    for (int i = tid; i < 600; i += 256) {
        float w = dw5_w[(g * 24 + i / 25) * 25 + i % 25];
        w5p[i] = pk2(w, w);
    }
    for (int i = tid; i < 216; i += 256) {
        float w = dw3_w[(g * 24 + i / 9) * 9 + i % 9];
        w3p[i] = pk2(w, w);
    }
    for (int i = tid; i < 576; i += 256) {
        float a = pw3_w[g * 576 + i];
        float c = pw5_w[g * 576 + i];
        pwp[i] = pk2(a, a);
        pwp[576 + i] = pk2(c, c);
    }
    if (tid < 24) {
        float b3 = pw3_b[g * 24 + tid], b5 = pw5_b[g * 24 + tid];
        pwb[tid] = pk2(b3, b3);
        pwb[24 + tid] = pk2(b5, b5);
        float d3b = dw3_b[g * 24 + tid], d5b = dw5_b[g * 24 + tid];
        db3[tid] = pk2(d3b, d3b);
        db5[tid] = pk2(d5b, d5b);
    }

    const int c  = tid >> 5;
    const int t  = tid & 31;
    const int py = t >> 3;
    const int xo = (t & 7) * 8;

    for (int grp = 0; grp < 3; grp++) {
        __syncthreads();
        const int icb = grp * 8;
        const float* src = qkv + ((size_t)b * C3 + g * 24 + icb) * NPIX;
        for (int i = tid; i < 8 * 8 * 68; i += 256) {
            int xx = i % 68;
            int r  = (i / 68) & 7;
            int cc = i / (68 * 8);
            int yy = y0 - 2 + r;
            int xg = xx - 2;
            float v = 0.f;
            if ((unsigned)yy < 64u && (unsigned)xg < 64u)
                v = src[(size_t)cc * NPIX + yy * WIDTH + xg];
            sin_[(cc * 8 + r) * 68 + xx] = v;
        }
        __syncthreads();

        const int ch = icb + c;
        ull acc5[4], acc3[4];
        {
            ull b5v = db5[ch], b3v = db3[ch];
#pragma unroll
            for (int j = 0; j < 4; j++) { acc5[j] = b5v; acc3[j] = b3v; }
        }
#pragma unroll
        for (int dy = 0; dy < 5; dy++) {
            const ull* row = (const ull*)&sin_[(c * 8 + py + dy) * 68 + xo];
            ull r0 = row[0], r1 = row[1], r2 = row[2],
                r3 = row[3], r4 = row[4], r5 = row[5];
            ull m0 = pk2(f2hi(r0), f2lo(r1));
            ull m1 = pk2(f2hi(r1), f2lo(r2));
            ull m2 = pk2(f2hi(r2), f2lo(r3));
            ull m3 = pk2(f2hi(r3), f2lo(r4));
            ull m4 = pk2(f2hi(r4), f2lo(r5));
            const ull* w5r = &w5p[ch * 25 + dy * 5];
            ull w0 = w5r[0], w1 = w5r[1], w2 = w5r[2], w3v = w5r[3], w4 = w5r[4];

            ffma2(acc5[0], w0, r0); ffma2(acc5[0], w1, m0); ffma2(acc5[0], w2, r1);
            ffma2(acc5[0], w3v, m1); ffma2(acc5[0], w4, r2);
            ffma2(acc5[1], w0, r1); ffma2(acc5[1], w1, m1); ffma2(acc5[1], w2, r2);
            ffma2(acc5[1], w3v, m2); ffma2(acc5[1], w4, r3);
            ffma2(acc5[2], w0, r2); ffma2(acc5[2], w1, m2); ffma2(acc5[2], w2, r3);
            ffma2(acc5[2], w3v, m3); ffma2(acc5[2], w4, r4);
            ffma2(acc5[3], w0, r3); ffma2(acc5[3], w1, m3); ffma2(acc5[3], w2, r4);
            ffma2(acc5[3], w3v, m4); ffma2(acc5[3], w4, r5);

            if (dy >= 1 && dy <= 3) {
                const ull* w3r = &w3p[ch * 9 + (dy - 1) * 3];
                ull u0 = w3r[0], u1 = w3r[1], u2 = w3r[2];
                ffma2(acc3[0], u0, m0); ffma2(acc3[0], u1, r1); ffma2(acc3[0], u2, m1);
                ffma2(acc3[1], u0, m1); ffma2(acc3[1], u1, r2); ffma2(acc3[1], u2, m2);
                ffma2(acc3[2], u0, m2); ffma2(acc3[2], u1, r3); ffma2(acc3[2], u2, m3);
                ffma2(acc3[3], u0, m3); ffma2(acc3[3], u1, r4); ffma2(acc3[3], u2, m4);
            }
        }
        const int ppb = py * 32 + (xo >> 1);
#pragma unroll
        for (int j = 0; j < 4; j++) {
            *(ull*)&d3s[ch * 256 + (ppb + j) * 2] = acc3[j];
            *(ull*)&d5s[ch * 256 + (ppb + j) * 2] = acc5[j];
        }

        if (grp == 1) {
            for (int i = tid; i < 8 * 256; i += 256) {
                int cc = i >> 8, px = i & 255;
                stash[i] = sin_[(cc * 8 + 2 + (px >> 6)) * 68 + 2 + (px & 63)];
            }
        }

        if (grp == 2) {
            const int px = tid;
            const int vy = px >> 6;
            const int vx = px & 63;
            float kk[8], vv[8];
#pragma unroll
            for (int e = 0; e < 8; e++)
                kk[e] = fmaxf(stash[e * 256 + px], 0.f);
#pragma unroll
            for (int d = 0; d < 8; d++)
                vv[d] = sin_[(d * 8 + 2 + vy) * 68 + 2 + vx];

            float vacc[9][8];
#pragma unroll
            for (int d = 0; d < 8; d++)
#pragma unroll
                for (int e = 0; e < 8; e++)
                    vacc[d][e] = vv[d] * kk[e];
#pragma unroll
            for (int e = 0; e < 8; e++) vacc[8][e] = kk[e];

#pragma unroll
            for (int d = 0; d < 9; d++)
#pragma unroll
                for (int e = 0; e < 8; e++) {
                    float v = vacc[d][e];
                    v += __shfl_xor_sync(0xffffffffu, v, 16);
                    v += __shfl_xor_sync(0xffffffffu, v, 8);
                    v += __shfl_xor_sync(0xffffffffu, v, 4);
                    v += __shfl_xor_sync(0xffffffffu, v, 2);
                    v += __shfl_xor_sync(0xffffffffu, v, 1);
                    vacc[d][e] = v;
                }
            __syncthreads();
            const int w    = tid >> 5;
            const int lane = tid & 31;
            if (lane == 0) {
#pragma unroll
                for (int d = 0; d < 9; d++)
#pragma unroll
                    for (int e = 0; e < 8; e++)
                        stash[w * 72 + d * 8 + e] = vacc[d][e];
            }
            __syncthreads();
            if (tid < 72) {
                float s = 0.f;
#pragma unroll
                for (int j = 0; j < 8; j++) s += stash[j * 72 + tid];
                atomicAdd(&vkg[((size_t)b * 96 + g) * 72 + tid], s);
            }
        }
    }
    __syncthreads();

    const int conv = tid >> 7;
    const int tt   = tid & 127;
    const int og   = tt >> 5;
    const int pg   = tt & 31;
    const float* dsrc = conv ? d5s : d3s;
    const ull* wp = &pwp[conv * 576];
    const ull* bb = &pwb[conv * 24];
    float* qout = conv ? s5q : s3q;

    ull acc[6][4];
#pragma unroll
    for (int j = 0; j < 6; j++) {
        ull bv = bb[og * 6 + j];
#pragma unroll
        for (int i = 0; i < 4; i++) acc[j][i] = bv;
    }

#pragma unroll
    for (int ic = 0; ic < 24; ic++) {
        const ulonglong2 dA = *(const ulonglong2*)&dsrc[ic * 256 + pg * 8];
        const ulonglong2 dB = *(const ulonglong2*)&dsrc[ic * 256 + pg * 8 + 4];
        ull dv[4] = {dA.x, dA.y, dB.x, dB.y};
#pragma unroll
        for (int j = 0; j < 6; j++) {
            ull wv = wp[(og * 6 + j) * 24 + ic];
#pragma unroll
            for (int i = 0; i < 4; i++)
                ffma2(acc[j][i], wv, dv[i]);
        }
    }
    __syncthreads();

    {
        const int pair0 = pg * 4;
        const int by = y0 + (pair0 >> 5);
        const int bx = (pair0 & 31) * 2;
        const size_t qbase = (((size_t)b * 32 + g) * 8) * NPIX + by * WIDTH + bx;
#pragma unroll
        for (int j = 0; j < 6; j++) {
            const int o = og * 6 + j;
            if (o < 8) {
#pragma unroll
                for (int i = 0; i < 4; i++)
                    *(float2*)&qout[qbase + (size_t)o * NPIX + i * 2] =
                        make_float2(f2lo(acc[j][i]), f2hi(acc[j][i]));
            } else {
#pragma unroll
                for (int i = 0; i < 4; i++)
                    kvq[(conv * 16 + (o - 8)) * 128 + pair0 + i] = acc[j][i];
            }
        }
    }
    __syncthreads();

    {
        const int w    = tid >> 5;
        const int lane = tid & 31;
        const int cv   = w >> 2;
        const int sub  = w & 3;
        const int pair = sub * 32 + lane;

        ull kvv[16];
#pragma unroll
        for (int ch = 0; ch < 16; ch++)
            kvv[ch] = kvq[(cv * 16 + ch) * 128 + pair];

        float acc2[9][8];
#pragma unroll
        for (int d = 0; d < 9; d++)
#pragma unroll
            for (int e = 0; e < 8; e++) acc2[d][e] = 0.f;

#pragma unroll
        for (int hx = 0; hx < 2; hx++) {
            float kk[8], vv[8];
#pragma unroll
            for (int e = 0; e < 8; e++)
                kk[e] = fmaxf(hx ? f2hi(kvv[e]) : f2lo(kvv[e]), 0.f);
#pragma unroll
            for (int d = 0; d < 8; d++)
                vv[d] = hx ? f2hi(kvv[8 + d]) : f2lo(kvv[8 + d]);
#pragma unroll
            for (int d = 0; d < 8; d++)
#pragma unroll
                for (int e = 0; e < 8; e++)
                    acc2[d][e] += vv[d] * kk[e];
#pragma unroll
            for (int e = 0; e < 8; e++)
                acc2[8][e] += kk[e];
        }

#pragma unroll
        for (int d = 0; d < 9; d++)
#pragma unroll
            for (int e = 0; e < 8; e++) {
                float v = acc2[d][e];
                v += __shfl_xor_sync(0xffffffffu, v, 16);
                v += __shfl_xor_sync(0xffffffffu, v, 8);
                v += __shfl_xor_sync(0xffffffffu, v, 4);
                acc2[d][e] = v;
            }
        if (lane < 4) {
            float* rp = &red[((cv * 16) + sub * 4 + lane) * 72];
#pragma unroll
            for (int d = 0; d < 9; d++)
#pragma unroll
                for (int e = 0; e < 8; e++)
                    rp[d * 8 + e] = acc2[d][e];
        }
    }
    __syncthreads();

    if (tid < 144) {
        const int cv  = tid / 72;
        const int idx = tid % 72;
        float s = 0.f;
#pragma unroll
        for (int j = 0; j < 16; j++)
            s += red[(cv * 16 + j) * 72 + idx];
        atomicAdd(&vkg[((size_t)b * 96 + 32 + cv * 32 + g) * 72 + idx], s);
    }
}

// ---------------------------------------------------------------------------
// attention normalize: 4 CTAs/SM, packed f32x2, z-split.  (unchanged R8)
// ---------------------------------------------------------------------------
__global__ __launch_bounds__(256, 4)
void att_kernel(const float* __restrict__ qkv, const float* __restrict__ s3q,
                const float* __restrict__ s5q, const float* __restrict__ vk,
                __half* __restrict__ atth)
{
    const int hh = blockIdx.x;
    const int b  = blockIdx.y;
    const int n0 = blockIdx.z * (NPIX / 4);
    const int src_id = hh >> 5;
    const int g      = hh & 31;
    const float* base;
    if (src_id == 0)      base = qkv + ((size_t)b * C3 + g * 24) * NPIX;
    else if (src_id == 1) base = s3q + (((size_t)b * 32 + g) * 8) * NPIX;
    else                  base = s5q + (((size_t)b * 32 + g) * 8) * NPIX;

    __shared__ ull vsp[72];
    const int tid = threadIdx.x;
    if (tid < 72) {
        float v = vk[((size_t)b * 96 + hh) * 72 + tid];
        vsp[tid] = pk2(v, v);
    }
    __syncthreads();

    __half* oh = atth + ((size_t)b * C3 + hh * 8) * NPIX;

#pragma unroll
    for (int it = 0; it < 2; it++) {
        const int n = n0 + (tid + it * 256) * 2;
        ull qp[8];
#pragma unroll
        for (int e = 0; e < 8; e++) {
            ull raw = *(const ull*)(base + (size_t)e * NPIX + n);
            qp[e] = pk2(fmaxf(f2lo(raw), 0.f), fmaxf(f2hi(raw), 0.f));
        }
        ull den = pk2(1e-15f, 1e-15f);
#pragma unroll
        for (int e = 0; e < 8; e++) ffma2(den, vsp[64 + e], qp[e]);
        const float rd0 = __fdividef(1.f, f2lo(den));
        const float rd1 = __fdividef(1.f, f2hi(den));
#pragma unroll
        for (int d = 0; d < 8; d++) {
            ull num = 0ull;
#pragma unroll
            for (int e = 0; e < 8; e++) ffma2(num, vsp[d * 8 + e], qp[e]);
            __half2 hp;
            hp.x = __float2half_rn(f2lo(num) * rd0);
            hp.y = __float2half_rn(f2hi(num) * rd1);
            *(__half2*)(oh + (size_t)d * NPIX + n) = hp;
        }
    }
}

// ---------------------------------------------------------------------------
struct HalfArgs {
    const float *x, *qkv_b, *dw3_w, *dw3_b, *pw3_w, *pw3_b;
    const float *dw5_w, *dw5_b, *pw5_w, *pw5_b, *proj_b;
    __half *xth, *xtl, *ath, *wqh, *wql, *wph, *wpl;
    float *qkv, *s3q, *s5q, *vkb, *out;
};

static void enqueue_half(cudaStream_t st, const HalfArgs& a, int b0)
{
    const int HB = BATCH / 2;   // 4 batches per half
    const size_t offX = (size_t)b0 * 256 * NPIX;
    const size_t offQ = (size_t)b0 * C3 * NPIX;
    const size_t off3 = (size_t)b0 * 32 * 8 * NPIX;
    const size_t offV = (size_t)b0 * 96 * 72;

    // x split for this half
    wsplit_kernel<<<(HB * 256 * NPIX + 255) / 256, 256, 0, st>>>(
        a.x + offX, a.xth + offX, a.xtl + offX, HB * 256 * NPIX);

    // qkv GEMM (3-product, 3-stage)
    gemm_f16<<<dim3(NPIX / 128, C3 / 128, HB), 256, 3 * STG2, st>>>(
        a.wqh, a.wql, a.xth + offX, a.xtl + offX, a.qkv_b, a.qkv + offQ,
        C3, NPIX, 256);

    // zero vk accumulators for this half
    cudaMemsetAsync(a.vkb + offV, 0, (size_t)HB * 96 * 72 * sizeof(float), st);

    // fused dwpw
    dwpw_kernel<<<dim3(16, 32, HB), 256, DW_SMEM, st>>>(
        a.qkv + offQ, a.dw3_w, a.dw3_b, a.pw3_w, a.pw3_b,
        a.dw5_w, a.dw5_b, a.pw5_w, a.pw5_b,
        a.s3q + off3, a.s5q + off3, a.vkb + offV);

    // attention normalize
    att_kernel<<<dim3(96, HB, 4), 256, 0, st>>>(
        a.qkv + offQ, a.s3q + off3, a.s5q + off3, a.vkb + offV, a.ath + offQ);

    // proj GEMM (2-product, 3-stage)
    gemm_f16_2p<<<dim3(NPIX / 128, 256 / 128, HB), 256, 3 * P2_STG, st>>>(
        a.wph, a.wpl, a.ath + offQ, a.proj_b, a.out + (size_t)b0 * 256 * NPIX,
        256, NPIX, C3);
}

extern "C" void kernel_launch(void* const* d_in, const int* in_sizes, int n_in,
                              void* d_out, int out_size)
{
    HalfArgs a;
    a.x      = (const float*)d_in[0];
    const float* qkv_w = (const float*)d_in[1];
    a.qkv_b  = (const float*)d_in[2];
    a.dw3_w  = (const float*)d_in[3];
    a.dw3_b  = (const float*)d_in[4];
    a.pw3_w  = (const float*)d_in[5];
    a.pw3_b  = (const float*)d_in[6];
    a.dw5_w  = (const float*)d_in[7];
    a.dw5_b  = (const float*)d_in[8];
    a.pw5_w  = (const float*)d_in[9];
    a.pw5_b  = (const float*)d_in[10];
    const float* proj_w = (const float*)d_in[11];
    a.proj_b = (const float*)d_in[12];
    a.out    = (float*)d_out;

    void *p;
    cudaGetSymbolAddress(&p, g_qkv);  a.qkv = (float*)p;
    cudaGetSymbolAddress(&p, g_s3q);  a.s3q = (float*)p;
    cudaGetSymbolAddress(&p, g_s5q);  a.s5q = (float*)p;
    cudaGetSymbolAddress(&p, g_vk);   a.vkb = (float*)p;
    cudaGetSymbolAddress(&p, g_xt_h); a.xth = (__half*)p;
    cudaGetSymbolAddress(&p, g_xt_l); a.xtl = (__half*)p;
    cudaGetSymbolAddress(&p, g_at_h); a.ath = (__half*)p;
    cudaGetSymbolAddress(&p, g_wq_h); a.wqh = (__half*)p;
    cudaGetSymbolAddress(&p, g_wq_l); a.wql = (__half*)p;
    cudaGetSymbolAddress(&p, g_wp_h); a.wph = (__half*)p;
    cudaGetSymbolAddress(&p, g_wp_l); a.wpl = (__half*)p;

    static bool inited = false;
    static cudaStream_t s1;
    static cudaEvent_t evW, evD;
    if (!inited) {
        cudaStreamCreateWithFlags(&s1, cudaStreamNonBlocking);
        cudaEventCreateWithFlags(&evW, cudaEventDisableTiming);
        cudaEventCreateWithFlags(&evD, cudaEventDisableTiming);
        cudaFuncSetAttribute(gemm_f16,
            cudaFuncAttributeMaxDynamicSharedMemorySize, 3 * STG2);
        cudaFuncSetAttribute(gemm_f16_2p,
            cudaFuncAttributeMaxDynamicSharedMemorySize, 3 * P2_STG);
        cudaFuncSetAttribute(dwpw_kernel,
            cudaFuncAttributeMaxDynamicSharedMemorySize, DW_SMEM);
        inited = true;
    }

    // weight splits (shared by both halves) on the main stream
    wsplit_kernel<<<(C3 * 256 + 255) / 256, 256>>>(qkv_w, a.wqh, a.wql, C3 * 256);
    wsplit_kernel<<<(256 * C3 + 255) / 256, 256>>>(proj_w, a.wph, a.wpl, 256 * C3);

    // fork: half 1 (b4-7) on s1, half 0 (b0-3) on the main stream
    cudaEventRecord(evW, 0);
    cudaStreamWaitEvent(s1, evW, 0);

    enqueue_half(0,  a, 0);
    enqueue_half(s1, a, BATCH / 2);

    // join
    cudaEventRecord(evD, s1);
    cudaStreamWaitEvent(0, evD, 0);
}

// round 10
// speedup vs baseline: 2.0691x; 1.0037x over previous
#include <cuda_runtime.h>
#include <cuda_fp16.h>
#include <cstdint>

// ---------------------------------------------------------------------------
// LiteMLA on sm_103a.
// Four-stream batch-split pipeline (2 batches each) to overlap stage tails.
// qkv GEMM: fp16 hi/lo x hi/lo, 3 mma products, 3-stage cp.async ring.
// proj GEMM: weights hi/lo x att fp16, 2 products, 3-stage ring.
// dwpw: depthwise f32x2 -> register-tiled pointwise -> fused vk (all heads).
// ---------------------------------------------------------------------------

#define BATCH 8
#define C3 768
#define NPIX 4096
#define WIDTH 64

__device__ float g_qkv[(size_t)BATCH * C3 * NPIX];
__device__ float g_s3q[(size_t)BATCH * 32 * 8 * NPIX];   // q channels only
__device__ float g_s5q[(size_t)BATCH * 32 * 8 * NPIX];
__device__ float g_vk [(size_t)BATCH * 96 * 72];

__device__ __half g_xt_h [(size_t)BATCH * 256 * NPIX];   // x split [b][k][n]
__device__ __half g_xt_l [(size_t)BATCH * 256 * NPIX];
__device__ __half g_at_h [(size_t)BATCH * C3 * NPIX];    // att fp16 [b][k][n]
__device__ __half g_wq_h [C3 * 256];
__device__ __half g_wq_l [C3 * 256];
__device__ __half g_wp_h [256 * C3];
__device__ __half g_wp_l [256 * C3];

// ---------------------------------------------------------------------------
typedef unsigned long long ull;

__device__ __forceinline__ uint32_t smem_u32(const void* p) {
    uint32_t a;
    asm("{ .reg .u64 t; cvta.to.shared.u64 t, %1; cvt.u32.u64 %0, t; }"
        : "=r"(a) : "l"(p));
    return a;
}
__device__ __forceinline__ ull pk2(float lo, float hi) {
    ull r;
    asm("mov.b64 %0, {%1, %2};" : "=l"(r)
        : "r"(__float_as_uint(lo)), "r"(__float_as_uint(hi)));
    return r;
}
__device__ __forceinline__ void ffma2(ull& d, ull a, ull b) {
    asm("fma.rn.f32x2 %0, %1, %2, %0;" : "+l"(d) : "l"(a), "l"(b));
}
__device__ __forceinline__ float f2lo(ull v) {
    return __uint_as_float((unsigned)(v & 0xffffffffull));
}
__device__ __forceinline__ float f2hi(ull v) {
    return __uint_as_float((unsigned)(v >> 32));
}

#define CP_ASYNC16(s, g) \
    asm volatile("cp.async.cg.shared.global [%0], [%1], 16;" :: "r"(s), "l"(g))
#define CP_COMMIT() asm volatile("cp.async.commit_group;" ::: "memory")
#define CP_WAIT(n)  asm volatile("cp.async.wait_group %0;" :: "n"(n) : "memory")

__device__ __forceinline__ void ldsm4(uint32_t addr, uint32_t* r) {
    asm volatile("ldmatrix.sync.aligned.m8n8.x4.shared.b16 {%0,%1,%2,%3}, [%4];"
                 : "=r"(r[0]), "=r"(r[1]), "=r"(r[2]), "=r"(r[3]) : "r"(addr));
}
__device__ __forceinline__ void ldsm4t(uint32_t addr, uint32_t* r) {
    asm volatile("ldmatrix.sync.aligned.m8n8.x4.trans.shared.b16 {%0,%1,%2,%3}, [%4];"
                 : "=r"(r[0]), "=r"(r[1]), "=r"(r[2]), "=r"(r[3]) : "r"(addr));
}
__device__ __forceinline__ void mma_f16(float* d, const uint32_t* a,
                                        const uint32_t* b) {
    asm volatile(
        "mma.sync.aligned.m16n8k16.row.col.f32.f16.f16.f32 "
        "{%0,%1,%2,%3}, {%4,%5,%6,%7}, {%8,%9}, {%0,%1,%2,%3};"
        : "+f"(d[0]), "+f"(d[1]), "+f"(d[2]), "+f"(d[3])
        : "r"(a[0]), "r"(a[1]), "r"(a[2]), "r"(a[3]), "r"(b[0]), "r"(b[1]));
}

#define A_PITCH 80
#define B_PITCH 272

// ---------------------------------------------------------------------------
// 3-product GEMM (qkv): C[b] = (Ah+Al)(M,K) @ (Bh+Bl)(b,K,N) + bias
// 3-stage cp.async ring, 2 CTAs/SM.
// ---------------------------------------------------------------------------
#define OFF_AL  10240
#define OFF_BH  20480
#define OFF_BL  29184
#define STG2    37888

__device__ __forceinline__ void stage_load(
    uint32_t sbase, const __half* gA_h, const __half* gA_l,
    const __half* gB_h, const __half* gB_l, int K, int N, int kc, int tid)
{
    const int op = tid >> 6;
    const int t  = tid & 63;
    if (op < 2) {
        const __half* g = ((op == 0) ? gA_h : gA_l) + kc * 32;
        const uint32_t sb = sbase + op * OFF_AL;
#pragma unroll
        for (int it = 0; it < 8; it++) {
            int chunk = t + it * 64;
            int row = chunk >> 2, c = chunk & 3;
            CP_ASYNC16(sb + row * A_PITCH + c * 16, g + (size_t)row * K + c * 8);
        }
    } else {
        const __half* g = ((op == 2) ? gB_h : gB_l) + (size_t)kc * 32 * N;
        const uint32_t sb = sbase + ((op == 2) ? OFF_BH : OFF_BL);
#pragma unroll
        for (int it = 0; it < 8; it++) {
            int chunk = t + it * 64;
            int row = chunk >> 4, c = chunk & 15;
            CP_ASYNC16(sb + row * B_PITCH + c * 16, g + (size_t)row * N + c * 8);
        }
    }
}

__global__ __launch_bounds__(256, 2)
void gemm_f16(const __half* __restrict__ Ah, const __half* __restrict__ Al,
              const __half* __restrict__ Bmh, const __half* __restrict__ Bml,
              const float* __restrict__ bias, float* __restrict__ C,
              int M, int N, int K)
{
    extern __shared__ __align__(16) char smem[];
    const uint32_t sm0 = smem_u32(smem);

    const int tid  = threadIdx.x;
    const int wid  = tid >> 5;
    const int lane = tid & 31;
    const int n0 = blockIdx.x * 128;
    const int m0 = blockIdx.y * 128;
    const int b  = blockIdx.z;

    const int wm = (wid >> 1) * 32;
    const int wn = (wid & 1) * 64;

    const __half* gA_h = Ah + (size_t)m0 * K;
    const __half* gA_l = Al + (size_t)m0 * K;
    const __half* gB_h = Bmh + (size_t)b * K * N + n0;
    const __half* gB_l = Bml + (size_t)b * K * N + n0;

    float acc[2][8][4];
#pragma unroll
    for (int t = 0; t < 2; t++)
#pragma unroll
        for (int nt = 0; nt < 8; nt++)
#pragma unroll
            for (int i = 0; i < 4; i++) acc[t][nt][i] = 0.f;

    const int nk = K / 32;

    stage_load(sm0, gA_h, gA_l, gB_h, gB_l, K, N, 0, tid);
    CP_COMMIT();
    if (nk > 1) {
        stage_load(sm0 + STG2, gA_h, gA_l, gB_h, gB_l, K, N, 1, tid);
        CP_COMMIT();
    }

    const int a_row = lane & 15;
    const int a_hi  = (lane >> 4) * 16;
    const int b_kr = (lane & 7) + ((lane >> 3) & 1) * 8;
    const int b_nc = (lane >> 4) * 8;

    for (int kc = 0; kc < nk; kc++) {
        if (kc + 2 < nk) {
            stage_load(sm0 + ((kc + 2) % 3) * STG2,
                       gA_h, gA_l, gB_h, gB_l, K, N, kc + 2, tid);
            CP_COMMIT();
        }
        if (kc + 2 < nk)      CP_WAIT(2);
        else if (kc + 1 < nk) CP_WAIT(1);
        else                  CP_WAIT(0);
        __syncthreads();

        const uint32_t sb  = sm0 + (kc % 3) * STG2;
        const uint32_t aAh = sb;
        const uint32_t aAl = sb + OFF_AL;
        const uint32_t aBh = sb + OFF_BH;
        const uint32_t aBl = sb + OFF_BL;

#pragma unroll
        for (int j = 0; j < 2; j++) {
            uint32_t ah[2][4], al[2][4];
#pragma unroll
            for (int t = 0; t < 2; t++) {
                uint32_t off = (uint32_t)(wm + t * 16 + a_row) * A_PITCH + j * 32 + a_hi;
                ldsm4(aAh + off, ah[t]);
                ldsm4(aAl + off, al[t]);
            }
            uint32_t bh[4][4], bl[4][4];
#pragma unroll
            for (int p = 0; p < 4; p++) {
                uint32_t off = (uint32_t)(j * 16 + b_kr) * B_PITCH +
                               (uint32_t)(wn + p * 16 + b_nc) * 2;
                ldsm4t(aBh + off, bh[p]);
                ldsm4t(aBl + off, bl[p]);
            }
#pragma unroll
            for (int t = 0; t < 2; t++)
#pragma unroll
                for (int nt = 0; nt < 8; nt++) {
                    const uint32_t* bhp = &bh[nt >> 1][(nt & 1) * 2];
                    const uint32_t* blp = &bl[nt >> 1][(nt & 1) * 2];
                    mma_f16(acc[t][nt], ah[t], bhp);
                    mma_f16(acc[t][nt], ah[t], blp);
                    mma_f16(acc[t][nt], al[t], bhp);
                }
        }
        __syncthreads();
    }

    const int l4 = lane >> 2;
    const int l2 = (lane & 3) * 2;
#pragma unroll
    for (int t = 0; t < 2; t++) {
        const int m_lo = m0 + wm + t * 16 + l4;
        const float bi_lo = bias[m_lo];
        const float bi_hi = bias[m_lo + 8];
        float* c_lo = C + ((size_t)b * M + m_lo) * N + n0 + wn + l2;
        float* c_hi = c_lo + (size_t)8 * N;
#pragma unroll
        for (int nt = 0; nt < 8; nt++) {
            float2 v0 = {acc[t][nt][0] + bi_lo, acc[t][nt][1] + bi_lo};
            float2 v1 = {acc[t][nt][2] + bi_hi, acc[t][nt][3] + bi_hi};
            *(float2*)(c_lo + nt * 8) = v0;
            *(float2*)(c_hi + nt * 8) = v1;
        }
    }
}

// ---------------------------------------------------------------------------
// 2-product GEMM (proj): C[b] = (Ah+Al)(M,K) @ Bh(b,K,N) + bias, 3-stage.
// ---------------------------------------------------------------------------
#define P2_AL   10240
#define P2_BH   20480
#define P2_STG  29184

__device__ __forceinline__ void stage_load_2p(
    uint32_t sbase, const __half* gA_h, const __half* gA_l,
    const __half* gB_h, int K, int N, int kc, int tid)
{
    if (tid < 128) {
        const int op = tid >> 6;
        const int t  = tid & 63;
        const __half* g = ((op == 0) ? gA_h : gA_l) + kc * 32;
        const uint32_t sb = sbase + op * P2_AL;
#pragma unroll
        for (int it = 0; it < 8; it++) {
            int chunk = t + it * 64;
            int row = chunk >> 2, c = chunk & 3;
            CP_ASYNC16(sb + row * A_PITCH + c * 16, g + (size_t)row * K + c * 8);
        }
    } else {
        const int t = tid - 128;
        const __half* g = gB_h + (size_t)kc * 32 * N;
        const uint32_t sb = sbase + P2_BH;
#pragma unroll
        for (int it = 0; it < 4; it++) {
            int chunk = t + it * 128;
            int row = chunk >> 4, c = chunk & 15;
            CP_ASYNC16(sb + row * B_PITCH + c * 16, g + (size_t)row * N + c * 8);
        }
    }
}

__global__ __launch_bounds__(256, 2)
void gemm_f16_2p(const __half* __restrict__ Ah, const __half* __restrict__ Al,
                 const __half* __restrict__ Bmh,
                 const float* __restrict__ bias, float* __restrict__ C,
                 int M, int N, int K)
{
    extern __shared__ __align__(16) char smem[];
    const uint32_t sm0 = smem_u32(smem);

    const int tid  = threadIdx.x;
    const int wid  = tid >> 5;
    const int lane = tid & 31;
    const int n0 = blockIdx.x * 128;
    const int m0 = blockIdx.y * 128;
    const int b  = blockIdx.z;

    const int wm = (wid >> 1) * 32;
    const int wn = (wid & 1) * 64;

    const __half* gA_h = Ah + (size_t)m0 * K;
    const __half* gA_l = Al + (size_t)m0 * K;
    const __half* gB_h = Bmh + (size_t)b * K * N + n0;

    float acc[2][8][4];
#pragma unroll
    for (int t = 0; t < 2; t++)
#pragma unroll
        for (int nt = 0; nt < 8; nt++)
#pragma unroll
            for (int i = 0; i < 4; i++) acc[t][nt][i] = 0.f;

    const int nk = K / 32;

    stage_load_2p(sm0, gA_h, gA_l, gB_h, K, N, 0, tid);
    CP_COMMIT();
    if (nk > 1) {
        stage_load_2p(sm0 + P2_STG, gA_h, gA_l, gB_h, K, N, 1, tid);
        CP_COMMIT();
    }

    const int a_row = lane & 15;
    const int a_hi  = (lane >> 4) * 16;
    const int b_kr = (lane & 7) + ((lane >> 3) & 1) * 8;
    const int b_nc = (lane >> 4) * 8;

    for (int kc = 0; kc < nk; kc++) {
        if (kc + 2 < nk) {
            stage_load_2p(sm0 + ((kc + 2) % 3) * P2_STG,
                          gA_h, gA_l, gB_h, K, N, kc + 2, tid);
            CP_COMMIT();
        }
        if (kc + 2 < nk)      CP_WAIT(2);
        else if (kc + 1 < nk) CP_WAIT(1);
        else                  CP_WAIT(0);
        __syncthreads();

        const uint32_t sb  = sm0 + (kc % 3) * P2_STG;
        const uint32_t aAh = sb;
        const uint32_t aAl = sb + P2_AL;
        const uint32_t aBh = sb + P2_BH;

#pragma unroll
        for (int j = 0; j < 2; j++) {
            uint32_t ah[2][4], al[2][4];
#pragma unroll
            for (int t = 0; t < 2; t++) {
                uint32_t off = (uint32_t)(wm + t * 16 + a_row) * A_PITCH + j * 32 + a_hi;
                ldsm4(aAh + off, ah[t]);
                ldsm4(aAl + off, al[t]);
            }
            uint32_t bh[4][4];
#pragma unroll
            for (int p = 0; p < 4; p++) {
                uint32_t off = (uint32_t)(j * 16 + b_kr) * B_PITCH +
                               (uint32_t)(wn + p * 16 + b_nc) * 2;
                ldsm4t(aBh + off, bh[p]);
            }
#pragma unroll
            for (int t = 0; t < 2; t++)
#pragma unroll
                for (int nt = 0; nt < 8; nt++) {
                    const uint32_t* bhp = &bh[nt >> 1][(nt & 1) * 2];
                    mma_f16(acc[t][nt], ah[t], bhp);
                    mma_f16(acc[t][nt], al[t], bhp);
                }
        }
        __syncthreads();
    }

    const int l4 = lane >> 2;
    const int l2 = (lane & 3) * 2;
#pragma unroll
    for (int t = 0; t < 2; t++) {
        const int m_lo = m0 + wm + t * 16 + l4;
        const float bi_lo = bias[m_lo];
        const float bi_hi = bias[m_lo + 8];
        float* c_lo = C + ((size_t)b * M + m_lo) * N + n0 + wn + l2;
        float* c_hi = c_lo + (size_t)8 * N;
#pragma unroll
        for (int nt = 0; nt < 8; nt++) {
            float2 v0 = {acc[t][nt][0] + bi_lo, acc[t][nt][1] + bi_lo};
            float2 v1 = {acc[t][nt][2] + bi_hi, acc[t][nt][3] + bi_hi};
            *(float2*)(c_lo + nt * 8) = v0;
            *(float2*)(c_hi + nt * 8) = v1;
        }
    }
}

// ---------------------------------------------------------------------------
__global__ void wsplit_kernel(const float* __restrict__ w,
                              __half* __restrict__ hi,
                              __half* __restrict__ lo, int n)
{
    int i = blockIdx.x * 256 + threadIdx.x;
    if (i < n) {
        float v = w[i];
        __half h = __float2half_rn(v);
        hi[i] = h;
        lo[i] = __float2half_rn(v - __half2float(h));
    }
}

// ---------------------------------------------------------------------------
// dwpw: phase A (channel x 8px) + fused qkv-head vk + register-tiled
// pointwise + s3/s5 vk.  (unchanged from R8/R9)
// ---------------------------------------------------------------------------
#define OFF_SIN   0
#define OFF_D3    17408
#define OFF_D5    41984
#define OFF_W5P   66560
#define OFF_W3P   71360
#define OFF_PWP   73088
#define OFF_PWB   82304
#define OFF_DB5   82688
#define OFF_DB3   82880
#define OFF_STASH 83072
#define DW_SMEM   91264

__global__ __launch_bounds__(256, 2)
void dwpw_kernel(const float* __restrict__ qkv,
                 const float* __restrict__ dw3_w, const float* __restrict__ dw3_b,
                 const float* __restrict__ pw3_w, const float* __restrict__ pw3_b,
                 const float* __restrict__ dw5_w, const float* __restrict__ dw5_b,
                 const float* __restrict__ pw5_w, const float* __restrict__ pw5_b,
                 float* __restrict__ s3q, float* __restrict__ s5q,
                 float* __restrict__ vkg)
{
    extern __shared__ __align__(16) char sm[];
    float* sin_  = (float*)(sm + OFF_SIN);
    float* d3s   = (float*)(sm + OFF_D3);
    float* d5s   = (float*)(sm + OFF_D5);
    ull*   kvq   = (ull*)(sm + OFF_D3);
    float* red   = (float*)(sm + OFF_PWP);
    float* stash = (float*)(sm + OFF_STASH);
    ull*   w5p   = (ull*)(sm + OFF_W5P);
    ull*   w3p   = (ull*)(sm + OFF_W3P);
    ull*   pwp   = (ull*)(sm + OFF_PWP);
    ull*   pwb   = (ull*)(sm + OFF_PWB);
    ull*   db5   = (ull*)(sm + OFF_DB5);
    ull*   db3   = (ull*)(sm + OFF_DB3);

    const int ytile = blockIdx.x;
    const int g     = blockIdx.y;
    const int b     = blockIdx.z;
    const int tid   = threadIdx.x;
    const int y0    = ytile * 4;

    for (int i = tid; i < 600; i += 256) {
        float w = dw5_w[(g * 24 + i / 25) * 25 + i % 25];
        w5p[i] = pk2(w, w);
    }
    for (int i = tid; i < 216; i += 256) {
        float w = dw3_w[(g * 24 + i / 9) * 9 + i % 9];
        w3p[i] = pk2(w, w);
    }
    for (int i = tid; i < 576; i += 256) {
        float a = pw3_w[g * 576 + i];
        float c = pw5_w[g * 576 + i];
        pwp[i] = pk2(a, a);
        pwp[576 + i] = pk2(c, c);
    }
    if (tid < 24) {
        float b3 = pw3_b[g * 24 + tid], b5 = pw5_b[g * 24 + tid];
        pwb[tid] = pk2(b3, b3);
        pwb[24 + tid] = pk2(b5, b5);
        float d3b = dw3_b[g * 24 + tid], d5b = dw5_b[g * 24 + tid];
        db3[tid] = pk2(d3b, d3b);
        db5[tid] = pk2(d5b, d5b);
    }

    const int c  = tid >> 5;
    const int t  = tid & 31;
    const int py = t >> 3;
    const int xo = (t & 7) * 8;

    for (int grp = 0; grp < 3; grp++) {
        __syncthreads();
        const int icb = grp * 8;
        const float* src = qkv + ((size_t)b * C3 + g * 24 + icb) * NPIX;
        for (int i = tid; i < 8 * 8 * 68; i += 256) {
            int xx = i % 68;
            int r  = (i / 68) & 7;
            int cc = i / (68 * 8);
            int yy = y0 - 2 + r;
            int xg = xx - 2;
            float v = 0.f;
            if ((unsigned)yy < 64u && (unsigned)xg < 64u)
                v = src[(size_t)cc * NPIX + yy * WIDTH + xg];
            sin_[(cc * 8 + r) * 68 + xx] = v;
        }
        __syncthreads();

        const int ch = icb + c;
        ull acc5[4], acc3[4];
        {
            ull b5v = db5[ch], b3v = db3[ch];
#pragma unroll
            for (int j = 0; j < 4; j++) { acc5[j] = b5v; acc3[j] = b3v; }
        }
#pragma unroll
        for (int dy = 0; dy < 5; dy++) {
            const ull* row = (const ull*)&sin_[(c * 8 + py + dy) * 68 + xo];
            ull r0 = row[0], r1 = row[1], r2 = row[2],
                r3 = row[3], r4 = row[4], r5 = row[5];
            ull m0 = pk2(f2hi(r0), f2lo(r1));
            ull m1 = pk2(f2hi(r1), f2lo(r2));
            ull m2 = pk2(f2hi(r2), f2lo(r3));
            ull m3 = pk2(f2hi(r3), f2lo(r4));
            ull m4 = pk2(f2hi(r4), f2lo(r5));
            const ull* w5r = &w5p[ch * 25 + dy * 5];
            ull w0 = w5r[0], w1 = w5r[1], w2 = w5r[2], w3v = w5r[3], w4 = w5r[4];

            ffma2(acc5[0], w0, r0); ffma2(acc5[0], w1, m0); ffma2(acc5[0], w2, r1);
            ffma2(acc5[0], w3v, m1); ffma2(acc5[0], w4, r2);
            ffma2(acc5[1], w0, r1); ffma2(acc5[1], w1, m1); ffma2(acc5[1], w2, r2);
            ffma2(acc5[1], w3v, m2); ffma2(acc5[1], w4, r3);
            ffma2(acc5[2], w0, r2); ffma2(acc5[2], w1, m2); ffma2(acc5[2], w2, r3);
            ffma2(acc5[2], w3v, m3); ffma2(acc5[2], w4, r4);
            ffma2(acc5[3], w0, r3); ffma2(acc5[3], w1, m3); ffma2(acc5[3], w2, r4);
            ffma2(acc5[3], w3v, m4); ffma2(acc5[3], w4, r5);

            if (dy >= 1 && dy <= 3) {
                const ull* w3r = &w3p[ch * 9 + (dy - 1) * 3];
                ull u0 = w3r[0], u1 = w3r[1], u2 = w3r[2];
                ffma2(acc3[0], u0, m0); ffma2(acc3[0], u1, r1); ffma2(acc3[0], u2, m1);
                ffma2(acc3[1], u0, m1); ffma2(acc3[1], u1, r2); ffma2(acc3[1], u2, m2);
                ffma2(acc3[2], u0, m2); ffma2(acc3[2], u1, r3); ffma2(acc3[2], u2, m3);
                ffma2(acc3[3], u0, m3); ffma2(acc3[3], u1, r4); ffma2(acc3[3], u2, m4);
            }
        }
        const int ppb = py * 32 + (xo >> 1);
#pragma unroll
        for (int j = 0; j < 4; j++) {
            *(ull*)&d3s[ch * 256 + (ppb + j) * 2] = acc3[j];
            *(ull*)&d5s[ch * 256 + (ppb + j) * 2] = acc5[j];
        }

        if (grp == 1) {
            for (int i = tid; i < 8 * 256; i += 256) {
                int cc = i >> 8, px = i & 255;
                stash[i] = sin_[(cc * 8 + 2 + (px >> 6)) * 68 + 2 + (px & 63)];
            }
        }

        if (grp == 2) {
            const int px = tid;
            const int vy = px >> 6;
            const int vx = px & 63;
            float kk[8], vv[8];
#pragma unroll
            for (int e = 0; e < 8; e++)
                kk[e] = fmaxf(stash[e * 256 + px], 0.f);
#pragma unroll
            for (int d = 0; d < 8; d++)
                vv[d] = sin_[(d * 8 + 2 + vy) * 68 + 2 + vx];

            float vacc[9][8];
#pragma unroll
            for (int d = 0; d < 8; d++)
#pragma unroll
                for (int e = 0; e < 8; e++)
                    vacc[d][e] = vv[d] * kk[e];
#pragma unroll
            for (int e = 0; e < 8; e++) vacc[8][e] = kk[e];

#pragma unroll
            for (int d = 0; d < 9; d++)
#pragma unroll
                for (int e = 0; e < 8; e++) {
                    float v = vacc[d][e];
                    v += __shfl_xor_sync(0xffffffffu, v, 16);
                    v += __shfl_xor_sync(0xffffffffu, v, 8);
                    v += __shfl_xor_sync(0xffffffffu, v, 4);
                    v += __shfl_xor_sync(0xffffffffu, v, 2);
                    v += __shfl_xor_sync(0xffffffffu, v, 1);
                    vacc[d][e] = v;
                }
            __syncthreads();
            const int w    = tid >> 5;
            const int lane = tid & 31;
            if (lane == 0) {
#pragma unroll
                for (int d = 0; d < 9; d++)
#pragma unroll
                    for (int e = 0; e < 8; e++)
                        stash[w * 72 + d * 8 + e] = vacc[d][e];
            }
            __syncthreads();
            if (tid < 72) {
                float s = 0.f;
#pragma unroll
                for (int j = 0; j < 8; j++) s += stash[j * 72 + tid];
                atomicAdd(&vkg[((size_t)b * 96 + g) * 72 + tid], s);
            }
        }
    }
    __syncthreads();

    const int conv = tid >> 7;
    const int tt   = tid & 127;
    const int og   = tt >> 5;
    const int pg   = tt & 31;
    const float* dsrc = conv ? d5s : d3s;
    const ull* wp = &pwp[conv * 576];
    const ull* bb = &pwb[conv * 24];
    float* qout = conv ? s5q : s3q;

    ull acc[6][4];
#pragma unroll
    for (int j = 0; j < 6; j++) {
        ull bv = bb[og * 6 + j];
#pragma unroll
        for (int i = 0; i < 4; i++) acc[j][i] = bv;
    }

#pragma unroll
    for (int ic = 0; ic < 24; ic++) {
        const ulonglong2 dA = *(const ulonglong2*)&dsrc[ic * 256 + pg * 8];
        const ulonglong2 dB = *(const ulonglong2*)&dsrc[ic * 256 + pg * 8 + 4];
        ull dv[4] = {dA.x, dA.y, dB.x, dB.y};
#pragma unroll
        for (int j = 0; j < 6; j++) {
            ull wv = wp[(og * 6 + j) * 24 + ic];
#pragma unroll
            for (int i = 0; i < 4; i++)
                ffma2(acc[j][i], wv, dv[i]);
        }
    }
    __syncthreads();

    {
        const int pair0 = pg * 4;
        const int by = y0 + (pair0 >> 5);
        const int bx = (pair0 & 31) * 2;
        const size_t qbase = (((size_t)b * 32 + g) * 8) * NPIX + by * WIDTH + bx;
#pragma unroll
        for (int j = 0; j < 6; j++) {
            const int o = og * 6 + j;
            if (o < 8) {
#pragma unroll
                for (int i = 0; i < 4; i++)
                    *(float2*)&qout[qbase + (size_t)o * NPIX + i * 2] =
                        make_float2(f2lo(acc[j][i]), f2hi(acc[j][i]));
            } else {
#pragma unroll
                for (int i = 0; i < 4; i++)
                    kvq[(conv * 16 + (o - 8)) * 128 + pair0 + i] = acc[j][i];
            }
        }
    }
    __syncthreads();

    {
        const int w    = tid >> 5;
        const int lane = tid & 31;
        const int cv   = w >> 2;
        const int sub  = w & 3;
        const int pair = sub * 32 + lane;

        ull kvv[16];
#pragma unroll
        for (int ch = 0; ch < 16; ch++)
            kvv[ch] = kvq[(cv * 16 + ch) * 128 + pair];

        float acc2[9][8];
#pragma unroll
        for (int d = 0; d < 9; d++)
#pragma unroll
            for (int e = 0; e < 8; e++) acc2[d][e] = 0.f;

#pragma unroll
        for (int hx = 0; hx < 2; hx++) {
            float kk[8], vv[8];
#pragma unroll
            for (int e = 0; e < 8; e++)
                kk[e] = fmaxf(hx ? f2hi(kvv[e]) : f2lo(kvv[e]), 0.f);
#pragma unroll
            for (int d = 0; d < 8; d++)
                vv[d] = hx ? f2hi(kvv[8 + d]) : f2lo(kvv[8 + d]);
#pragma unroll
            for (int d = 0; d < 8; d++)
#pragma unroll
                for (int e = 0; e < 8; e++)
                    acc2[d][e] += vv[d] * kk[e];
#pragma unroll
            for (int e = 0; e < 8; e++)
                acc2[8][e] += kk[e];
        }

#pragma unroll
        for (int d = 0; d < 9; d++)
#pragma unroll
            for (int e = 0; e < 8; e++) {
                float v = acc2[d][e];
                v += __shfl_xor_sync(0xffffffffu, v, 16);
                v += __shfl_xor_sync(0xffffffffu, v, 8);
                v += __shfl_xor_sync(0xffffffffu, v, 4);
                acc2[d][e] = v;
            }
        if (lane < 4) {
            float* rp = &red[((cv * 16) + sub * 4 + lane) * 72];
#pragma unroll
            for (int d = 0; d < 9; d++)
#pragma unroll
                for (int e = 0; e < 8; e++)
                    rp[d * 8 + e] = acc2[d][e];
        }
    }
    __syncthreads();

    if (tid < 144) {
        const int cv  = tid / 72;
        const int idx = tid % 72;
        float s = 0.f;
#pragma unroll
        for (int j = 0; j < 16; j++)
            s += red[(cv * 16 + j) * 72 + idx];
        atomicAdd(&vkg[((size_t)b * 96 + 32 + cv * 32 + g) * 72 + idx], s);
    }
}

// ---------------------------------------------------------------------------
// attention normalize: 4 CTAs/SM, packed f32x2, z-split.  (unchanged)
// ---------------------------------------------------------------------------
__global__ __launch_bounds__(256, 4)
void att_kernel(const float* __restrict__ qkv, const float* __restrict__ s3q,
                const float* __restrict__ s5q, const float* __restrict__ vk,
                __half* __restrict__ atth)
{
    const int hh = blockIdx.x;
    const int b  = blockIdx.y;
    const int n0 = blockIdx.z * (NPIX / 4);
    const int src_id = hh >> 5;
    const int g      = hh & 31;
    const float* base;
    if (src_id == 0)      base = qkv + ((size_t)b * C3 + g * 24) * NPIX;
    else if (src_id == 1) base = s3q + (((size_t)b * 32 + g) * 8) * NPIX;
    else                  base = s5q + (((size_t)b * 32 + g) * 8) * NPIX;

    __shared__ ull vsp[72];
    const int tid = threadIdx.x;
    if (tid < 72) {
        float v = vk[((size_t)b * 96 + hh) * 72 + tid];
        vsp[tid] = pk2(v, v);
    }
    __syncthreads();

    __half* oh = atth + ((size_t)b * C3 + hh * 8) * NPIX;

#pragma unroll
    for (int it = 0; it < 2; it++) {
        const int n = n0 + (tid + it * 256) * 2;
        ull qp[8];
#pragma unroll
        for (int e = 0; e < 8; e++) {
            ull raw = *(const ull*)(base + (size_t)e * NPIX + n);
            qp[e] = pk2(fmaxf(f2lo(raw), 0.f), fmaxf(f2hi(raw), 0.f));
        }
        ull den = pk2(1e-15f, 1e-15f);
#pragma unroll
        for (int e = 0; e < 8; e++) ffma2(den, vsp[64 + e], qp[e]);
        const float rd0 = __fdividef(1.f, f2lo(den));
        const float rd1 = __fdividef(1.f, f2hi(den));
#pragma unroll
        for (int d = 0; d < 8; d++) {
            ull num = 0ull;
#pragma unroll
            for (int e = 0; e < 8; e++) ffma2(num, vsp[d * 8 + e], qp[e]);
            __half2 hp;
            hp.x = __float2half_rn(f2lo(num) * rd0);
            hp.y = __float2half_rn(f2hi(num) * rd1);
            *(__half2*)(oh + (size_t)d * NPIX + n) = hp;
        }
    }
}

// ---------------------------------------------------------------------------
struct PipeArgs {
    const float *x, *qkv_b, *dw3_w, *dw3_b, *pw3_w, *pw3_b;
    const float *dw5_w, *dw5_b, *pw5_w, *pw5_b, *proj_b;
    __half *xth, *xtl, *ath, *wqh, *wql, *wph, *wpl;
    float *qkv, *s3q, *s5q, *vkb, *out;
};

static void enqueue_part(cudaStream_t st, const PipeArgs& a, int b0, int nb)
{
    const size_t offX = (size_t)b0 * 256 * NPIX;
    const size_t offQ = (size_t)b0 * C3 * NPIX;
    const size_t off3 = (size_t)b0 * 32 * 8 * NPIX;
    const size_t offV = (size_t)b0 * 96 * 72;

    wsplit_kernel<<<(nb * 256 * NPIX + 255) / 256, 256, 0, st>>>(
        a.x + offX, a.xth + offX, a.xtl + offX, nb * 256 * NPIX);

    gemm_f16<<<dim3(NPIX / 128, C3 / 128, nb), 256, 3 * STG2, st>>>(
        a.wqh, a.wql, a.xth + offX, a.xtl + offX, a.qkv_b, a.qkv + offQ,
        C3, NPIX, 256);

    dwpw_kernel<<<dim3(16, 32, nb), 256, DW_SMEM, st>>>(
        a.qkv + offQ, a.dw3_w, a.dw3_b, a.pw3_w, a.pw3_b,
        a.dw5_w, a.dw5_b, a.pw5_w, a.pw5_b,
        a.s3q + off3, a.s5q + off3, a.vkb + offV);

    att_kernel<<<dim3(96, nb, 4), 256, 0, st>>>(
        a.qkv + offQ, a.s3q + off3, a.s5q + off3, a.vkb + offV, a.ath + offQ);

    gemm_f16_2p<<<dim3(NPIX / 128, 256 / 128, nb), 256, 3 * P2_STG, st>>>(
        a.wph, a.wpl, a.ath + offQ, a.proj_b, a.out + (size_t)b0 * 256 * NPIX,
        256, NPIX, C3);
}

extern "C" void kernel_launch(void* const* d_in, const int* in_sizes, int n_in,
                              void* d_out, int out_size)
{
    PipeArgs a;
    a.x      = (const float*)d_in[0];
    const float* qkv_w = (const float*)d_in[1];
    a.qkv_b  = (const float*)d_in[2];
    a.dw3_w  = (const float*)d_in[3];
    a.dw3_b  = (const float*)d_in[4];
    a.pw3_w  = (const float*)d_in[5];
    a.pw3_b  = (const float*)d_in[6];
    a.dw5_w  = (const float*)d_in[7];
    a.dw5_b  = (const float*)d_in[8];
    a.pw5_w  = (const float*)d_in[9];
    a.pw5_b  = (const float*)d_in[10];
    const float* proj_w = (const float*)d_in[11];
    a.proj_b = (const float*)d_in[12];
    a.out    = (float*)d_out;

    void *p;
    cudaGetSymbolAddress(&p, g_qkv);  a.qkv = (float*)p;
    cudaGetSymbolAddress(&p, g_s3q);  a.s3q = (float*)p;
    cudaGetSymbolAddress(&p, g_s5q);  a.s5q = (float*)p;
    cudaGetSymbolAddress(&p, g_vk);   a.vkb = (float*)p;
    cudaGetSymbolAddress(&p, g_xt_h); a.xth = (__half*)p;
    cudaGetSymbolAddress(&p, g_xt_l); a.xtl = (__half*)p;
    cudaGetSymbolAddress(&p, g_at_h); a.ath = (__half*)p;
    cudaGetSymbolAddress(&p, g_wq_h); a.wqh = (__half*)p;
    cudaGetSymbolAddress(&p, g_wq_l); a.wql = (__half*)p;
    cudaGetSymbolAddress(&p, g_wp_h); a.wph = (__half*)p;
    cudaGetSymbolAddress(&p, g_wp_l); a.wpl = (__half*)p;

    static bool inited = false;
    static cudaStream_t s[3];
    static cudaEvent_t evW, evJ[3];
    if (!inited) {
        for (int i = 0; i < 3; i++) {
            cudaStreamCreateWithFlags(&s[i], cudaStreamNonBlocking);
            cudaEventCreateWithFlags(&evJ[i], cudaEventDisableTiming);
        }
        cudaEventCreateWithFlags(&evW, cudaEventDisableTiming);
        cudaFuncSetAttribute(gemm_f16,
            cudaFuncAttributeMaxDynamicSharedMemorySize, 3 * STG2);
        cudaFuncSetAttribute(gemm_f16_2p,
            cudaFuncAttributeMaxDynamicSharedMemorySize, 3 * P2_STG);
        cudaFuncSetAttribute(dwpw_kernel,
            cudaFuncAttributeMaxDynamicSharedMemorySize, DW_SMEM);
        inited = true;
    }

    // serial head on main stream: vk zero (all batches) + weight splits
    cudaMemsetAsync(a.vkb, 0, (size_t)BATCH * 96 * 72 * sizeof(float), 0);
    wsplit_kernel<<<(C3 * 256 + 255) / 256, 256>>>(qkv_w, a.wqh, a.wql, C3 * 256);
    wsplit_kernel<<<(256 * C3 + 255) / 256, 256>>>(proj_w, a.wph, a.wpl, 256 * C3);

    // fork to 4 pipelines: main stream + s[0..2]
    cudaEventRecord(evW, 0);
    for (int i = 0; i < 3; i++) cudaStreamWaitEvent(s[i], evW, 0);

    enqueue_part(0,    a, 0, 2);
    enqueue_part(s[0], a, 2, 2);
    enqueue_part(s[1], a, 4, 2);
    enqueue_part(s[2], a, 6, 2);

    // join
    for (int i = 0; i < 3; i++) {
        cudaEventRecord(evJ[i], s[i]);
        cudaStreamWaitEvent(0, evJ[i], 0);
    }
}